// round 1
// baseline (speedup 1.0000x reference)
#include <cuda_runtime.h>
#include <math.h>
#include <stdint.h>

#define D_MODEL 2048
#define N_HEADS 16
#define D_HEAD 128
#define BATCH 4
#define SEQ 2048
#define M_ROWS (BATCH*SEQ)      /* 8192 */
#define N_QKV (3*D_MODEL)       /* 6144 */
#define BH (BATCH*N_HEADS)      /* 64  */

// ---------------- scratch (no allocation allowed) ----------------
__device__ float g_Q[(size_t)BH*SEQ*D_HEAD];
__device__ float g_K[(size_t)BH*SEQ*D_HEAD];
__device__ float g_V[(size_t)BH*SEQ*D_HEAD];
__device__ float g_C[(size_t)M_ROWS*D_MODEL];   // ctx transposed back to (b*t, d_model)

// ---------------- SGEMM 128x128x8, 256 threads, 8x8 micro-tile ----------------
// C = A(MxK) * W(KxN) + bias ; K = 2048 for both GEMMs here.

template<int N_DIM>
__device__ __forceinline__ void sgemm_core(const float* __restrict__ A,
                                           const float* __restrict__ W,
                                           float acc[8][8])
{
    __shared__ float As[8][128];
    __shared__ float Bs[8][128];
    const int tid = threadIdx.x;
    const int row0 = blockIdx.y * 128;
    const int col0 = blockIdx.x * 128;

    const int arow = tid >> 1;            // 0..127
    const int acol = (tid & 1) * 4;       // 0 or 4
    const int brow = tid >> 5;            // 0..7
    const int bcol = (tid & 31) * 4;      // 0..124

    const int ty = tid >> 4;              // 0..15
    const int tx = tid & 15;              // 0..15

    for (int k0 = 0; k0 < D_MODEL; k0 += 8) {
        float4 av = *(const float4*)&A[(size_t)(row0 + arow) * D_MODEL + k0 + acol];
        As[acol + 0][arow] = av.x;
        As[acol + 1][arow] = av.y;
        As[acol + 2][arow] = av.z;
        As[acol + 3][arow] = av.w;
        float4 bv = *(const float4*)&W[(size_t)(k0 + brow) * N_DIM + col0 + bcol];
        *(float4*)&Bs[brow][bcol] = bv;
        __syncthreads();
#pragma unroll
        for (int k = 0; k < 8; k++) {
            float a[8], b[8];
            *(float4*)&a[0] = *(const float4*)&As[k][ty * 8];
            *(float4*)&a[4] = *(const float4*)&As[k][ty * 8 + 4];
            *(float4*)&b[0] = *(const float4*)&Bs[k][tx * 8];
            *(float4*)&b[4] = *(const float4*)&Bs[k][tx * 8 + 4];
#pragma unroll
            for (int i = 0; i < 8; i++)
#pragma unroll
                for (int j = 0; j < 8; j++)
                    acc[i][j] += a[i] * b[j];
        }
        __syncthreads();
    }
}

// QKV GEMM: epilogue adds bias and scatters into (b,h,t,d) Q/K/V buffers.
__global__ __launch_bounds__(256)
void sgemm_qkv_kernel(const float* __restrict__ x,
                      const float* __restrict__ w_qkv,
                      const float* __restrict__ b_qkv)
{
    float acc[8][8];
#pragma unroll
    for (int i = 0; i < 8; i++)
#pragma unroll
        for (int j = 0; j < 8; j++) acc[i][j] = 0.f;

    sgemm_core<N_QKV>(x, w_qkv, acc);

    const int tid = threadIdx.x;
    const int ty = tid >> 4;
    const int tx = tid & 15;
    const int row0 = blockIdx.y * 128;
    const int col0 = blockIdx.x * 128;

#pragma unroll
    for (int i = 0; i < 8; i++) {
        int grow = row0 + ty * 8 + i;
        int b_ = grow >> 11;            // /2048
        int t_ = grow & 2047;
#pragma unroll
        for (int j = 0; j < 8; j++) {
            int gcol = col0 + tx * 8 + j;
            float val = acc[i][j] + __ldg(&b_qkv[gcol]);
            int which = gcol >> 11;     // 0=q 1=k 2=v
            int rem   = gcol & 2047;
            int h     = rem >> 7;
            int dd    = rem & 127;
            size_t idx = (((size_t)b_ * N_HEADS + h) * SEQ + t_) * D_HEAD + dd;
            if (which == 0)      g_Q[idx] = val;
            else if (which == 1) g_K[idx] = val;
            else                 g_V[idx] = val;
        }
    }
}

// Out-projection GEMM: C(ctx) * w_out + b_out -> d_out
__global__ __launch_bounds__(256)
void sgemm_out_kernel(const float* __restrict__ w_out,
                      const float* __restrict__ b_out,
                      float* __restrict__ out)
{
    float acc[8][8];
#pragma unroll
    for (int i = 0; i < 8; i++)
#pragma unroll
        for (int j = 0; j < 8; j++) acc[i][j] = 0.f;

    sgemm_core<D_MODEL>(g_C, w_out, acc);

    const int tid = threadIdx.x;
    const int ty = tid >> 4;
    const int tx = tid & 15;
    const int row0 = blockIdx.y * 128;
    const int col0 = blockIdx.x * 128;

#pragma unroll
    for (int i = 0; i < 8; i++) {
        int grow = row0 + ty * 8 + i;
#pragma unroll
        for (int j = 0; j < 8; j++) {
            int gcol = col0 + tx * 8 + j;
            out[(size_t)grow * D_MODEL + gcol] = acc[i][j] + __ldg(&b_out[gcol]);
        }
    }
}

// ---------------- RoPE (in-place on g_Q, g_K) ----------------
__global__ __launch_bounds__(256)
void rope_kernel()
{
    int idx = blockIdx.x * blockDim.x + threadIdx.x;   // BH*SEQ*64 total
    if (idx >= BH * SEQ * 64) return;
    int i  = idx & 63;
    int t  = (idx >> 6) & (SEQ - 1);
    int bh = idx >> 17;

    // inv_freq = theta^(-i/64)
    float inv = __expf(-(float)i * (9.210340371976184f / 64.0f));
    float freq = (float)t * inv;
    float s, c;
    __sincosf(freq, &s, &c);

    size_t base = ((size_t)bh * SEQ + t) * D_HEAD;
    float q1 = g_Q[base + i], q2 = g_Q[base + i + 64];
    g_Q[base + i]      = q1 * c - q2 * s;
    g_Q[base + i + 64] = q2 * c + q1 * s;
    float k1 = g_K[base + i], k2 = g_K[base + i + 64];
    g_K[base + i]      = k1 * c - k2 * s;
    g_K[base + i + 64] = k2 * c + k1 * s;
}

// ---------------- Flash attention (fp32, causal) ----------------
// Block: 128 threads, BM=64 queries, BN=32 keys per iteration.
// smem: sQ 64x132, sK 32x132, sV 32x132, sP 64x33   -> 76032 bytes
#define SQ_STRIDE 132
#define SP_STRIDE 33
#define ATTN_SMEM_FLOATS (64*SQ_STRIDE + 32*SQ_STRIDE + 32*SQ_STRIDE + 64*SP_STRIDE)
#define ATTN_SMEM_BYTES  (ATTN_SMEM_FLOATS * 4)

__global__ __launch_bounds__(128)
void attn_kernel()
{
    extern __shared__ float sm[];
    float* sQ = sm;                       // 64 x 132
    float* sK = sQ + 64 * SQ_STRIDE;      // 32 x 132
    float* sV = sK + 32 * SQ_STRIDE;      // 32 x 132
    float* sP = sV + 32 * SQ_STRIDE;      // 64 x 33

    const int bh = blockIdx.y;            // 0..63
    const int qt = blockIdx.x;            // 0..31
    const int q0 = qt * 64;
    const float scale = 0.08838834764831845f;  // 1/sqrt(128)

    const float* Qb = g_Q + (size_t)bh * SEQ * D_HEAD;
    const float* Kb = g_K + (size_t)bh * SEQ * D_HEAD;
    const float* Vb = g_V + (size_t)bh * SEQ * D_HEAD;

    const int tid = threadIdx.x;
    const int ty = tid >> 3;              // 0..15 -> query rows ty*4..+3
    const int tx = tid & 7;               // 0..7  -> key cols tx*4..+3 ; ctx cols tx*16..+15

    // load Q tile (64x128)
    for (int i = tid; i < 64 * 32; i += 128) {
        int r = i >> 5, c4 = i & 31;
        *(float4*)&sQ[r * SQ_STRIDE + c4 * 4] =
            *(const float4*)&Qb[(size_t)(q0 + r) * D_HEAD + c4 * 4];
    }

    float m_i[4], l_i[4], ctx[4][16];
#pragma unroll
    for (int i = 0; i < 4; i++) {
        m_i[i] = -INFINITY; l_i[i] = 0.f;
#pragma unroll
        for (int c = 0; c < 16; c++) ctx[i][c] = 0.f;
    }

    const int ktiles = 2 * qt + 2;        // keys 0 .. q0+63
    for (int kt = 0; kt < ktiles; kt++) {
        const int kb = kt * 32;
        __syncthreads();   // prev iteration's sK/sV/sP reads done
        for (int i = tid; i < 32 * 32; i += 128) {
            int r = i >> 5, c4 = i & 31;
            *(float4*)&sK[r * SQ_STRIDE + c4 * 4] =
                *(const float4*)&Kb[(size_t)(kb + r) * D_HEAD + c4 * 4];
            *(float4*)&sV[r * SQ_STRIDE + c4 * 4] =
                *(const float4*)&Vb[(size_t)(kb + r) * D_HEAD + c4 * 4];
        }
        __syncthreads();

        // scores 4x4
        float s[4][4];
#pragma unroll
        for (int i = 0; i < 4; i++)
#pragma unroll
            for (int j = 0; j < 4; j++) s[i][j] = 0.f;

#pragma unroll 4
        for (int d4 = 0; d4 < 32; d4++) {
            float4 a[4], b[4];
#pragma unroll
            for (int i = 0; i < 4; i++)
                a[i] = *(const float4*)&sQ[(ty * 4 + i) * SQ_STRIDE + d4 * 4];
#pragma unroll
            for (int j = 0; j < 4; j++)
                b[j] = *(const float4*)&sK[(tx * 4 + j) * SQ_STRIDE + d4 * 4];
#pragma unroll
            for (int i = 0; i < 4; i++)
#pragma unroll
                for (int j = 0; j < 4; j++)
                    s[i][j] += a[i].x * b[j].x + a[i].y * b[j].y
                             + a[i].z * b[j].z + a[i].w * b[j].w;
        }

        // mask + scale + online softmax
#pragma unroll
        for (int i = 0; i < 4; i++) {
            int qg = q0 + ty * 4 + i;
            float sv[4];
#pragma unroll
            for (int j = 0; j < 4; j++) {
                int kg = kb + tx * 4 + j;
                sv[j] = (kg <= qg) ? s[i][j] * scale : -INFINITY;
            }
            float mrow = fmaxf(fmaxf(sv[0], sv[1]), fmaxf(sv[2], sv[3]));
            mrow = fmaxf(mrow, __shfl_xor_sync(0xffffffffu, mrow, 1));
            mrow = fmaxf(mrow, __shfl_xor_sync(0xffffffffu, mrow, 2));
            mrow = fmaxf(mrow, __shfl_xor_sync(0xffffffffu, mrow, 4));
            float mnew = fmaxf(m_i[i], mrow);
            float corr = __expf(m_i[i] - mnew);   // 0 if m_i was -inf
            float psum = 0.f;
#pragma unroll
            for (int j = 0; j < 4; j++) {
                float p = __expf(sv[j] - mnew);
                sP[(ty * 4 + i) * SP_STRIDE + tx * 4 + j] = p;
                psum += p;
            }
            psum += __shfl_xor_sync(0xffffffffu, psum, 1);
            psum += __shfl_xor_sync(0xffffffffu, psum, 2);
            psum += __shfl_xor_sync(0xffffffffu, psum, 4);
            l_i[i] = l_i[i] * corr + psum;
            m_i[i] = mnew;
#pragma unroll
            for (int c = 0; c < 16; c++) ctx[i][c] *= corr;
        }
        __syncthreads();   // sP visible to all

        // ctx += P * V
#pragma unroll 4
        for (int kc = 0; kc < 32; kc++) {
            float p0 = sP[(ty * 4 + 0) * SP_STRIDE + kc];
            float p1 = sP[(ty * 4 + 1) * SP_STRIDE + kc];
            float p2 = sP[(ty * 4 + 2) * SP_STRIDE + kc];
            float p3 = sP[(ty * 4 + 3) * SP_STRIDE + kc];
            const float* vrow = &sV[kc * SQ_STRIDE + tx * 16];
            float4 v0 = *(const float4*)&vrow[0];
            float4 v1 = *(const float4*)&vrow[4];
            float4 v2 = *(const float4*)&vrow[8];
            float4 v3 = *(const float4*)&vrow[12];
            float vv[16] = { v0.x, v0.y, v0.z, v0.w, v1.x, v1.y, v1.z, v1.w,
                             v2.x, v2.y, v2.z, v2.w, v3.x, v3.y, v3.z, v3.w };
            float pp[4] = { p0, p1, p2, p3 };
#pragma unroll
            for (int i = 0; i < 4; i++)
#pragma unroll
                for (int c = 0; c < 16; c++)
                    ctx[i][c] += pp[i] * vv[c];
        }
    }

    // normalize + store transposed to (b*t, d_model)
    const int b_ = bh >> 4;
    const int h_ = bh & 15;
#pragma unroll
    for (int i = 0; i < 4; i++) {
        float rinv = 1.0f / l_i[i];
        int qg = q0 + ty * 4 + i;
        size_t base = ((size_t)(b_ * SEQ + qg)) * D_MODEL + h_ * D_HEAD + tx * 16;
#pragma unroll
        for (int c4 = 0; c4 < 4; c4++) {
            float4 o;
            o.x = ctx[i][c4 * 4 + 0] * rinv;
            o.y = ctx[i][c4 * 4 + 1] * rinv;
            o.z = ctx[i][c4 * 4 + 2] * rinv;
            o.w = ctx[i][c4 * 4 + 3] * rinv;
            *(float4*)&g_C[base + c4 * 4] = o;
        }
    }
}

// ---------------- launcher ----------------
extern "C" void kernel_launch(void* const* d_in, const int* in_sizes, int n_in,
                              void* d_out, int out_size)
{
    const float* x     = (const float*)d_in[0];
    const float* w_qkv = (const float*)d_in[1];
    const float* b_qkv = (const float*)d_in[2];
    const float* w_out = (const float*)d_in[3];
    const float* b_out = (const float*)d_in[4];
    float* out = (float*)d_out;

    (void)in_sizes; (void)n_in; (void)out_size;

    // 1) QKV projection (fused bias + head-layout scatter)
    {
        dim3 grid(N_QKV / 128, M_ROWS / 128);
        sgemm_qkv_kernel<<<grid, 256>>>(x, w_qkv, b_qkv);
    }
    // 2) RoPE on Q,K
    {
        int total = BH * SEQ * 64;
        rope_kernel<<<(total + 255) / 256, 256>>>();
    }
    // 3) Flash attention
    {
        cudaFuncSetAttribute(attn_kernel,
                             cudaFuncAttributeMaxDynamicSharedMemorySize,
                             ATTN_SMEM_BYTES);
        dim3 grid(SEQ / 64, BH);
        attn_kernel<<<grid, 128, ATTN_SMEM_BYTES>>>();
    }
    // 4) Output projection
    {
        dim3 grid(D_MODEL / 128, M_ROWS / 128);
        sgemm_out_kernel<<<grid, 256>>>(w_out, b_out, out);
    }
}

// round 2
// speedup vs baseline: 1.5171x; 1.5171x over previous
#include <cuda_runtime.h>
#include <cuda_bf16.h>
#include <math.h>
#include <stdint.h>

#define D_MODEL 2048
#define N_HEADS 16
#define D_HEAD 128
#define BATCH 4
#define SEQ 2048
#define M_ROWS (BATCH*SEQ)      /* 8192 */
#define N_QKV (3*D_MODEL)       /* 6144 */
#define BH (BATCH*N_HEADS)      /* 64  */

// ---------------- scratch (no allocation allowed) ----------------
__device__ float g_Q[(size_t)BH*SEQ*D_HEAD];
__device__ float g_K[(size_t)BH*SEQ*D_HEAD];
__device__ float g_V[(size_t)BH*SEQ*D_HEAD];

__device__ __nv_bfloat16 g_xh[(size_t)M_ROWS*D_MODEL];
__device__ __nv_bfloat16 g_xl[(size_t)M_ROWS*D_MODEL];
__device__ __nv_bfloat16 g_wqh[(size_t)D_MODEL*N_QKV];
__device__ __nv_bfloat16 g_wql[(size_t)D_MODEL*N_QKV];
__device__ __nv_bfloat16 g_woh[(size_t)D_MODEL*D_MODEL];
__device__ __nv_bfloat16 g_wol[(size_t)D_MODEL*D_MODEL];
__device__ __nv_bfloat16 g_ch[(size_t)M_ROWS*D_MODEL];
__device__ __nv_bfloat16 g_cl[(size_t)M_ROWS*D_MODEL];

// ---------------- fp32 -> split bf16 (hi + lo) ----------------
__global__ __launch_bounds__(256)
void split_kernel(const float* __restrict__ in,
                  __nv_bfloat16* __restrict__ hi,
                  __nv_bfloat16* __restrict__ lo, int n4)
{
    int idx = blockIdx.x * blockDim.x + threadIdx.x;
    if (idx >= n4) return;
    float4 v = *(const float4*)&in[idx * 4];
    float vv[4] = { v.x, v.y, v.z, v.w };
#pragma unroll
    for (int i = 0; i < 4; i++) {
        __nv_bfloat16 h = __float2bfloat16(vv[i]);
        hi[idx * 4 + i] = h;
        lo[idx * 4 + i] = __float2bfloat16(vv[i] - __bfloat162float(h));
    }
}

// ---------------- mma helpers ----------------
__device__ __forceinline__ uint32_t smem_u32(const void* p) {
    return (uint32_t)__cvta_generic_to_shared(p);
}
__device__ __forceinline__ void ldsm_x4(uint32_t (&r)[4], uint32_t addr) {
    asm volatile("ldmatrix.sync.aligned.m8n8.x4.shared.b16 {%0,%1,%2,%3}, [%4];"
                 : "=r"(r[0]), "=r"(r[1]), "=r"(r[2]), "=r"(r[3]) : "r"(addr));
}
__device__ __forceinline__ void ldsm_x2t(uint32_t (&r)[2], uint32_t addr) {
    asm volatile("ldmatrix.sync.aligned.m8n8.x2.trans.shared.b16 {%0,%1}, [%2];"
                 : "=r"(r[0]), "=r"(r[1]) : "r"(addr));
}
__device__ __forceinline__ void mma16816(float (&d)[4], const uint32_t (&a)[4],
                                         const uint32_t (&b)[2]) {
    asm volatile("mma.sync.aligned.m16n8k16.row.col.f32.bf16.bf16.f32 "
                 "{%0,%1,%2,%3}, {%4,%5,%6,%7}, {%8,%9}, {%0,%1,%2,%3};"
                 : "+f"(d[0]), "+f"(d[1]), "+f"(d[2]), "+f"(d[3])
                 : "r"(a[0]), "r"(a[1]), "r"(a[2]), "r"(a[3]),
                   "r"(b[0]), "r"(b[1]));
}

// ---------------- split-bf16 GEMM core: 128x128 tile, K-step 32, 256 thr ----
// acc[mt][nt][4] computed as Ah*Bh + Ah*Bl + Al*Bh  (fp32 accumulate)
#define AS_STRIDE 40
#define BS_STRIDE 136

template<int N_DIM>
__device__ __forceinline__ void gemm_split_core(const __nv_bfloat16* __restrict__ Ah,
                                                const __nv_bfloat16* __restrict__ Al,
                                                const __nv_bfloat16* __restrict__ Bh,
                                                const __nv_bfloat16* __restrict__ Bl,
                                                float acc[4][4][4])
{
    __shared__ __align__(16) __nv_bfloat16 Ahs[128 * AS_STRIDE];
    __shared__ __align__(16) __nv_bfloat16 Als[128 * AS_STRIDE];
    __shared__ __align__(16) __nv_bfloat16 Bhs[32 * BS_STRIDE];
    __shared__ __align__(16) __nv_bfloat16 Bls[32 * BS_STRIDE];

    const int tid  = threadIdx.x;
    const int lane = tid & 31;
    const int warp = tid >> 5;
    const int wm = warp & 1;      // 0..1  -> m offset wm*64
    const int wn = warp >> 1;     // 0..3  -> n offset wn*32
    const int row0 = blockIdx.y * 128;
    const int col0 = blockIdx.x * 128;

    const int l16 = lane & 15;
    const int lhi = lane >> 4;

    for (int k0 = 0; k0 < D_MODEL; k0 += 32) {
        __syncthreads();
#pragma unroll
        for (int s = 0; s < 2; s++) {
            int id = tid + s * 256;
            int ra = id >> 2, ca = id & 3;                 // A: 128 rows x 4 chunks
            *(uint4*)&Ahs[ra * AS_STRIDE + ca * 8] =
                *(const uint4*)&Ah[(size_t)(row0 + ra) * D_MODEL + k0 + ca * 8];
            *(uint4*)&Als[ra * AS_STRIDE + ca * 8] =
                *(const uint4*)&Al[(size_t)(row0 + ra) * D_MODEL + k0 + ca * 8];
            int rb = id >> 4, cb = id & 15;                // B: 32 rows x 16 chunks
            *(uint4*)&Bhs[rb * BS_STRIDE + cb * 8] =
                *(const uint4*)&Bh[(size_t)(k0 + rb) * N_DIM + col0 + cb * 8];
            *(uint4*)&Bls[rb * BS_STRIDE + cb * 8] =
                *(const uint4*)&Bl[(size_t)(k0 + rb) * N_DIM + col0 + cb * 8];
        }
        __syncthreads();

#pragma unroll
        for (int ksub = 0; ksub < 2; ksub++) {
            uint32_t bh[4][2], bl[4][2];
#pragma unroll
            for (int nt = 0; nt < 4; nt++) {
                uint32_t baddr = smem_u32(&Bhs[(ksub * 16 + l16) * BS_STRIDE +
                                               wn * 32 + nt * 8]);
                ldsm_x2t(bh[nt], baddr);
                uint32_t baddr2 = smem_u32(&Bls[(ksub * 16 + l16) * BS_STRIDE +
                                                wn * 32 + nt * 8]);
                ldsm_x2t(bl[nt], baddr2);
            }
#pragma unroll
            for (int mt = 0; mt < 4; mt++) {
                uint32_t ah[4], al[4];
                uint32_t aaddr = smem_u32(&Ahs[(wm * 64 + mt * 16 + l16) * AS_STRIDE +
                                               ksub * 16 + lhi * 8]);
                ldsm_x4(ah, aaddr);
                uint32_t aaddr2 = smem_u32(&Als[(wm * 64 + mt * 16 + l16) * AS_STRIDE +
                                                ksub * 16 + lhi * 8]);
                ldsm_x4(al, aaddr2);
#pragma unroll
                for (int nt = 0; nt < 4; nt++) {
                    mma16816(acc[mt][nt], ah, bh[nt]);
                    mma16816(acc[mt][nt], ah, bl[nt]);
                    mma16816(acc[mt][nt], al, bh[nt]);
                }
            }
        }
    }
}

// ---------------- QKV GEMM: bias + scatter into (b,h,t,d) ----------------
__device__ __forceinline__ void store_qkv(int grow, int gcol, float val)
{
    int b_ = grow >> 11;
    int t_ = grow & 2047;
    int which = gcol >> 11;     // 0=q 1=k 2=v
    int rem   = gcol & 2047;
    int h     = rem >> 7;
    int dd    = rem & 127;
    size_t idx = (((size_t)b_ * N_HEADS + h) * SEQ + t_) * D_HEAD + dd;
    if (which == 0)      g_Q[idx] = val;
    else if (which == 1) g_K[idx] = val;
    else                 g_V[idx] = val;
}

__global__ __launch_bounds__(256)
void gemm_qkv_kernel(const float* __restrict__ b_qkv)
{
    float acc[4][4][4];
#pragma unroll
    for (int i = 0; i < 4; i++)
#pragma unroll
        for (int j = 0; j < 4; j++)
#pragma unroll
            for (int k = 0; k < 4; k++) acc[i][j][k] = 0.f;

    gemm_split_core<N_QKV>(g_xh, g_xl, g_wqh, g_wql, acc);

    const int tid  = threadIdx.x;
    const int lane = tid & 31;
    const int warp = tid >> 5;
    const int wm = warp & 1, wn = warp >> 1;
    const int g = lane >> 2, tig = lane & 3;
    const int row0 = blockIdx.y * 128;
    const int col0 = blockIdx.x * 128;

#pragma unroll
    for (int mt = 0; mt < 4; mt++) {
#pragma unroll
        for (int nt = 0; nt < 4; nt++) {
            int r = row0 + wm * 64 + mt * 16 + g;
            int c = col0 + wn * 32 + nt * 8 + tig * 2;
            float bias0 = __ldg(&b_qkv[c]);
            float bias1 = __ldg(&b_qkv[c + 1]);
            store_qkv(r,     c,     acc[mt][nt][0] + bias0);
            store_qkv(r,     c + 1, acc[mt][nt][1] + bias1);
            store_qkv(r + 8, c,     acc[mt][nt][2] + bias0);
            store_qkv(r + 8, c + 1, acc[mt][nt][3] + bias1);
        }
    }
}

// ---------------- out-proj GEMM ----------------
__global__ __launch_bounds__(256)
void gemm_out_kernel(const float* __restrict__ b_out, float* __restrict__ out)
{
    float acc[4][4][4];
#pragma unroll
    for (int i = 0; i < 4; i++)
#pragma unroll
        for (int j = 0; j < 4; j++)
#pragma unroll
            for (int k = 0; k < 4; k++) acc[i][j][k] = 0.f;

    gemm_split_core<D_MODEL>(g_ch, g_cl, g_woh, g_wol, acc);

    const int tid  = threadIdx.x;
    const int lane = tid & 31;
    const int warp = tid >> 5;
    const int wm = warp & 1, wn = warp >> 1;
    const int g = lane >> 2, tig = lane & 3;
    const int row0 = blockIdx.y * 128;
    const int col0 = blockIdx.x * 128;

#pragma unroll
    for (int mt = 0; mt < 4; mt++) {
#pragma unroll
        for (int nt = 0; nt < 4; nt++) {
            int r = row0 + wm * 64 + mt * 16 + g;
            int c = col0 + wn * 32 + nt * 8 + tig * 2;
            float bias0 = __ldg(&b_out[c]);
            float bias1 = __ldg(&b_out[c + 1]);
            out[(size_t)r * D_MODEL + c]           = acc[mt][nt][0] + bias0;
            out[(size_t)r * D_MODEL + c + 1]       = acc[mt][nt][1] + bias1;
            out[(size_t)(r + 8) * D_MODEL + c]     = acc[mt][nt][2] + bias0;
            out[(size_t)(r + 8) * D_MODEL + c + 1] = acc[mt][nt][3] + bias1;
        }
    }
}

// ---------------- RoPE (in-place on g_Q, g_K) ----------------
__global__ __launch_bounds__(256)
void rope_kernel()
{
    int idx = blockIdx.x * blockDim.x + threadIdx.x;
    if (idx >= BH * SEQ * 64) return;
    int i  = idx & 63;
    int t  = (idx >> 6) & (SEQ - 1);
    int bh = idx >> 17;

    float inv = __expf(-(float)i * (9.210340371976184f / 64.0f));
    float freq = (float)t * inv;
    float s, c;
    __sincosf(freq, &s, &c);

    size_t base = ((size_t)bh * SEQ + t) * D_HEAD;
    float q1 = g_Q[base + i], q2 = g_Q[base + i + 64];
    g_Q[base + i]      = q1 * c - q2 * s;
    g_Q[base + i + 64] = q2 * c + q1 * s;
    float k1 = g_K[base + i], k2 = g_K[base + i + 64];
    g_K[base + i]      = k1 * c - k2 * s;
    g_K[base + i + 64] = k2 * c + k1 * s;
}

// ---------------- Flash attention (fp32, causal) ----------------
#define SQ_STRIDE 132
#define SP_STRIDE 33
#define ATTN_SMEM_FLOATS (64*SQ_STRIDE + 32*SQ_STRIDE + 32*SQ_STRIDE + 64*SP_STRIDE)
#define ATTN_SMEM_BYTES  (ATTN_SMEM_FLOATS * 4)

__global__ __launch_bounds__(128)
void attn_kernel()
{
    extern __shared__ float sm[];
    float* sQ = sm;                       // 64 x 132
    float* sK = sQ + 64 * SQ_STRIDE;      // 32 x 132
    float* sV = sK + 32 * SQ_STRIDE;      // 32 x 132
    float* sP = sV + 32 * SQ_STRIDE;      // 64 x 33

    const int bh = blockIdx.y;
    const int qt = blockIdx.x;
    const int q0 = qt * 64;
    const float scale = 0.08838834764831845f;

    const float* Qb = g_Q + (size_t)bh * SEQ * D_HEAD;
    const float* Kb = g_K + (size_t)bh * SEQ * D_HEAD;
    const float* Vb = g_V + (size_t)bh * SEQ * D_HEAD;

    const int tid = threadIdx.x;
    const int ty = tid >> 3;
    const int tx = tid & 7;

    for (int i = tid; i < 64 * 32; i += 128) {
        int r = i >> 5, c4 = i & 31;
        *(float4*)&sQ[r * SQ_STRIDE + c4 * 4] =
            *(const float4*)&Qb[(size_t)(q0 + r) * D_HEAD + c4 * 4];
    }

    float m_i[4], l_i[4], ctx[4][16];
#pragma unroll
    for (int i = 0; i < 4; i++) {
        m_i[i] = -INFINITY; l_i[i] = 0.f;
#pragma unroll
        for (int c = 0; c < 16; c++) ctx[i][c] = 0.f;
    }

    const int ktiles = 2 * qt + 2;
    for (int kt = 0; kt < ktiles; kt++) {
        const int kb = kt * 32;
        __syncthreads();
        for (int i = tid; i < 32 * 32; i += 128) {
            int r = i >> 5, c4 = i & 31;
            *(float4*)&sK[r * SQ_STRIDE + c4 * 4] =
                *(const float4*)&Kb[(size_t)(kb + r) * D_HEAD + c4 * 4];
            *(float4*)&sV[r * SQ_STRIDE + c4 * 4] =
                *(const float4*)&Vb[(size_t)(kb + r) * D_HEAD + c4 * 4];
        }
        __syncthreads();

        float s[4][4];
#pragma unroll
        for (int i = 0; i < 4; i++)
#pragma unroll
            for (int j = 0; j < 4; j++) s[i][j] = 0.f;

#pragma unroll 4
        for (int d4 = 0; d4 < 32; d4++) {
            float4 a[4], b[4];
#pragma unroll
            for (int i = 0; i < 4; i++)
                a[i] = *(const float4*)&sQ[(ty * 4 + i) * SQ_STRIDE + d4 * 4];
#pragma unroll
            for (int j = 0; j < 4; j++)
                b[j] = *(const float4*)&sK[(tx * 4 + j) * SQ_STRIDE + d4 * 4];
#pragma unroll
            for (int i = 0; i < 4; i++)
#pragma unroll
                for (int j = 0; j < 4; j++)
                    s[i][j] += a[i].x * b[j].x + a[i].y * b[j].y
                             + a[i].z * b[j].z + a[i].w * b[j].w;
        }

#pragma unroll
        for (int i = 0; i < 4; i++) {
            int qg = q0 + ty * 4 + i;
            float sv[4];
#pragma unroll
            for (int j = 0; j < 4; j++) {
                int kg = kb + tx * 4 + j;
                sv[j] = (kg <= qg) ? s[i][j] * scale : -INFINITY;
            }
            float mrow = fmaxf(fmaxf(sv[0], sv[1]), fmaxf(sv[2], sv[3]));
            mrow = fmaxf(mrow, __shfl_xor_sync(0xffffffffu, mrow, 1));
            mrow = fmaxf(mrow, __shfl_xor_sync(0xffffffffu, mrow, 2));
            mrow = fmaxf(mrow, __shfl_xor_sync(0xffffffffu, mrow, 4));
            float mnew = fmaxf(m_i[i], mrow);
            float corr = __expf(m_i[i] - mnew);
            float psum = 0.f;
#pragma unroll
            for (int j = 0; j < 4; j++) {
                float p = __expf(sv[j] - mnew);
                sP[(ty * 4 + i) * SP_STRIDE + tx * 4 + j] = p;
                psum += p;
            }
            psum += __shfl_xor_sync(0xffffffffu, psum, 1);
            psum += __shfl_xor_sync(0xffffffffu, psum, 2);
            psum += __shfl_xor_sync(0xffffffffu, psum, 4);
            l_i[i] = l_i[i] * corr + psum;
            m_i[i] = mnew;
#pragma unroll
            for (int c = 0; c < 16; c++) ctx[i][c] *= corr;
        }
        __syncthreads();

#pragma unroll 4
        for (int kc = 0; kc < 32; kc++) {
            float p0 = sP[(ty * 4 + 0) * SP_STRIDE + kc];
            float p1 = sP[(ty * 4 + 1) * SP_STRIDE + kc];
            float p2 = sP[(ty * 4 + 2) * SP_STRIDE + kc];
            float p3 = sP[(ty * 4 + 3) * SP_STRIDE + kc];
            const float* vrow = &sV[kc * SQ_STRIDE + tx * 16];
            float4 v0 = *(const float4*)&vrow[0];
            float4 v1 = *(const float4*)&vrow[4];
            float4 v2 = *(const float4*)&vrow[8];
            float4 v3 = *(const float4*)&vrow[12];
            float vv[16] = { v0.x, v0.y, v0.z, v0.w, v1.x, v1.y, v1.z, v1.w,
                             v2.x, v2.y, v2.z, v2.w, v3.x, v3.y, v3.z, v3.w };
            float pp[4] = { p0, p1, p2, p3 };
#pragma unroll
            for (int i = 0; i < 4; i++)
#pragma unroll
                for (int c = 0; c < 16; c++)
                    ctx[i][c] += pp[i] * vv[c];
        }
    }

    // normalize + store as split bf16 into (b*t, d_model)
    const int b_ = bh >> 4;
    const int h_ = bh & 15;
#pragma unroll
    for (int i = 0; i < 4; i++) {
        float rinv = 1.0f / l_i[i];
        int qg = q0 + ty * 4 + i;
        size_t base = ((size_t)(b_ * SEQ + qg)) * D_MODEL + h_ * D_HEAD + tx * 16;
#pragma unroll
        for (int c = 0; c < 16; c++) {
            float o = ctx[i][c] * rinv;
            __nv_bfloat16 h = __float2bfloat16(o);
            g_ch[base + c] = h;
            g_cl[base + c] = __float2bfloat16(o - __bfloat162float(h));
        }
    }
}

// ---------------- launcher ----------------
extern "C" void kernel_launch(void* const* d_in, const int* in_sizes, int n_in,
                              void* d_out, int out_size)
{
    const float* x     = (const float*)d_in[0];
    const float* w_qkv = (const float*)d_in[1];
    const float* b_qkv = (const float*)d_in[2];
    const float* w_out = (const float*)d_in[3];
    const float* b_out = (const float*)d_in[4];
    float* out = (float*)d_out;

    (void)in_sizes; (void)n_in; (void)out_size;

    __nv_bfloat16 *xh, *xl, *wqh, *wql, *woh, *wol;
    cudaGetSymbolAddress((void**)&xh,  g_xh);
    cudaGetSymbolAddress((void**)&xl,  g_xl);
    cudaGetSymbolAddress((void**)&wqh, g_wqh);
    cudaGetSymbolAddress((void**)&wql, g_wql);
    cudaGetSymbolAddress((void**)&woh, g_woh);
    cudaGetSymbolAddress((void**)&wol, g_wol);

    // 0) split fp32 -> (hi, lo) bf16
    {
        int n4 = M_ROWS * D_MODEL / 4;
        split_kernel<<<(n4 + 255) / 256, 256>>>(x, xh, xl, n4);
        n4 = D_MODEL * N_QKV / 4;
        split_kernel<<<(n4 + 255) / 256, 256>>>(w_qkv, wqh, wql, n4);
        n4 = D_MODEL * D_MODEL / 4;
        split_kernel<<<(n4 + 255) / 256, 256>>>(w_out, woh, wol, n4);
    }
    // 1) QKV projection (tensor cores, fused bias + head-layout scatter)
    {
        dim3 grid(N_QKV / 128, M_ROWS / 128);
        gemm_qkv_kernel<<<grid, 256>>>(b_qkv);
    }
    // 2) RoPE on Q,K
    {
        int total = BH * SEQ * 64;
        rope_kernel<<<(total + 255) / 256, 256>>>();
    }
    // 3) Flash attention (writes ctx as split bf16)
    {
        cudaFuncSetAttribute(attn_kernel,
                             cudaFuncAttributeMaxDynamicSharedMemorySize,
                             ATTN_SMEM_BYTES);
        dim3 grid(SEQ / 64, BH);
        attn_kernel<<<grid, 128, ATTN_SMEM_BYTES>>>();
    }
    // 4) Output projection (tensor cores)
    {
        dim3 grid(D_MODEL / 128, M_ROWS / 128);
        gemm_out_kernel<<<grid, 256>>>(b_out, out);
    }
}

// round 4
// speedup vs baseline: 3.4439x; 2.2701x over previous
#include <cuda_runtime.h>
#include <cuda_bf16.h>
#include <cuda_fp16.h>
#include <math.h>
#include <stdint.h>

#define D_MODEL 2048
#define N_HEADS 16
#define D_HEAD 128
#define BATCH 4
#define SEQ 2048
#define M_ROWS (BATCH*SEQ)      /* 8192 */
#define N_QKV (3*D_MODEL)       /* 6144 */
#define BH (BATCH*N_HEADS)      /* 64  */

// ---------------- scratch (no allocation allowed) ----------------
__device__ float g_Q[(size_t)BH*SEQ*D_HEAD];
__device__ float g_K[(size_t)BH*SEQ*D_HEAD];
__device__ float g_V[(size_t)BH*SEQ*D_HEAD];

__device__ __nv_bfloat16 g_xh[(size_t)M_ROWS*D_MODEL];
__device__ __nv_bfloat16 g_xl[(size_t)M_ROWS*D_MODEL];
__device__ __nv_bfloat16 g_wqh[(size_t)D_MODEL*N_QKV];
__device__ __nv_bfloat16 g_wql[(size_t)D_MODEL*N_QKV];
__device__ __nv_bfloat16 g_woh[(size_t)D_MODEL*D_MODEL];
__device__ __nv_bfloat16 g_wol[(size_t)D_MODEL*D_MODEL];
__device__ __nv_bfloat16 g_ch[(size_t)M_ROWS*D_MODEL];
__device__ __nv_bfloat16 g_cl[(size_t)M_ROWS*D_MODEL];

// ---------------- helpers ----------------
__device__ __forceinline__ uint32_t smem_u32(const void* p) {
    return (uint32_t)__cvta_generic_to_shared(p);
}
#define CP_ASYNC16(dst, src) \
    asm volatile("cp.async.cg.shared.global [%0], [%1], 16;" :: "r"(dst), "l"(src))
#define CP_COMMIT()  asm volatile("cp.async.commit_group;" ::: "memory")

__device__ __forceinline__ void ldsm_x4(uint32_t (&r)[4], uint32_t addr) {
    asm volatile("ldmatrix.sync.aligned.m8n8.x4.shared.b16 {%0,%1,%2,%3}, [%4];"
                 : "=r"(r[0]), "=r"(r[1]), "=r"(r[2]), "=r"(r[3]) : "r"(addr));
}
__device__ __forceinline__ void ldsm_x2(uint32_t (&r)[2], uint32_t addr) {
    asm volatile("ldmatrix.sync.aligned.m8n8.x2.shared.b16 {%0,%1}, [%2];"
                 : "=r"(r[0]), "=r"(r[1]) : "r"(addr));
}
__device__ __forceinline__ void ldsm_x2t(uint32_t (&r)[2], uint32_t addr) {
    asm volatile("ldmatrix.sync.aligned.m8n8.x2.trans.shared.b16 {%0,%1}, [%2];"
                 : "=r"(r[0]), "=r"(r[1]) : "r"(addr));
}
__device__ __forceinline__ void mma_bf16(float (&d)[4], const uint32_t (&a)[4],
                                         const uint32_t (&b)[2]) {
    asm volatile("mma.sync.aligned.m16n8k16.row.col.f32.bf16.bf16.f32 "
                 "{%0,%1,%2,%3}, {%4,%5,%6,%7}, {%8,%9}, {%0,%1,%2,%3};"
                 : "+f"(d[0]), "+f"(d[1]), "+f"(d[2]), "+f"(d[3])
                 : "r"(a[0]), "r"(a[1]), "r"(a[2]), "r"(a[3]),
                   "r"(b[0]), "r"(b[1]));
}
__device__ __forceinline__ void mma_fp16(float (&d)[4], const uint32_t (&a)[4],
                                         const uint32_t (&b)[2]) {
    asm volatile("mma.sync.aligned.m16n8k16.row.col.f32.f16.f16.f32 "
                 "{%0,%1,%2,%3}, {%4,%5,%6,%7}, {%8,%9}, {%0,%1,%2,%3};"
                 : "+f"(d[0]), "+f"(d[1]), "+f"(d[2]), "+f"(d[3])
                 : "r"(a[0]), "r"(a[1]), "r"(a[2]), "r"(a[3]),
                   "r"(b[0]), "r"(b[1]));
}

// ---------------- fp32 -> split bf16 (hi + lo) ----------------
__global__ __launch_bounds__(256)
void split_kernel(const float* __restrict__ in,
                  __nv_bfloat16* __restrict__ hi,
                  __nv_bfloat16* __restrict__ lo, int n4)
{
    int idx = blockIdx.x * blockDim.x + threadIdx.x;
    if (idx >= n4) return;
    float4 v = *(const float4*)&in[idx * 4];
    float vv[4] = { v.x, v.y, v.z, v.w };
#pragma unroll
    for (int i = 0; i < 4; i++) {
        __nv_bfloat16 h = __float2bfloat16(vv[i]);
        hi[idx * 4 + i] = h;
        lo[idx * 4 + i] = __float2bfloat16(vv[i] - __bfloat162float(h));
    }
}

// ---------- split-bf16 GEMM: 128x128 tile, K-step 32, cp.async 2-stage ----
#define AS_STRIDE 40
#define BS_STRIDE 136
#define GA_TILE (128*AS_STRIDE)   /* 5120 elems */
#define GB_TILE (32*BS_STRIDE)    /* 4352 elems */
#define GSTAGE (2*GA_TILE + 2*GB_TILE)
#define GEMM_SMEM_BYTES (2*GSTAGE*2)
#define NCHUNK (D_MODEL/32)

__device__ __forceinline__ void gemm_load_stage(char* dsm, int buf, int k0,
    const __nv_bfloat16* Ah, const __nv_bfloat16* Al,
    const __nv_bfloat16* Bh, const __nv_bfloat16* Bl,
    int row0, int col0, int N_DIM, int tid)
{
    uint32_t base = smem_u32(dsm) + (uint32_t)buf * (GSTAGE*2);
#pragma unroll
    for (int s = 0; s < 2; s++) {
        int id = tid + s * 256;
        int ra = id >> 2, ca = id & 3;
        uint32_t da = base + ra * (AS_STRIDE*2) + ca * 16;
        const size_t aoff = (size_t)(row0 + ra) * D_MODEL + k0 + ca * 8;
        CP_ASYNC16(da, Ah + aoff);
        CP_ASYNC16(da + GA_TILE*2, Al + aoff);
        int rb = id >> 4, cb = id & 15;
        uint32_t db = base + 2*GA_TILE*2 + rb * (BS_STRIDE*2) + cb * 16;
        const size_t boff = (size_t)(k0 + rb) * N_DIM + col0 + cb * 8;
        CP_ASYNC16(db, Bh + boff);
        CP_ASYNC16(db + GB_TILE*2, Bl + boff);
    }
    CP_COMMIT();
}

__device__ __forceinline__ void store_qkv(int grow, int gcol, float val)
{
    int b_ = grow >> 11;
    int t_ = grow & 2047;
    int which = gcol >> 11;     // 0=q 1=k 2=v
    int rem   = gcol & 2047;
    int h     = rem >> 7;
    int dd    = rem & 127;
    size_t idx = (((size_t)b_ * N_HEADS + h) * SEQ + t_) * D_HEAD + dd;
    if (which == 0)      g_Q[idx] = val;
    else if (which == 1) g_K[idx] = val;
    else                 g_V[idx] = val;
}

template<int N_DIM, bool IS_QKV>
__global__ __launch_bounds__(256)
void gemm_kernel(const __nv_bfloat16* __restrict__ Ah,
                 const __nv_bfloat16* __restrict__ Al,
                 const __nv_bfloat16* __restrict__ Bh,
                 const __nv_bfloat16* __restrict__ Bl,
                 const float* __restrict__ bias,
                 float* __restrict__ out)
{
    extern __shared__ __align__(16) char dsm[];
    const int tid  = threadIdx.x;
    const int lane = tid & 31;
    const int warp = tid >> 5;
    const int wm = warp & 1;
    const int wn = warp >> 1;
    const int row0 = blockIdx.y * 128;
    const int col0 = blockIdx.x * 128;
    const int l16 = lane & 15;
    const int lhi = lane >> 4;

    float acc[4][4][4];
#pragma unroll
    for (int i = 0; i < 4; i++)
#pragma unroll
        for (int j = 0; j < 4; j++)
#pragma unroll
            for (int k = 0; k < 4; k++) acc[i][j][k] = 0.f;

    gemm_load_stage(dsm, 0, 0,  Ah, Al, Bh, Bl, row0, col0, N_DIM, tid);
    gemm_load_stage(dsm, 1, 32, Ah, Al, Bh, Bl, row0, col0, N_DIM, tid);

#pragma unroll 1
    for (int c = 0; c < NCHUNK; c++) {
        if (c + 1 < NCHUNK)
            asm volatile("cp.async.wait_group 1;" ::: "memory");
        else
            asm volatile("cp.async.wait_group 0;" ::: "memory");
        __syncthreads();

        const __nv_bfloat16* Ahs = (const __nv_bfloat16*)(dsm + (size_t)(c & 1) * GSTAGE * 2);
        const __nv_bfloat16* Als = Ahs + GA_TILE;
        const __nv_bfloat16* Bhs = Als + GA_TILE;
        const __nv_bfloat16* Bls = Bhs + GB_TILE;

#pragma unroll
        for (int ksub = 0; ksub < 2; ksub++) {
            uint32_t bhf[4][2], blf[4][2];
#pragma unroll
            for (int nt = 0; nt < 4; nt++) {
                ldsm_x2t(bhf[nt], smem_u32(&Bhs[(ksub*16 + l16) * BS_STRIDE + wn*32 + nt*8]));
                ldsm_x2t(blf[nt], smem_u32(&Bls[(ksub*16 + l16) * BS_STRIDE + wn*32 + nt*8]));
            }
#pragma unroll
            for (int mt = 0; mt < 4; mt++) {
                uint32_t ah[4], al[4];
                ldsm_x4(ah, smem_u32(&Ahs[(wm*64 + mt*16 + l16) * AS_STRIDE + ksub*16 + lhi*8]));
                ldsm_x4(al, smem_u32(&Als[(wm*64 + mt*16 + l16) * AS_STRIDE + ksub*16 + lhi*8]));
#pragma unroll
                for (int nt = 0; nt < 4; nt++) {
                    mma_bf16(acc[mt][nt], ah, bhf[nt]);
                    mma_bf16(acc[mt][nt], ah, blf[nt]);
                    mma_bf16(acc[mt][nt], al, bhf[nt]);
                }
            }
        }
        __syncthreads();
        if (c + 2 < NCHUNK)
            gemm_load_stage(dsm, c & 1, (c + 2) * 32, Ah, Al, Bh, Bl, row0, col0, N_DIM, tid);
    }

    // epilogue (verified R2 mapping)
    const int g = lane >> 2, tq = lane & 3;
#pragma unroll
    for (int mt = 0; mt < 4; mt++) {
#pragma unroll
        for (int nt = 0; nt < 4; nt++) {
            int r = row0 + wm*64 + mt*16 + g;
            int cc = col0 + wn*32 + nt*8 + tq*2;
            float bias0 = __ldg(&bias[cc]);
            float bias1 = __ldg(&bias[cc + 1]);
            if (IS_QKV) {
                store_qkv(r,     cc,     acc[mt][nt][0] + bias0);
                store_qkv(r,     cc + 1, acc[mt][nt][1] + bias1);
                store_qkv(r + 8, cc,     acc[mt][nt][2] + bias0);
                store_qkv(r + 8, cc + 1, acc[mt][nt][3] + bias1);
            } else {
                out[(size_t)r * D_MODEL + cc]           = acc[mt][nt][0] + bias0;
                out[(size_t)r * D_MODEL + cc + 1]       = acc[mt][nt][1] + bias1;
                out[(size_t)(r + 8) * D_MODEL + cc]     = acc[mt][nt][2] + bias0;
                out[(size_t)(r + 8) * D_MODEL + cc + 1] = acc[mt][nt][3] + bias1;
            }
        }
    }
}

// ---------------- RoPE (in-place on g_Q, g_K) ----------------
__global__ __launch_bounds__(256)
void rope_kernel()
{
    int idx = blockIdx.x * blockDim.x + threadIdx.x;
    if (idx >= BH * SEQ * 64) return;
    int i  = idx & 63;
    int t  = (idx >> 6) & (SEQ - 1);
    int bh = idx >> 17;

    float inv = __expf(-(float)i * (9.210340371976184f / 64.0f));
    float freq = (float)t * inv;
    float s, c;
    __sincosf(freq, &s, &c);

    size_t base = ((size_t)bh * SEQ + t) * D_HEAD;
    float q1 = g_Q[base + i], q2 = g_Q[base + i + 64];
    g_Q[base + i]      = q1 * c - q2 * s;
    g_Q[base + i + 64] = q2 * c + q1 * s;
    float k1 = g_K[base + i], k2 = g_K[base + i + 64];
    g_K[base + i]      = k1 * c - k2 * s;
    g_K[base + i + 64] = k2 * c + k1 * s;
}

// ---------------- Flash attention via mma.sync ----------------
// BM=128 queries, BN=64 keys/iter, dh=128, 8 warps (warp w owns rows w*16..+15).
// QK: A=Q (split bf16, ldsm_x4 row-major recipe), B=K[t][d]: the n8k16 col-major
//     fragment needs thread t to hold K[n=t/4][k=2*(t%4)+{0,1}]. Non-trans
//     ldmatrix of a [n][k] row-major tile delivers exactly that; addresses:
//     lanes 0-7 -> rows n0..n0+7 at col k0, lanes 8-15 -> same rows at k0+8.
// PV: A=P (split fp16, row-major), B=V[t][d] = [k][n] row-major -> verified
//     ldsm_x2t recipe. ctx accumulated fp32 (16 n-tiles x 4 regs).
#define TS 136
#define PS 72
#define ATTN_Q_ELEMS (128*TS)
#define ATTN_K_ELEMS (64*TS)
#define ATTN_P_ELEMS (128*PS)
#define ATTN_SMEM_BYTES ((2*ATTN_Q_ELEMS + 4*ATTN_K_ELEMS + 2*ATTN_P_ELEMS)*2)

__global__ __launch_bounds__(256)
void attn_mma_kernel()
{
    extern __shared__ __align__(16) char dsm[];
    __nv_bfloat16* Qh = (__nv_bfloat16*)dsm;
    __nv_bfloat16* Ql = Qh + ATTN_Q_ELEMS;
    __nv_bfloat16* Kh = Ql + ATTN_Q_ELEMS;
    __nv_bfloat16* Kl = Kh + ATTN_K_ELEMS;
    __half* Vh = (__half*)(Kl + ATTN_K_ELEMS);
    __half* Vl = Vh + ATTN_K_ELEMS;
    __half* Ph = Vl + ATTN_K_ELEMS;
    __half* Pl = Ph + ATTN_P_ELEMS;

    const int bh = blockIdx.y;
    const int qt = blockIdx.x;
    const int q0 = qt * 128;
    const float SC2 = 0.08838834764831845f * 1.4426950408889634f; // scale*log2e

    const float* Qg = g_Q + (size_t)bh * SEQ * D_HEAD;
    const float* Kg = g_K + (size_t)bh * SEQ * D_HEAD;
    const float* Vg = g_V + (size_t)bh * SEQ * D_HEAD;

    const int tid = threadIdx.x;
    const int warp = tid >> 5, lane = tid & 31;
    const int m0 = warp * 16;
    const int l16 = lane & 15, lhi = lane >> 4;
    const int g = lane >> 2, tq = lane & 3;

    // load Q tile (fp32 -> split bf16 smem)
    for (int i = tid; i < 128 * 32; i += 256) {
        int r = i >> 5, c4 = i & 31;
        float4 v = *(const float4*)&Qg[(size_t)(q0 + r) * D_HEAD + c4 * 4];
        __nv_bfloat162 h01, h23, l01, l23;
        h01.x = __float2bfloat16(v.x); l01.x = __float2bfloat16(v.x - __bfloat162float(h01.x));
        h01.y = __float2bfloat16(v.y); l01.y = __float2bfloat16(v.y - __bfloat162float(h01.y));
        h23.x = __float2bfloat16(v.z); l23.x = __float2bfloat16(v.z - __bfloat162float(h23.x));
        h23.y = __float2bfloat16(v.w); l23.y = __float2bfloat16(v.w - __bfloat162float(h23.y));
        *(__nv_bfloat162*)&Qh[r * TS + c4 * 4]     = h01;
        *(__nv_bfloat162*)&Qh[r * TS + c4 * 4 + 2] = h23;
        *(__nv_bfloat162*)&Ql[r * TS + c4 * 4]     = l01;
        *(__nv_bfloat162*)&Ql[r * TS + c4 * 4 + 2] = l23;
    }

    float mI0 = -INFINITY, mI1 = -INFINITY, lI0 = 0.f, lI1 = 0.f;
    float ctx[16][4];
#pragma unroll
    for (int i = 0; i < 16; i++)
#pragma unroll
        for (int j = 0; j < 4; j++) ctx[i][j] = 0.f;

    const int ktiles = 2 * qt + 2;
#pragma unroll 1
    for (int kt = 0; kt < ktiles; kt++) {
        const int kb = kt * 64;
        __syncthreads();   // prior-iter K/V/P reads complete
        for (int i = tid; i < 64 * 32; i += 256) {
            int r = i >> 5, c4 = i & 31;
            size_t goff = (size_t)(kb + r) * D_HEAD + c4 * 4;
            float4 kv = *(const float4*)&Kg[goff];
            __nv_bfloat162 h01, h23, l01, l23;
            h01.x = __float2bfloat16(kv.x); l01.x = __float2bfloat16(kv.x - __bfloat162float(h01.x));
            h01.y = __float2bfloat16(kv.y); l01.y = __float2bfloat16(kv.y - __bfloat162float(h01.y));
            h23.x = __float2bfloat16(kv.z); l23.x = __float2bfloat16(kv.z - __bfloat162float(h23.x));
            h23.y = __float2bfloat16(kv.w); l23.y = __float2bfloat16(kv.w - __bfloat162float(h23.y));
            *(__nv_bfloat162*)&Kh[r * TS + c4 * 4]     = h01;
            *(__nv_bfloat162*)&Kh[r * TS + c4 * 4 + 2] = h23;
            *(__nv_bfloat162*)&Kl[r * TS + c4 * 4]     = l01;
            *(__nv_bfloat162*)&Kl[r * TS + c4 * 4 + 2] = l23;
            float4 vv = *(const float4*)&Vg[goff];
            __half2 vh01, vh23, vl01, vl23;
            vh01.x = __float2half(vv.x); vl01.x = __float2half(vv.x - __half2float(vh01.x));
            vh01.y = __float2half(vv.y); vl01.y = __float2half(vv.y - __half2float(vh01.y));
            vh23.x = __float2half(vv.z); vl23.x = __float2half(vv.z - __half2float(vh23.x));
            vh23.y = __float2half(vv.w); vl23.y = __float2half(vv.w - __half2float(vh23.y));
            *(__half2*)&Vh[r * TS + c4 * 4]     = vh01;
            *(__half2*)&Vh[r * TS + c4 * 4 + 2] = vh23;
            *(__half2*)&Vl[r * TS + c4 * 4]     = vl01;
            *(__half2*)&Vl[r * TS + c4 * 4 + 2] = vl23;
        }
        __syncthreads();

        // ---- scores S = Q @ K^T (split-bf16, 3 terms) ----
        float sacc[8][4];
#pragma unroll
        for (int nt = 0; nt < 8; nt++)
#pragma unroll
            for (int e = 0; e < 4; e++) sacc[nt][e] = 0.f;

        const int krow = lane & 7;
        const int kcolsel = ((lane >> 3) & 1) * 8;
#pragma unroll
        for (int ks = 0; ks < 8; ks++) {
            uint32_t ah[4], al[4];
            ldsm_x4(ah, smem_u32(&Qh[(m0 + l16) * TS + ks * 16 + lhi * 8]));
            ldsm_x4(al, smem_u32(&Ql[(m0 + l16) * TS + ks * 16 + lhi * 8]));
#pragma unroll
            for (int nt = 0; nt < 8; nt++) {
                uint32_t bhf[2], blf[2];
                ldsm_x2(bhf, smem_u32(&Kh[(nt * 8 + krow) * TS + ks * 16 + kcolsel]));
                ldsm_x2(blf, smem_u32(&Kl[(nt * 8 + krow) * TS + ks * 16 + kcolsel]));
                mma_bf16(sacc[nt], ah, bhf);
                mma_bf16(sacc[nt], ah, blf);
                mma_bf16(sacc[nt], al, bhf);
            }
        }

        // ---- online softmax (base-2) ----
        const bool diag = (kt >= ktiles - 2);
        const int r0 = q0 + m0 + g, r1 = r0 + 8;
        float rm0 = -INFINITY, rm1 = -INFINITY;
#pragma unroll
        for (int nt = 0; nt < 8; nt++) {
            int cb0 = kb + nt * 8 + tq * 2;
            float s0 = sacc[nt][0] * SC2, s1 = sacc[nt][1] * SC2;
            float s2 = sacc[nt][2] * SC2, s3 = sacc[nt][3] * SC2;
            if (diag) {
                if (cb0     > r0) s0 = -INFINITY;
                if (cb0 + 1 > r0) s1 = -INFINITY;
                if (cb0     > r1) s2 = -INFINITY;
                if (cb0 + 1 > r1) s3 = -INFINITY;
            }
            sacc[nt][0] = s0; sacc[nt][1] = s1; sacc[nt][2] = s2; sacc[nt][3] = s3;
            rm0 = fmaxf(rm0, fmaxf(s0, s1));
            rm1 = fmaxf(rm1, fmaxf(s2, s3));
        }
        rm0 = fmaxf(rm0, __shfl_xor_sync(0xffffffffu, rm0, 1));
        rm0 = fmaxf(rm0, __shfl_xor_sync(0xffffffffu, rm0, 2));
        rm1 = fmaxf(rm1, __shfl_xor_sync(0xffffffffu, rm1, 1));
        rm1 = fmaxf(rm1, __shfl_xor_sync(0xffffffffu, rm1, 2));
        float mn0 = fmaxf(mI0, rm0), mn1 = fmaxf(mI1, rm1);
        float c0 = exp2f(mI0 - mn0), c1 = exp2f(mI1 - mn1);
        float ps0 = 0.f, ps1 = 0.f;
#pragma unroll
        for (int nt = 0; nt < 8; nt++) {
            float p0 = exp2f(sacc[nt][0] - mn0);
            float p1 = exp2f(sacc[nt][1] - mn0);
            float p2 = exp2f(sacc[nt][2] - mn1);
            float p3 = exp2f(sacc[nt][3] - mn1);
            ps0 += p0 + p1; ps1 += p2 + p3;
            __half2 ph, pl;
            ph.x = __float2half(p0); pl.x = __float2half(p0 - __half2float(ph.x));
            ph.y = __float2half(p1); pl.y = __float2half(p1 - __half2float(ph.y));
            *(__half2*)&Ph[(m0 + g) * PS + nt * 8 + tq * 2] = ph;
            *(__half2*)&Pl[(m0 + g) * PS + nt * 8 + tq * 2] = pl;
            ph.x = __float2half(p2); pl.x = __float2half(p2 - __half2float(ph.x));
            ph.y = __float2half(p3); pl.y = __float2half(p3 - __half2float(ph.y));
            *(__half2*)&Ph[(m0 + g + 8) * PS + nt * 8 + tq * 2] = ph;
            *(__half2*)&Pl[(m0 + g + 8) * PS + nt * 8 + tq * 2] = pl;
        }
        ps0 += __shfl_xor_sync(0xffffffffu, ps0, 1);
        ps0 += __shfl_xor_sync(0xffffffffu, ps0, 2);
        ps1 += __shfl_xor_sync(0xffffffffu, ps1, 1);
        ps1 += __shfl_xor_sync(0xffffffffu, ps1, 2);
        lI0 = lI0 * c0 + ps0; lI1 = lI1 * c1 + ps1;
        mI0 = mn0; mI1 = mn1;
#pragma unroll
        for (int n2 = 0; n2 < 16; n2++) {
            ctx[n2][0] *= c0; ctx[n2][1] *= c0;
            ctx[n2][2] *= c1; ctx[n2][3] *= c1;
        }
        __syncwarp();   // P rows are per-warp; make STS visible to warp's ldmatrix

        // ---- ctx += P @ V (split-fp16, 3 terms) ----
#pragma unroll
        for (int ks = 0; ks < 4; ks++) {
            uint32_t aph[4], apl[4];
            ldsm_x4(aph, smem_u32(&Ph[(m0 + l16) * PS + ks * 16 + lhi * 8]));
            ldsm_x4(apl, smem_u32(&Pl[(m0 + l16) * PS + ks * 16 + lhi * 8]));
#pragma unroll
            for (int nt = 0; nt < 16; nt++) {
                uint32_t bhf[2], blf[2];
                ldsm_x2t(bhf, smem_u32(&Vh[(ks * 16 + l16) * TS + nt * 8]));
                ldsm_x2t(blf, smem_u32(&Vl[(ks * 16 + l16) * TS + nt * 8]));
                mma_fp16(ctx[nt], aph, bhf);
                mma_fp16(ctx[nt], aph, blf);
                mma_fp16(ctx[nt], apl, bhf);
            }
        }
    }

    // ---- epilogue: normalize, split to bf16 hi/lo, write (b*t, d_model) ----
    float ri0 = 1.0f / lI0, ri1 = 1.0f / lI1;
    const int b_ = bh >> 4, h_ = bh & 15;
    const int t0 = q0 + m0 + g, t1 = t0 + 8;
#pragma unroll
    for (int nt = 0; nt < 16; nt++) {
        int col = h_ * D_HEAD + nt * 8 + tq * 2;
        {
            float o0 = ctx[nt][0] * ri0, o1 = ctx[nt][1] * ri0;
            __nv_bfloat162 hh, ll;
            hh.x = __float2bfloat16(o0); ll.x = __float2bfloat16(o0 - __bfloat162float(hh.x));
            hh.y = __float2bfloat16(o1); ll.y = __float2bfloat16(o1 - __bfloat162float(hh.y));
            size_t idx = (size_t)(b_ * SEQ + t0) * D_MODEL + col;
            *(__nv_bfloat162*)&g_ch[idx] = hh;
            *(__nv_bfloat162*)&g_cl[idx] = ll;
        }
        {
            float o0 = ctx[nt][2] * ri1, o1 = ctx[nt][3] * ri1;
            __nv_bfloat162 hh, ll;
            hh.x = __float2bfloat16(o0); ll.x = __float2bfloat16(o0 - __bfloat162float(hh.x));
            hh.y = __float2bfloat16(o1); ll.y = __float2bfloat16(o1 - __bfloat162float(hh.y));
            size_t idx = (size_t)(b_ * SEQ + t1) * D_MODEL + col;
            *(__nv_bfloat162*)&g_ch[idx] = hh;
            *(__nv_bfloat162*)&g_cl[idx] = ll;
        }
    }
}

// ---------------- launcher ----------------
extern "C" void kernel_launch(void* const* d_in, const int* in_sizes, int n_in,
                              void* d_out, int out_size)
{
    const float* x     = (const float*)d_in[0];
    const float* w_qkv = (const float*)d_in[1];
    const float* b_qkv = (const float*)d_in[2];
    const float* w_out = (const float*)d_in[3];
    const float* b_out = (const float*)d_in[4];
    float* out = (float*)d_out;

    (void)in_sizes; (void)n_in; (void)out_size;

    __nv_bfloat16 *xh, *xl, *wqh, *wql, *woh, *wol, *ch, *cl;
    cudaGetSymbolAddress((void**)&xh,  g_xh);
    cudaGetSymbolAddress((void**)&xl,  g_xl);
    cudaGetSymbolAddress((void**)&wqh, g_wqh);
    cudaGetSymbolAddress((void**)&wql, g_wql);
    cudaGetSymbolAddress((void**)&woh, g_woh);
    cudaGetSymbolAddress((void**)&wol, g_wol);
    cudaGetSymbolAddress((void**)&ch,  g_ch);
    cudaGetSymbolAddress((void**)&cl,  g_cl);

    // 0) split fp32 -> (hi, lo) bf16
    {
        int n4 = M_ROWS * D_MODEL / 4;
        split_kernel<<<(n4 + 255) / 256, 256>>>(x, xh, xl, n4);
        n4 = D_MODEL * N_QKV / 4;
        split_kernel<<<(n4 + 255) / 256, 256>>>(w_qkv, wqh, wql, n4);
        n4 = D_MODEL * D_MODEL / 4;
        split_kernel<<<(n4 + 255) / 256, 256>>>(w_out, woh, wol, n4);
    }
    // 1) QKV projection (pipelined split-bf16 mma)
    {
        cudaFuncSetAttribute(gemm_kernel<N_QKV, true>,
                             cudaFuncAttributeMaxDynamicSharedMemorySize, GEMM_SMEM_BYTES);
        dim3 grid(N_QKV / 128, M_ROWS / 128);
        gemm_kernel<N_QKV, true><<<grid, 256, GEMM_SMEM_BYTES>>>(
            xh, xl, wqh, wql, b_qkv, nullptr);
    }
    // 2) RoPE on Q,K
    {
        int total = BH * SEQ * 64;
        rope_kernel<<<(total + 255) / 256, 256>>>();
    }
    // 3) Flash attention (mma.sync)
    {
        cudaFuncSetAttribute(attn_mma_kernel,
                             cudaFuncAttributeMaxDynamicSharedMemorySize, ATTN_SMEM_BYTES);
        dim3 grid(SEQ / 128, BH);
        attn_mma_kernel<<<grid, 256, ATTN_SMEM_BYTES>>>();
    }
    // 4) Output projection (pipelined split-bf16 mma)
    {
        cudaFuncSetAttribute(gemm_kernel<D_MODEL, false>,
                             cudaFuncAttributeMaxDynamicSharedMemorySize, GEMM_SMEM_BYTES);
        dim3 grid(D_MODEL / 128, M_ROWS / 128);
        gemm_kernel<D_MODEL, false><<<grid, 256, GEMM_SMEM_BYTES>>>(
            ch, cl, woh, wol, b_out, out);
    }
}

// round 5
// speedup vs baseline: 3.7478x; 1.0882x over previous
#include <cuda_runtime.h>
#include <cuda_bf16.h>
#include <cuda_fp16.h>
#include <math.h>
#include <stdint.h>

#define D_MODEL 2048
#define N_HEADS 16
#define D_HEAD 128
#define BATCH 4
#define SEQ 2048
#define M_ROWS (BATCH*SEQ)      /* 8192 */
#define N_QKV (3*D_MODEL)       /* 6144 */
#define BH (BATCH*N_HEADS)      /* 64  */

// ---------------- scratch (no allocation allowed) ----------------
__device__ float g_Q[(size_t)BH*SEQ*D_HEAD];
__device__ float g_K[(size_t)BH*SEQ*D_HEAD];
__device__ float g_V[(size_t)BH*SEQ*D_HEAD];

__device__ __nv_bfloat16 g_xh[(size_t)M_ROWS*D_MODEL];
__device__ __nv_bfloat16 g_xl[(size_t)M_ROWS*D_MODEL];
__device__ __nv_bfloat16 g_wqh[(size_t)D_MODEL*N_QKV];
__device__ __nv_bfloat16 g_wql[(size_t)D_MODEL*N_QKV];
__device__ __nv_bfloat16 g_woh[(size_t)D_MODEL*D_MODEL];
__device__ __nv_bfloat16 g_wol[(size_t)D_MODEL*D_MODEL];
__device__ __nv_bfloat16 g_ch[(size_t)M_ROWS*D_MODEL];
__device__ __nv_bfloat16 g_cl[(size_t)M_ROWS*D_MODEL];

// ---------------- helpers ----------------
__device__ __forceinline__ uint32_t smem_u32(const void* p) {
    return (uint32_t)__cvta_generic_to_shared(p);
}
#define CP_ASYNC16(dst, src) \
    asm volatile("cp.async.cg.shared.global [%0], [%1], 16;" :: "r"(dst), "l"(src))
#define CP_COMMIT()  asm volatile("cp.async.commit_group;" ::: "memory")
#define CP_WAITG(n)  asm volatile("cp.async.wait_group %0;" :: "n"(n) : "memory")

__device__ __forceinline__ void ldsm_x4(uint32_t (&r)[4], uint32_t addr) {
    asm volatile("ldmatrix.sync.aligned.m8n8.x4.shared.b16 {%0,%1,%2,%3}, [%4];"
                 : "=r"(r[0]), "=r"(r[1]), "=r"(r[2]), "=r"(r[3]) : "r"(addr));
}
__device__ __forceinline__ void ldsm_x2(uint32_t (&r)[2], uint32_t addr) {
    asm volatile("ldmatrix.sync.aligned.m8n8.x2.shared.b16 {%0,%1}, [%2];"
                 : "=r"(r[0]), "=r"(r[1]) : "r"(addr));
}
__device__ __forceinline__ void ldsm_x2t(uint32_t (&r)[2], uint32_t addr) {
    asm volatile("ldmatrix.sync.aligned.m8n8.x2.trans.shared.b16 {%0,%1}, [%2];"
                 : "=r"(r[0]), "=r"(r[1]) : "r"(addr));
}
__device__ __forceinline__ void mma_bf16(float (&d)[4], const uint32_t (&a)[4],
                                         const uint32_t (&b)[2]) {
    asm volatile("mma.sync.aligned.m16n8k16.row.col.f32.bf16.bf16.f32 "
                 "{%0,%1,%2,%3}, {%4,%5,%6,%7}, {%8,%9}, {%0,%1,%2,%3};"
                 : "+f"(d[0]), "+f"(d[1]), "+f"(d[2]), "+f"(d[3])
                 : "r"(a[0]), "r"(a[1]), "r"(a[2]), "r"(a[3]),
                   "r"(b[0]), "r"(b[1]));
}
__device__ __forceinline__ void mma_fp16(float (&d)[4], const uint32_t (&a)[4],
                                         const uint32_t (&b)[2]) {
    asm volatile("mma.sync.aligned.m16n8k16.row.col.f32.f16.f16.f32 "
                 "{%0,%1,%2,%3}, {%4,%5,%6,%7}, {%8,%9}, {%0,%1,%2,%3};"
                 : "+f"(d[0]), "+f"(d[1]), "+f"(d[2]), "+f"(d[3])
                 : "r"(a[0]), "r"(a[1]), "r"(a[2]), "r"(a[3]),
                   "r"(b[0]), "r"(b[1]));
}

// ---------------- fp32 -> split bf16 (hi + lo) ----------------
__global__ __launch_bounds__(256)
void split_kernel(const float* __restrict__ in,
                  __nv_bfloat16* __restrict__ hi,
                  __nv_bfloat16* __restrict__ lo, int n4)
{
    int idx = blockIdx.x * blockDim.x + threadIdx.x;
    if (idx >= n4) return;
    float4 v = *(const float4*)&in[idx * 4];
    float vv[4] = { v.x, v.y, v.z, v.w };
#pragma unroll
    for (int i = 0; i < 4; i++) {
        __nv_bfloat16 h = __float2bfloat16(vv[i]);
        hi[idx * 4 + i] = h;
        lo[idx * 4 + i] = __float2bfloat16(vv[i] - __bfloat162float(h));
    }
}

// ---------- split-bf16 GEMM: 128x128 tile, K-step 32, 4-stage cp.async ----
#define AS_STRIDE 40
#define BS_STRIDE 136
#define GA_TILE (128*AS_STRIDE)   /* 5120 elems */
#define GB_TILE (32*BS_STRIDE)    /* 4352 elems */
#define GSTAGE (2*GA_TILE + 2*GB_TILE)          /* elems per stage */
#define NSTAGE 4
#define GEMM_SMEM_BYTES (NSTAGE*GSTAGE*2)
#define NCHUNK (D_MODEL/32)

__device__ __forceinline__ void gemm_load_stage(char* dsm, int buf, int k0,
    const __nv_bfloat16* Ah, const __nv_bfloat16* Al,
    const __nv_bfloat16* Bh, const __nv_bfloat16* Bl,
    int row0, int col0, int N_DIM, int tid)
{
    uint32_t base = smem_u32(dsm) + (uint32_t)buf * (GSTAGE*2);
#pragma unroll
    for (int s = 0; s < 2; s++) {
        int id = tid + s * 256;
        int ra = id >> 2, ca = id & 3;
        uint32_t da = base + ra * (AS_STRIDE*2) + ca * 16;
        const size_t aoff = (size_t)(row0 + ra) * D_MODEL + k0 + ca * 8;
        CP_ASYNC16(da, Ah + aoff);
        CP_ASYNC16(da + GA_TILE*2, Al + aoff);
        int rb = id >> 4, cb = id & 15;
        uint32_t db = base + 2*GA_TILE*2 + rb * (BS_STRIDE*2) + cb * 16;
        const size_t boff = (size_t)(k0 + rb) * N_DIM + col0 + cb * 8;
        CP_ASYNC16(db, Bh + boff);
        CP_ASYNC16(db + GB_TILE*2, Bl + boff);
    }
}

__device__ __forceinline__ void store_qkv(int grow, int gcol, float val)
{
    int b_ = grow >> 11;
    int t_ = grow & 2047;
    int which = gcol >> 11;     // 0=q 1=k 2=v
    int rem   = gcol & 2047;
    int h     = rem >> 7;
    int dd    = rem & 127;
    size_t idx = (((size_t)b_ * N_HEADS + h) * SEQ + t_) * D_HEAD + dd;
    if (which == 0)      g_Q[idx] = val;
    else if (which == 1) g_K[idx] = val;
    else                 g_V[idx] = val;
}

template<int N_DIM, bool IS_QKV>
__global__ __launch_bounds__(256)
void gemm_kernel(const __nv_bfloat16* __restrict__ Ah,
                 const __nv_bfloat16* __restrict__ Al,
                 const __nv_bfloat16* __restrict__ Bh,
                 const __nv_bfloat16* __restrict__ Bl,
                 const float* __restrict__ bias,
                 float* __restrict__ out)
{
    extern __shared__ __align__(16) char dsm[];
    const int tid  = threadIdx.x;
    const int lane = tid & 31;
    const int warp = tid >> 5;
    const int wm = warp & 1;
    const int wn = warp >> 1;
    const int row0 = blockIdx.y * 128;
    const int col0 = blockIdx.x * 128;
    const int l16 = lane & 15;
    const int lhi = lane >> 4;

    float acc[4][4][4];
#pragma unroll
    for (int i = 0; i < 4; i++)
#pragma unroll
        for (int j = 0; j < 4; j++)
#pragma unroll
            for (int k = 0; k < 4; k++) acc[i][j][k] = 0.f;

    // prologue: stages 0..2 in flight
#pragma unroll
    for (int s = 0; s < 3; s++) {
        gemm_load_stage(dsm, s, s * 32, Ah, Al, Bh, Bl, row0, col0, N_DIM, tid);
        CP_COMMIT();
    }

#pragma unroll 1
    for (int c = 0; c < NCHUNK; c++) {
        CP_WAITG(2);          // oldest (chunk c) arrived
        __syncthreads();      // data visible; all threads done with chunk c-1 compute

        if (c + 3 < NCHUNK)
            gemm_load_stage(dsm, (c + 3) & 3, (c + 3) * 32, Ah, Al, Bh, Bl,
                            row0, col0, N_DIM, tid);
        CP_COMMIT();          // commit every iteration (possibly empty group)

        const __nv_bfloat16* Ahs = (const __nv_bfloat16*)(dsm + (size_t)(c & 3) * GSTAGE * 2);
        const __nv_bfloat16* Als = Ahs + GA_TILE;
        const __nv_bfloat16* Bhs = Als + GA_TILE;
        const __nv_bfloat16* Bls = Bhs + GB_TILE;

#pragma unroll
        for (int ksub = 0; ksub < 2; ksub++) {
            uint32_t bhf[4][2], blf[4][2];
#pragma unroll
            for (int nt = 0; nt < 4; nt++) {
                ldsm_x2t(bhf[nt], smem_u32(&Bhs[(ksub*16 + l16) * BS_STRIDE + wn*32 + nt*8]));
                ldsm_x2t(blf[nt], smem_u32(&Bls[(ksub*16 + l16) * BS_STRIDE + wn*32 + nt*8]));
            }
#pragma unroll
            for (int mt = 0; mt < 4; mt++) {
                uint32_t ah[4], al[4];
                ldsm_x4(ah, smem_u32(&Ahs[(wm*64 + mt*16 + l16) * AS_STRIDE + ksub*16 + lhi*8]));
                ldsm_x4(al, smem_u32(&Als[(wm*64 + mt*16 + l16) * AS_STRIDE + ksub*16 + lhi*8]));
#pragma unroll
                for (int nt = 0; nt < 4; nt++) {
                    mma_bf16(acc[mt][nt], ah, bhf[nt]);
                    mma_bf16(acc[mt][nt], ah, blf[nt]);
                    mma_bf16(acc[mt][nt], al, bhf[nt]);
                }
            }
        }
    }

    // epilogue (verified R2 mapping)
    const int g = lane >> 2, tq = lane & 3;
#pragma unroll
    for (int mt = 0; mt < 4; mt++) {
#pragma unroll
        for (int nt = 0; nt < 4; nt++) {
            int r = row0 + wm*64 + mt*16 + g;
            int cc = col0 + wn*32 + nt*8 + tq*2;
            float bias0 = __ldg(&bias[cc]);
            float bias1 = __ldg(&bias[cc + 1]);
            if (IS_QKV) {
                store_qkv(r,     cc,     acc[mt][nt][0] + bias0);
                store_qkv(r,     cc + 1, acc[mt][nt][1] + bias1);
                store_qkv(r + 8, cc,     acc[mt][nt][2] + bias0);
                store_qkv(r + 8, cc + 1, acc[mt][nt][3] + bias1);
            } else {
                out[(size_t)r * D_MODEL + cc]           = acc[mt][nt][0] + bias0;
                out[(size_t)r * D_MODEL + cc + 1]       = acc[mt][nt][1] + bias1;
                out[(size_t)(r + 8) * D_MODEL + cc]     = acc[mt][nt][2] + bias0;
                out[(size_t)(r + 8) * D_MODEL + cc + 1] = acc[mt][nt][3] + bias1;
            }
        }
    }
}

// ---------------- RoPE (in-place on g_Q, g_K) ----------------
__global__ __launch_bounds__(256)
void rope_kernel()
{
    int idx = blockIdx.x * blockDim.x + threadIdx.x;
    if (idx >= BH * SEQ * 64) return;
    int i  = idx & 63;
    int t  = (idx >> 6) & (SEQ - 1);
    int bh = idx >> 17;

    float inv = __expf(-(float)i * (9.210340371976184f / 64.0f));
    float freq = (float)t * inv;
    float s, c;
    __sincosf(freq, &s, &c);

    size_t base = ((size_t)bh * SEQ + t) * D_HEAD;
    float q1 = g_Q[base + i], q2 = g_Q[base + i + 64];
    g_Q[base + i]      = q1 * c - q2 * s;
    g_Q[base + i + 64] = q2 * c + q1 * s;
    float k1 = g_K[base + i], k2 = g_K[base + i + 64];
    g_K[base + i]      = k1 * c - k2 * s;
    g_K[base + i + 64] = k2 * c + k1 * s;
}

// ---------------- Flash attention via mma.sync (1-term fp16) ----------------
// BM=128 queries, BN=64 keys/iter, dh=128, 8 warps (warp w owns rows w*16..+15).
// Layout recipes identical to verified R4 kernel; hi-only operands in fp16.
#define TS 136
#define PS 72
#define ATTN_Q_ELEMS (128*TS)
#define ATTN_K_ELEMS (64*TS)
#define ATTN_P_ELEMS (128*PS)
#define ATTN_SMEM_BYTES ((ATTN_Q_ELEMS + 2*ATTN_K_ELEMS + ATTN_P_ELEMS)*2)

__global__ __launch_bounds__(256)
void attn_mma_kernel()
{
    extern __shared__ __align__(16) char dsm[];
    __half* Qh = (__half*)dsm;
    __half* Kh = Qh + ATTN_Q_ELEMS;
    __half* Vh = Kh + ATTN_K_ELEMS;
    __half* Ph = Vh + ATTN_K_ELEMS;

    const int bh = blockIdx.y;
    const int qt = blockIdx.x;
    const int q0 = qt * 128;
    const float SC2 = 0.08838834764831845f * 1.4426950408889634f; // scale*log2e

    const float* Qg = g_Q + (size_t)bh * SEQ * D_HEAD;
    const float* Kg = g_K + (size_t)bh * SEQ * D_HEAD;
    const float* Vg = g_V + (size_t)bh * SEQ * D_HEAD;

    const int tid = threadIdx.x;
    const int warp = tid >> 5, lane = tid & 31;
    const int m0 = warp * 16;
    const int l16 = lane & 15, lhi = lane >> 4;
    const int g = lane >> 2, tq = lane & 3;

    // load Q tile (fp32 -> fp16 smem)
    for (int i = tid; i < 128 * 32; i += 256) {
        int r = i >> 5, c4 = i & 31;
        float4 v = *(const float4*)&Qg[(size_t)(q0 + r) * D_HEAD + c4 * 4];
        __half2 h01, h23;
        h01.x = __float2half(v.x); h01.y = __float2half(v.y);
        h23.x = __float2half(v.z); h23.y = __float2half(v.w);
        *(__half2*)&Qh[r * TS + c4 * 4]     = h01;
        *(__half2*)&Qh[r * TS + c4 * 4 + 2] = h23;
    }

    float mI0 = -INFINITY, mI1 = -INFINITY, lI0 = 0.f, lI1 = 0.f;
    float ctx[16][4];
#pragma unroll
    for (int i = 0; i < 16; i++)
#pragma unroll
        for (int j = 0; j < 4; j++) ctx[i][j] = 0.f;

    const int ktiles = 2 * qt + 2;
#pragma unroll 1
    for (int kt = 0; kt < ktiles; kt++) {
        const int kb = kt * 64;
        __syncthreads();   // prior-iter K/V/P reads complete
        for (int i = tid; i < 64 * 32; i += 256) {
            int r = i >> 5, c4 = i & 31;
            size_t goff = (size_t)(kb + r) * D_HEAD + c4 * 4;
            float4 kv = *(const float4*)&Kg[goff];
            __half2 h01, h23;
            h01.x = __float2half(kv.x); h01.y = __float2half(kv.y);
            h23.x = __float2half(kv.z); h23.y = __float2half(kv.w);
            *(__half2*)&Kh[r * TS + c4 * 4]     = h01;
            *(__half2*)&Kh[r * TS + c4 * 4 + 2] = h23;
            float4 vv = *(const float4*)&Vg[goff];
            __half2 v01, v23;
            v01.x = __float2half(vv.x); v01.y = __float2half(vv.y);
            v23.x = __float2half(vv.z); v23.y = __float2half(vv.w);
            *(__half2*)&Vh[r * TS + c4 * 4]     = v01;
            *(__half2*)&Vh[r * TS + c4 * 4 + 2] = v23;
        }
        __syncthreads();

        // ---- scores S = Q @ K^T (fp16 1-term) ----
        float sacc[8][4];
#pragma unroll
        for (int nt = 0; nt < 8; nt++)
#pragma unroll
            for (int e = 0; e < 4; e++) sacc[nt][e] = 0.f;

        const int krow = lane & 7;
        const int kcolsel = ((lane >> 3) & 1) * 8;
#pragma unroll
        for (int ks = 0; ks < 8; ks++) {
            uint32_t ah[4];
            ldsm_x4(ah, smem_u32(&Qh[(m0 + l16) * TS + ks * 16 + lhi * 8]));
#pragma unroll
            for (int nt = 0; nt < 8; nt++) {
                uint32_t bhf[2];
                ldsm_x2(bhf, smem_u32(&Kh[(nt * 8 + krow) * TS + ks * 16 + kcolsel]));
                mma_fp16(sacc[nt], ah, bhf);
            }
        }

        // ---- online softmax (base-2) ----
        const bool diag = (kt >= ktiles - 2);
        const int r0 = q0 + m0 + g, r1 = r0 + 8;
        float rm0 = -INFINITY, rm1 = -INFINITY;
#pragma unroll
        for (int nt = 0; nt < 8; nt++) {
            int cb0 = kb + nt * 8 + tq * 2;
            float s0 = sacc[nt][0] * SC2, s1 = sacc[nt][1] * SC2;
            float s2 = sacc[nt][2] * SC2, s3 = sacc[nt][3] * SC2;
            if (diag) {
                if (cb0     > r0) s0 = -INFINITY;
                if (cb0 + 1 > r0) s1 = -INFINITY;
                if (cb0     > r1) s2 = -INFINITY;
                if (cb0 + 1 > r1) s3 = -INFINITY;
            }
            sacc[nt][0] = s0; sacc[nt][1] = s1; sacc[nt][2] = s2; sacc[nt][3] = s3;
            rm0 = fmaxf(rm0, fmaxf(s0, s1));
            rm1 = fmaxf(rm1, fmaxf(s2, s3));
        }
        rm0 = fmaxf(rm0, __shfl_xor_sync(0xffffffffu, rm0, 1));
        rm0 = fmaxf(rm0, __shfl_xor_sync(0xffffffffu, rm0, 2));
        rm1 = fmaxf(rm1, __shfl_xor_sync(0xffffffffu, rm1, 1));
        rm1 = fmaxf(rm1, __shfl_xor_sync(0xffffffffu, rm1, 2));
        float mn0 = fmaxf(mI0, rm0), mn1 = fmaxf(mI1, rm1);
        float c0 = exp2f(mI0 - mn0), c1 = exp2f(mI1 - mn1);
        float ps0 = 0.f, ps1 = 0.f;
#pragma unroll
        for (int nt = 0; nt < 8; nt++) {
            float p0 = exp2f(sacc[nt][0] - mn0);
            float p1 = exp2f(sacc[nt][1] - mn0);
            float p2 = exp2f(sacc[nt][2] - mn1);
            float p3 = exp2f(sacc[nt][3] - mn1);
            ps0 += p0 + p1; ps1 += p2 + p3;
            __half2 ph;
            ph.x = __float2half(p0); ph.y = __float2half(p1);
            *(__half2*)&Ph[(m0 + g) * PS + nt * 8 + tq * 2] = ph;
            ph.x = __float2half(p2); ph.y = __float2half(p3);
            *(__half2*)&Ph[(m0 + g + 8) * PS + nt * 8 + tq * 2] = ph;
        }
        ps0 += __shfl_xor_sync(0xffffffffu, ps0, 1);
        ps0 += __shfl_xor_sync(0xffffffffu, ps0, 2);
        ps1 += __shfl_xor_sync(0xffffffffu, ps1, 1);
        ps1 += __shfl_xor_sync(0xffffffffu, ps1, 2);
        lI0 = lI0 * c0 + ps0; lI1 = lI1 * c1 + ps1;
        mI0 = mn0; mI1 = mn1;
#pragma unroll
        for (int n2 = 0; n2 < 16; n2++) {
            ctx[n2][0] *= c0; ctx[n2][1] *= c0;
            ctx[n2][2] *= c1; ctx[n2][3] *= c1;
        }
        __syncwarp();   // P rows are per-warp; make STS visible to warp's ldmatrix

        // ---- ctx += P @ V (fp16 1-term) ----
#pragma unroll
        for (int ks = 0; ks < 4; ks++) {
            uint32_t aph[4];
            ldsm_x4(aph, smem_u32(&Ph[(m0 + l16) * PS + ks * 16 + lhi * 8]));
#pragma unroll
            for (int nt = 0; nt < 16; nt++) {
                uint32_t bhf[2];
                ldsm_x2t(bhf, smem_u32(&Vh[(ks * 16 + l16) * TS + nt * 8]));
                mma_fp16(ctx[nt], aph, bhf);
            }
        }
    }

    // ---- epilogue: normalize, split to bf16 hi/lo, write (b*t, d_model) ----
    float ri0 = 1.0f / lI0, ri1 = 1.0f / lI1;
    const int b_ = bh >> 4, h_ = bh & 15;
    const int t0 = q0 + m0 + g, t1 = t0 + 8;
#pragma unroll
    for (int nt = 0; nt < 16; nt++) {
        int col = h_ * D_HEAD + nt * 8 + tq * 2;
        {
            float o0 = ctx[nt][0] * ri0, o1 = ctx[nt][1] * ri0;
            __nv_bfloat162 hh, ll;
            hh.x = __float2bfloat16(o0); ll.x = __float2bfloat16(o0 - __bfloat162float(hh.x));
            hh.y = __float2bfloat16(o1); ll.y = __float2bfloat16(o1 - __bfloat162float(hh.y));
            size_t idx = (size_t)(b_ * SEQ + t0) * D_MODEL + col;
            *(__nv_bfloat162*)&g_ch[idx] = hh;
            *(__nv_bfloat162*)&g_cl[idx] = ll;
        }
        {
            float o0 = ctx[nt][2] * ri1, o1 = ctx[nt][3] * ri1;
            __nv_bfloat162 hh, ll;
            hh.x = __float2bfloat16(o0); ll.x = __float2bfloat16(o0 - __bfloat162float(hh.x));
            hh.y = __float2bfloat16(o1); ll.y = __float2bfloat16(o1 - __bfloat162float(hh.y));
            size_t idx = (size_t)(b_ * SEQ + t1) * D_MODEL + col;
            *(__nv_bfloat162*)&g_ch[idx] = hh;
            *(__nv_bfloat162*)&g_cl[idx] = ll;
        }
    }
}

// ---------------- launcher ----------------
extern "C" void kernel_launch(void* const* d_in, const int* in_sizes, int n_in,
                              void* d_out, int out_size)
{
    const float* x     = (const float*)d_in[0];
    const float* w_qkv = (const float*)d_in[1];
    const float* b_qkv = (const float*)d_in[2];
    const float* w_out = (const float*)d_in[3];
    const float* b_out = (const float*)d_in[4];
    float* out = (float*)d_out;

    (void)in_sizes; (void)n_in; (void)out_size;

    __nv_bfloat16 *xh, *xl, *wqh, *wql, *woh, *wol, *ch, *cl;
    cudaGetSymbolAddress((void**)&xh,  g_xh);
    cudaGetSymbolAddress((void**)&xl,  g_xl);
    cudaGetSymbolAddress((void**)&wqh, g_wqh);
    cudaGetSymbolAddress((void**)&wql, g_wql);
    cudaGetSymbolAddress((void**)&woh, g_woh);
    cudaGetSymbolAddress((void**)&wol, g_wol);
    cudaGetSymbolAddress((void**)&ch,  g_ch);
    cudaGetSymbolAddress((void**)&cl,  g_cl);

    // 0) split fp32 -> (hi, lo) bf16
    {
        int n4 = M_ROWS * D_MODEL / 4;
        split_kernel<<<(n4 + 255) / 256, 256>>>(x, xh, xl, n4);
        n4 = D_MODEL * N_QKV / 4;
        split_kernel<<<(n4 + 255) / 256, 256>>>(w_qkv, wqh, wql, n4);
        n4 = D_MODEL * D_MODEL / 4;
        split_kernel<<<(n4 + 255) / 256, 256>>>(w_out, woh, wol, n4);
    }
    // 1) QKV projection (4-stage pipelined split-bf16 mma)
    {
        cudaFuncSetAttribute(gemm_kernel<N_QKV, true>,
                             cudaFuncAttributeMaxDynamicSharedMemorySize, GEMM_SMEM_BYTES);
        dim3 grid(N_QKV / 128, M_ROWS / 128);
        gemm_kernel<N_QKV, true><<<grid, 256, GEMM_SMEM_BYTES>>>(
            xh, xl, wqh, wql, b_qkv, nullptr);
    }
    // 2) RoPE on Q,K
    {
        int total = BH * SEQ * 64;
        rope_kernel<<<(total + 255) / 256, 256>>>();
    }
    // 3) Flash attention (1-term fp16 mma)
    {
        cudaFuncSetAttribute(attn_mma_kernel,
                             cudaFuncAttributeMaxDynamicSharedMemorySize, ATTN_SMEM_BYTES);
        dim3 grid(SEQ / 128, BH);
        attn_mma_kernel<<<grid, 256, ATTN_SMEM_BYTES>>>();
    }
    // 4) Output projection (4-stage pipelined split-bf16 mma)
    {
        cudaFuncSetAttribute(gemm_kernel<D_MODEL, false>,
                             cudaFuncAttributeMaxDynamicSharedMemorySize, GEMM_SMEM_BYTES);
        dim3 grid(D_MODEL / 128, M_ROWS / 128);
        gemm_kernel<D_MODEL, false><<<grid, 256, GEMM_SMEM_BYTES>>>(
            ch, cl, woh, wol, b_out, out);
    }
}

// round 6
// speedup vs baseline: 4.1454x; 1.1061x over previous
#include <cuda_runtime.h>
#include <cuda_bf16.h>
#include <cuda_fp16.h>
#include <math.h>
#include <stdint.h>

#define D_MODEL 2048
#define N_HEADS 16
#define D_HEAD 128
#define BATCH 4
#define SEQ 2048
#define M_ROWS (BATCH*SEQ)      /* 8192 */
#define N_QKV (3*D_MODEL)       /* 6144 */
#define BH (BATCH*N_HEADS)      /* 64  */

// ---------------- scratch (no allocation allowed) ----------------
__device__ float g_Q[(size_t)BH*SEQ*D_HEAD];
__device__ float g_K[(size_t)BH*SEQ*D_HEAD];
__device__ __half g_Qh[(size_t)BH*SEQ*D_HEAD];
__device__ __half g_Kh[(size_t)BH*SEQ*D_HEAD];
__device__ __half g_Vh[(size_t)BH*SEQ*D_HEAD];

__device__ __nv_bfloat16 g_xh[(size_t)M_ROWS*D_MODEL];
__device__ __nv_bfloat16 g_xl[(size_t)M_ROWS*D_MODEL];
__device__ __nv_bfloat16 g_wqh[(size_t)D_MODEL*N_QKV];
__device__ __nv_bfloat16 g_wql[(size_t)D_MODEL*N_QKV];
__device__ __nv_bfloat16 g_woh[(size_t)D_MODEL*D_MODEL];
__device__ __nv_bfloat16 g_wol[(size_t)D_MODEL*D_MODEL];
__device__ __nv_bfloat16 g_ch[(size_t)M_ROWS*D_MODEL];
__device__ __nv_bfloat16 g_cl[(size_t)M_ROWS*D_MODEL];

// ---------------- helpers ----------------
__device__ __forceinline__ uint32_t smem_u32(const void* p) {
    return (uint32_t)__cvta_generic_to_shared(p);
}
#define CP_ASYNC16(dst, src) \
    asm volatile("cp.async.cg.shared.global [%0], [%1], 16;" :: "r"(dst), "l"(src))
#define CP_COMMIT()  asm volatile("cp.async.commit_group;" ::: "memory")
#define CP_WAITG(n)  asm volatile("cp.async.wait_group %0;" :: "n"(n) : "memory")

__device__ __forceinline__ void ldsm_x4(uint32_t (&r)[4], uint32_t addr) {
    asm volatile("ldmatrix.sync.aligned.m8n8.x4.shared.b16 {%0,%1,%2,%3}, [%4];"
                 : "=r"(r[0]), "=r"(r[1]), "=r"(r[2]), "=r"(r[3]) : "r"(addr));
}
__device__ __forceinline__ void ldsm_x4t(uint32_t (&r)[4], uint32_t addr) {
    asm volatile("ldmatrix.sync.aligned.m8n8.x4.trans.shared.b16 {%0,%1,%2,%3}, [%4];"
                 : "=r"(r[0]), "=r"(r[1]), "=r"(r[2]), "=r"(r[3]) : "r"(addr));
}
__device__ __forceinline__ void ldsm_x2t(uint32_t (&r)[2], uint32_t addr) {
    asm volatile("ldmatrix.sync.aligned.m8n8.x2.trans.shared.b16 {%0,%1}, [%2];"
                 : "=r"(r[0]), "=r"(r[1]) : "r"(addr));
}
__device__ __forceinline__ void mma_bf16(float (&d)[4], const uint32_t (&a)[4],
                                         const uint32_t (&b)[2]) {
    asm volatile("mma.sync.aligned.m16n8k16.row.col.f32.bf16.bf16.f32 "
                 "{%0,%1,%2,%3}, {%4,%5,%6,%7}, {%8,%9}, {%0,%1,%2,%3};"
                 : "+f"(d[0]), "+f"(d[1]), "+f"(d[2]), "+f"(d[3])
                 : "r"(a[0]), "r"(a[1]), "r"(a[2]), "r"(a[3]),
                   "r"(b[0]), "r"(b[1]));
}
__device__ __forceinline__ void mma_fp16(float (&d)[4], const uint32_t (&a)[4],
                                         const uint32_t (&b)[2]) {
    asm volatile("mma.sync.aligned.m16n8k16.row.col.f32.f16.f16.f32 "
                 "{%0,%1,%2,%3}, {%4,%5,%6,%7}, {%8,%9}, {%0,%1,%2,%3};"
                 : "+f"(d[0]), "+f"(d[1]), "+f"(d[2]), "+f"(d[3])
                 : "r"(a[0]), "r"(a[1]), "r"(a[2]), "r"(a[3]),
                   "r"(b[0]), "r"(b[1]));
}

// ---------------- fp32 -> split bf16 (hi + lo) ----------------
__global__ __launch_bounds__(256)
void split_kernel(const float* __restrict__ in,
                  __nv_bfloat16* __restrict__ hi,
                  __nv_bfloat16* __restrict__ lo, int n4)
{
    int idx = blockIdx.x * blockDim.x + threadIdx.x;
    if (idx >= n4) return;
    float4 v = *(const float4*)&in[idx * 4];
    float vv[4] = { v.x, v.y, v.z, v.w };
#pragma unroll
    for (int i = 0; i < 4; i++) {
        __nv_bfloat16 h = __float2bfloat16(vv[i]);
        hi[idx * 4 + i] = h;
        lo[idx * 4 + i] = __float2bfloat16(vv[i] - __bfloat162float(h));
    }
}

// ---------- split-bf16 GEMM: 128x128 tile, K-step 32, 3-stage cp.async ----
#define AS_STRIDE 40
#define BS_STRIDE 136
#define GA_TILE (128*AS_STRIDE)   /* 5120 elems */
#define GB_TILE (32*BS_STRIDE)    /* 4352 elems */
#define GSTAGE (2*GA_TILE + 2*GB_TILE)          /* elems per stage */
#define NSTAGE 3
#define GEMM_SMEM_BYTES (NSTAGE*GSTAGE*2)       /* 113664 */
#define NCHUNK (D_MODEL/32)

__device__ __forceinline__ void gemm_load_stage(char* dsm, int buf, int k0,
    const __nv_bfloat16* Ah, const __nv_bfloat16* Al,
    const __nv_bfloat16* Bh, const __nv_bfloat16* Bl,
    int row0, int col0, int N_DIM, int tid)
{
    uint32_t base = smem_u32(dsm) + (uint32_t)buf * (GSTAGE*2);
#pragma unroll
    for (int s = 0; s < 2; s++) {
        int id = tid + s * 256;
        int ra = id >> 2, ca = id & 3;
        uint32_t da = base + ra * (AS_STRIDE*2) + ca * 16;
        const size_t aoff = (size_t)(row0 + ra) * D_MODEL + k0 + ca * 8;
        CP_ASYNC16(da, Ah + aoff);
        CP_ASYNC16(da + GA_TILE*2, Al + aoff);
        int rb = id >> 4, cb = id & 15;
        uint32_t db = base + 2*GA_TILE*2 + rb * (BS_STRIDE*2) + cb * 16;
        const size_t boff = (size_t)(k0 + rb) * N_DIM + col0 + cb * 8;
        CP_ASYNC16(db, Bh + boff);
        CP_ASYNC16(db + GB_TILE*2, Bl + boff);
    }
}

__device__ __forceinline__ void store_qkv(int grow, int gcol, float val)
{
    int b_ = grow >> 11;
    int t_ = grow & 2047;
    int which = gcol >> 11;     // 0=q 1=k 2=v
    int rem   = gcol & 2047;
    int h     = rem >> 7;
    int dd    = rem & 127;
    size_t idx = (((size_t)b_ * N_HEADS + h) * SEQ + t_) * D_HEAD + dd;
    if (which == 0)      g_Q[idx] = val;
    else if (which == 1) g_K[idx] = val;
    else                 g_Vh[idx] = __float2half(val);   // V used only in fp16
}

template<int N_DIM, bool IS_QKV>
__global__ __launch_bounds__(256)
void gemm_kernel(const __nv_bfloat16* __restrict__ Ah,
                 const __nv_bfloat16* __restrict__ Al,
                 const __nv_bfloat16* __restrict__ Bh,
                 const __nv_bfloat16* __restrict__ Bl,
                 const float* __restrict__ bias,
                 float* __restrict__ out)
{
    extern __shared__ __align__(16) char dsm[];
    const int tid  = threadIdx.x;
    const int lane = tid & 31;
    const int warp = tid >> 5;
    const int wm = warp & 1;
    const int wn = warp >> 1;
    const int row0 = blockIdx.y * 128;
    const int col0 = blockIdx.x * 128;
    const int l16 = lane & 15;
    const int lhi = lane >> 4;

    float acc[4][4][4];
#pragma unroll
    for (int i = 0; i < 4; i++)
#pragma unroll
        for (int j = 0; j < 4; j++)
#pragma unroll
            for (int k = 0; k < 4; k++) acc[i][j][k] = 0.f;

    // prologue: chunks 0,1 in flight
    gemm_load_stage(dsm, 0, 0,  Ah, Al, Bh, Bl, row0, col0, N_DIM, tid);
    CP_COMMIT();
    gemm_load_stage(dsm, 1, 32, Ah, Al, Bh, Bl, row0, col0, N_DIM, tid);
    CP_COMMIT();

    int bufc = 0;                 // compute buffer = c % 3
#pragma unroll 1
    for (int c = 0; c < NCHUNK; c++) {
        CP_WAITG(1);              // chunk c arrived (c+1 may be pending)
        __syncthreads();          // all threads finished compute c-1; c visible

        // load chunk c+2 into buf (c+2)%3 == (c-1)%3 (safe after sync)
        int bufl = bufc + 2; if (bufl >= 3) bufl -= 3;
        if (c + 2 < NCHUNK)
            gemm_load_stage(dsm, bufl, (c + 2) * 32, Ah, Al, Bh, Bl,
                            row0, col0, N_DIM, tid);
        CP_COMMIT();

        const __nv_bfloat16* Ahs = (const __nv_bfloat16*)(dsm + (size_t)bufc * GSTAGE * 2);
        const __nv_bfloat16* Als = Ahs + GA_TILE;
        const __nv_bfloat16* Bhs = Als + GA_TILE;
        const __nv_bfloat16* Bls = Bhs + GB_TILE;

#pragma unroll
        for (int ksub = 0; ksub < 2; ksub++) {
            uint32_t bhf[4][2], blf[4][2];
#pragma unroll
            for (int nt = 0; nt < 4; nt++) {
                ldsm_x2t(bhf[nt], smem_u32(&Bhs[(ksub*16 + l16) * BS_STRIDE + wn*32 + nt*8]));
                ldsm_x2t(blf[nt], smem_u32(&Bls[(ksub*16 + l16) * BS_STRIDE + wn*32 + nt*8]));
            }
#pragma unroll
            for (int mt = 0; mt < 4; mt++) {
                uint32_t ah[4], al[4];
                ldsm_x4(ah, smem_u32(&Ahs[(wm*64 + mt*16 + l16) * AS_STRIDE + ksub*16 + lhi*8]));
                ldsm_x4(al, smem_u32(&Als[(wm*64 + mt*16 + l16) * AS_STRIDE + ksub*16 + lhi*8]));
#pragma unroll
                for (int nt = 0; nt < 4; nt++) {
                    mma_bf16(acc[mt][nt], ah, bhf[nt]);
                    mma_bf16(acc[mt][nt], ah, blf[nt]);
                    mma_bf16(acc[mt][nt], al, bhf[nt]);
                }
            }
        }
        bufc++; if (bufc >= 3) bufc = 0;
    }

    // epilogue (verified R2 mapping)
    const int g = lane >> 2, tq = lane & 3;
#pragma unroll
    for (int mt = 0; mt < 4; mt++) {
#pragma unroll
        for (int nt = 0; nt < 4; nt++) {
            int r = row0 + wm*64 + mt*16 + g;
            int cc = col0 + wn*32 + nt*8 + tq*2;
            float bias0 = __ldg(&bias[cc]);
            float bias1 = __ldg(&bias[cc + 1]);
            if (IS_QKV) {
                store_qkv(r,     cc,     acc[mt][nt][0] + bias0);
                store_qkv(r,     cc + 1, acc[mt][nt][1] + bias1);
                store_qkv(r + 8, cc,     acc[mt][nt][2] + bias0);
                store_qkv(r + 8, cc + 1, acc[mt][nt][3] + bias1);
            } else {
                out[(size_t)r * D_MODEL + cc]           = acc[mt][nt][0] + bias0;
                out[(size_t)r * D_MODEL + cc + 1]       = acc[mt][nt][1] + bias1;
                out[(size_t)(r + 8) * D_MODEL + cc]     = acc[mt][nt][2] + bias0;
                out[(size_t)(r + 8) * D_MODEL + cc + 1] = acc[mt][nt][3] + bias1;
            }
        }
    }
}

// -------- RoPE: read fp32 Q/K, write rotated fp16 Q/K for attention --------
__global__ __launch_bounds__(256)
void rope_kernel()
{
    int idx = blockIdx.x * blockDim.x + threadIdx.x;
    if (idx >= BH * SEQ * 64) return;
    int i  = idx & 63;
    int t  = (idx >> 6) & (SEQ - 1);
    int bh = idx >> 17;

    float inv = __expf(-(float)i * (9.210340371976184f / 64.0f));
    float freq = (float)t * inv;
    float s, c;
    __sincosf(freq, &s, &c);

    size_t base = ((size_t)bh * SEQ + t) * D_HEAD;
    float q1 = g_Q[base + i], q2 = g_Q[base + i + 64];
    g_Qh[base + i]      = __float2half(q1 * c - q2 * s);
    g_Qh[base + i + 64] = __float2half(q2 * c + q1 * s);
    float k1 = g_K[base + i], k2 = g_K[base + i + 64];
    g_Kh[base + i]      = __float2half(k1 * c - k2 * s);
    g_Kh[base + i + 64] = __float2half(k2 * c + k1 * s);
}

// ---------------- Flash attention via mma.sync (fp16) ----------------
// BM=128 queries, BN=64 keys/iter, dh=128, 8 warps (warp w owns rows w*16..+15).
// Operands pre-converted to fp16 in gmem; staged via cp.async.
// K fragments: ldsm.x4 (2 n-tiles/instr), V: ldsm.x4.trans (2 n-tiles/instr).
#define TS 136
#define PS 72
#define ATTN_Q_ELEMS (128*TS)
#define ATTN_K_ELEMS (64*TS)
#define ATTN_P_ELEMS (128*PS)
#define ATTN_SMEM_BYTES ((ATTN_Q_ELEMS + 2*ATTN_K_ELEMS + ATTN_P_ELEMS)*2)

__global__ __launch_bounds__(256)
void attn_mma_kernel()
{
    extern __shared__ __align__(16) char dsm[];
    __half* Qs = (__half*)dsm;
    __half* Ks = Qs + ATTN_Q_ELEMS;
    __half* Vs = Ks + ATTN_K_ELEMS;
    __half* Ps = Vs + ATTN_K_ELEMS;

    const int bh = blockIdx.y;
    const int qt = blockIdx.x;
    const int q0 = qt * 128;
    const float SC2 = 0.08838834764831845f * 1.4426950408889634f; // scale*log2e

    const __half* Qg = g_Qh + (size_t)bh * SEQ * D_HEAD;
    const __half* Kg = g_Kh + (size_t)bh * SEQ * D_HEAD;
    const __half* Vg = g_Vh + (size_t)bh * SEQ * D_HEAD;

    const int tid = threadIdx.x;
    const int warp = tid >> 5, lane = tid & 31;
    const int m0 = warp * 16;
    const int l16 = lane & 15, lhi = lane >> 4;
    const int g = lane >> 2, tq = lane & 3;

    // load Q tile via cp.async (128 rows x 16 16B-chunks)
    for (int i = tid; i < 128 * 16; i += 256) {
        int r = i >> 4, c16 = i & 15;
        CP_ASYNC16(smem_u32(&Qs[r * TS + c16 * 8]),
                   &Qg[(size_t)(q0 + r) * D_HEAD + c16 * 8]);
    }
    CP_COMMIT();

    float mI0 = -INFINITY, mI1 = -INFINITY, lI0 = 0.f, lI1 = 0.f;
    float ctx[16][4];
#pragma unroll
    for (int i = 0; i < 16; i++)
#pragma unroll
        for (int j = 0; j < 4; j++) ctx[i][j] = 0.f;

    const int ktiles = 2 * qt + 2;
#pragma unroll 1
    for (int kt = 0; kt < ktiles; kt++) {
        const int kb = kt * 64;
        __syncthreads();   // prior-iter K/V/P reads complete
        for (int i = tid; i < 64 * 16; i += 256) {
            int r = i >> 4, c16 = i & 15;
            size_t goff = (size_t)(kb + r) * D_HEAD + c16 * 8;
            CP_ASYNC16(smem_u32(&Ks[r * TS + c16 * 8]), &Kg[goff]);
            CP_ASYNC16(smem_u32(&Vs[r * TS + c16 * 8]), &Vg[goff]);
        }
        CP_COMMIT();
        CP_WAITG(0);
        __syncthreads();

        // ---- scores S = Q @ K^T (fp16) ----
        float sacc[8][4];
#pragma unroll
        for (int nt = 0; nt < 8; nt++)
#pragma unroll
            for (int e = 0; e < 4; e++) sacc[nt][e] = 0.f;

        // K x4 address: row=(2*np + (lane>>4))*8 + (lane&7), col=ks*16+((lane>>3)&1)*8
        const int krow = lane & 7;
        const int kpair = (lane >> 4) & 1;
        const int kcolsel = ((lane >> 3) & 1) * 8;
#pragma unroll
        for (int ks = 0; ks < 8; ks++) {
            uint32_t ah[4];
            ldsm_x4(ah, smem_u32(&Qs[(m0 + l16) * TS + ks * 16 + lhi * 8]));
#pragma unroll
            for (int np = 0; np < 4; np++) {
                uint32_t bk[4];
                ldsm_x4(bk, smem_u32(&Ks[((np * 2 + kpair) * 8 + krow) * TS +
                                         ks * 16 + kcolsel]));
                uint32_t b0[2] = { bk[0], bk[1] };
                uint32_t b1[2] = { bk[2], bk[3] };
                mma_fp16(sacc[np * 2],     ah, b0);
                mma_fp16(sacc[np * 2 + 1], ah, b1);
            }
        }

        // ---- online softmax (base-2) ----
        const bool diag = (kt >= ktiles - 2);
        const int r0 = q0 + m0 + g, r1 = r0 + 8;
        float rm0 = -INFINITY, rm1 = -INFINITY;
#pragma unroll
        for (int nt = 0; nt < 8; nt++) {
            int cb0 = kb + nt * 8 + tq * 2;
            float s0 = sacc[nt][0] * SC2, s1 = sacc[nt][1] * SC2;
            float s2 = sacc[nt][2] * SC2, s3 = sacc[nt][3] * SC2;
            if (diag) {
                if (cb0     > r0) s0 = -INFINITY;
                if (cb0 + 1 > r0) s1 = -INFINITY;
                if (cb0     > r1) s2 = -INFINITY;
                if (cb0 + 1 > r1) s3 = -INFINITY;
            }
            sacc[nt][0] = s0; sacc[nt][1] = s1; sacc[nt][2] = s2; sacc[nt][3] = s3;
            rm0 = fmaxf(rm0, fmaxf(s0, s1));
            rm1 = fmaxf(rm1, fmaxf(s2, s3));
        }
        rm0 = fmaxf(rm0, __shfl_xor_sync(0xffffffffu, rm0, 1));
        rm0 = fmaxf(rm0, __shfl_xor_sync(0xffffffffu, rm0, 2));
        rm1 = fmaxf(rm1, __shfl_xor_sync(0xffffffffu, rm1, 1));
        rm1 = fmaxf(rm1, __shfl_xor_sync(0xffffffffu, rm1, 2));
        float mn0 = fmaxf(mI0, rm0), mn1 = fmaxf(mI1, rm1);
        float c0 = exp2f(mI0 - mn0), c1 = exp2f(mI1 - mn1);
        float ps0 = 0.f, ps1 = 0.f;
#pragma unroll
        for (int nt = 0; nt < 8; nt++) {
            float p0 = exp2f(sacc[nt][0] - mn0);
            float p1 = exp2f(sacc[nt][1] - mn0);
            float p2 = exp2f(sacc[nt][2] - mn1);
            float p3 = exp2f(sacc[nt][3] - mn1);
            ps0 += p0 + p1; ps1 += p2 + p3;
            __half2 ph;
            ph.x = __float2half(p0); ph.y = __float2half(p1);
            *(__half2*)&Ps[(m0 + g) * PS + nt * 8 + tq * 2] = ph;
            ph.x = __float2half(p2); ph.y = __float2half(p3);
            *(__half2*)&Ps[(m0 + g + 8) * PS + nt * 8 + tq * 2] = ph;
        }
        ps0 += __shfl_xor_sync(0xffffffffu, ps0, 1);
        ps0 += __shfl_xor_sync(0xffffffffu, ps0, 2);
        ps1 += __shfl_xor_sync(0xffffffffu, ps1, 1);
        ps1 += __shfl_xor_sync(0xffffffffu, ps1, 2);
        lI0 = lI0 * c0 + ps0; lI1 = lI1 * c1 + ps1;
        mI0 = mn0; mI1 = mn1;
#pragma unroll
        for (int n2 = 0; n2 < 16; n2++) {
            ctx[n2][0] *= c0; ctx[n2][1] *= c0;
            ctx[n2][2] *= c1; ctx[n2][3] *= c1;
        }
        __syncwarp();   // P rows are per-warp; make STS visible to warp's ldmatrix

        // ---- ctx += P @ V (fp16) ----
        // V x4t address: row = ks*16 + (lane&15), col = (2*np + (lane>>4))*8
        const int vpair = lane >> 4;
#pragma unroll
        for (int ks = 0; ks < 4; ks++) {
            uint32_t aph[4];
            ldsm_x4(aph, smem_u32(&Ps[(m0 + l16) * PS + ks * 16 + lhi * 8]));
#pragma unroll
            for (int np = 0; np < 8; np++) {
                uint32_t bv[4];
                ldsm_x4t(bv, smem_u32(&Vs[(ks * 16 + l16) * TS +
                                          (np * 2 + vpair) * 8]));
                uint32_t b0[2] = { bv[0], bv[1] };
                uint32_t b1[2] = { bv[2], bv[3] };
                mma_fp16(ctx[np * 2],     aph, b0);
                mma_fp16(ctx[np * 2 + 1], aph, b1);
            }
        }
    }

    // ---- epilogue: normalize, split to bf16 hi/lo, write (b*t, d_model) ----
    float ri0 = 1.0f / lI0, ri1 = 1.0f / lI1;
    const int b_ = bh >> 4, h_ = bh & 15;
    const int t0 = q0 + m0 + g, t1 = t0 + 8;
#pragma unroll
    for (int nt = 0; nt < 16; nt++) {
        int col = h_ * D_HEAD + nt * 8 + tq * 2;
        {
            float o0 = ctx[nt][0] * ri0, o1 = ctx[nt][1] * ri0;
            __nv_bfloat162 hh, ll;
            hh.x = __float2bfloat16(o0); ll.x = __float2bfloat16(o0 - __bfloat162float(hh.x));
            hh.y = __float2bfloat16(o1); ll.y = __float2bfloat16(o1 - __bfloat162float(hh.y));
            size_t idx = (size_t)(b_ * SEQ + t0) * D_MODEL + col;
            *(__nv_bfloat162*)&g_ch[idx] = hh;
            *(__nv_bfloat162*)&g_cl[idx] = ll;
        }
        {
            float o0 = ctx[nt][2] * ri1, o1 = ctx[nt][3] * ri1;
            __nv_bfloat162 hh, ll;
            hh.x = __float2bfloat16(o0); ll.x = __float2bfloat16(o0 - __bfloat162float(hh.x));
            hh.y = __float2bfloat16(o1); ll.y = __float2bfloat16(o1 - __bfloat162float(hh.y));
            size_t idx = (size_t)(b_ * SEQ + t1) * D_MODEL + col;
            *(__nv_bfloat162*)&g_ch[idx] = hh;
            *(__nv_bfloat162*)&g_cl[idx] = ll;
        }
    }
}

// ---------------- launcher ----------------
extern "C" void kernel_launch(void* const* d_in, const int* in_sizes, int n_in,
                              void* d_out, int out_size)
{
    const float* x     = (const float*)d_in[0];
    const float* w_qkv = (const float*)d_in[1];
    const float* b_qkv = (const float*)d_in[2];
    const float* w_out = (const float*)d_in[3];
    const float* b_out = (const float*)d_in[4];
    float* out = (float*)d_out;

    (void)in_sizes; (void)n_in; (void)out_size;

    __nv_bfloat16 *xh, *xl, *wqh, *wql, *woh, *wol, *ch, *cl;
    cudaGetSymbolAddress((void**)&xh,  g_xh);
    cudaGetSymbolAddress((void**)&xl,  g_xl);
    cudaGetSymbolAddress((void**)&wqh, g_wqh);
    cudaGetSymbolAddress((void**)&wql, g_wql);
    cudaGetSymbolAddress((void**)&woh, g_woh);
    cudaGetSymbolAddress((void**)&wol, g_wol);
    cudaGetSymbolAddress((void**)&ch,  g_ch);
    cudaGetSymbolAddress((void**)&cl,  g_cl);

    // 0) split fp32 -> (hi, lo) bf16
    {
        int n4 = M_ROWS * D_MODEL / 4;
        split_kernel<<<(n4 + 255) / 256, 256>>>(x, xh, xl, n4);
        n4 = D_MODEL * N_QKV / 4;
        split_kernel<<<(n4 + 255) / 256, 256>>>(w_qkv, wqh, wql, n4);
        n4 = D_MODEL * D_MODEL / 4;
        split_kernel<<<(n4 + 255) / 256, 256>>>(w_out, woh, wol, n4);
    }
    // 1) QKV projection (3-stage pipelined split-bf16 mma; V written fp16)
    {
        cudaFuncSetAttribute(gemm_kernel<N_QKV, true>,
                             cudaFuncAttributeMaxDynamicSharedMemorySize, GEMM_SMEM_BYTES);
        dim3 grid(N_QKV / 128, M_ROWS / 128);
        gemm_kernel<N_QKV, true><<<grid, 256, GEMM_SMEM_BYTES>>>(
            xh, xl, wqh, wql, b_qkv, nullptr);
    }
    // 2) RoPE on Q,K (fp32 -> rotated fp16)
    {
        int total = BH * SEQ * 64;
        rope_kernel<<<(total + 255) / 256, 256>>>();
    }
    // 3) Flash attention (fp16 mma, cp.async staging)
    {
        cudaFuncSetAttribute(attn_mma_kernel,
                             cudaFuncAttributeMaxDynamicSharedMemorySize, ATTN_SMEM_BYTES);
        dim3 grid(SEQ / 128, BH);
        attn_mma_kernel<<<grid, 256, ATTN_SMEM_BYTES>>>();
    }
    // 4) Output projection (3-stage pipelined split-bf16 mma)
    {
        cudaFuncSetAttribute(gemm_kernel<D_MODEL, false>,
                             cudaFuncAttributeMaxDynamicSharedMemorySize, GEMM_SMEM_BYTES);
        dim3 grid(D_MODEL / 128, M_ROWS / 128);
        gemm_kernel<D_MODEL, false><<<grid, 256, GEMM_SMEM_BYTES>>>(
            ch, cl, woh, wol, b_out, out);
    }
}

// round 7
// speedup vs baseline: 5.0923x; 1.2284x over previous
#include <cuda_runtime.h>
#include <cuda_bf16.h>
#include <cuda_fp16.h>
#include <math.h>
#include <stdint.h>

#define D_MODEL 2048
#define N_HEADS 16
#define D_HEAD 128
#define BATCH 4
#define SEQ 2048
#define M_ROWS (BATCH*SEQ)      /* 8192 */
#define N_QKV (3*D_MODEL)       /* 6144 */
#define BH (BATCH*N_HEADS)      /* 64  */

// ---------------- scratch (no allocation allowed) ----------------
__device__ __half g_Qh[(size_t)BH*SEQ*D_HEAD];
__device__ __half g_Kh[(size_t)BH*SEQ*D_HEAD];
__device__ __half g_Vh[(size_t)BH*SEQ*D_HEAD];

__device__ __half g_xh16[(size_t)M_ROWS*D_MODEL];
__device__ __half g_xl16[(size_t)M_ROWS*D_MODEL];
__device__ __half g_wq16[(size_t)D_MODEL*N_QKV];
__device__ __nv_bfloat16 g_woh[(size_t)D_MODEL*D_MODEL];
__device__ __nv_bfloat16 g_wol[(size_t)D_MODEL*D_MODEL];
__device__ __nv_bfloat16 g_ch[(size_t)M_ROWS*D_MODEL];
__device__ __nv_bfloat16 g_cl[(size_t)M_ROWS*D_MODEL];

// ---------------- helpers ----------------
__device__ __forceinline__ uint32_t smem_u32(const void* p) {
    return (uint32_t)__cvta_generic_to_shared(p);
}
#define CP_ASYNC16(dst, src) \
    asm volatile("cp.async.cg.shared.global [%0], [%1], 16;" :: "r"(dst), "l"(src))
#define CP_COMMIT()  asm volatile("cp.async.commit_group;" ::: "memory")
#define CP_WAITG(n)  asm volatile("cp.async.wait_group %0;" :: "n"(n) : "memory")

__device__ __forceinline__ void ldsm_x4(uint32_t (&r)[4], uint32_t addr) {
    asm volatile("ldmatrix.sync.aligned.m8n8.x4.shared.b16 {%0,%1,%2,%3}, [%4];"
                 : "=r"(r[0]), "=r"(r[1]), "=r"(r[2]), "=r"(r[3]) : "r"(addr));
}
__device__ __forceinline__ void ldsm_x4t(uint32_t (&r)[4], uint32_t addr) {
    asm volatile("ldmatrix.sync.aligned.m8n8.x4.trans.shared.b16 {%0,%1,%2,%3}, [%4];"
                 : "=r"(r[0]), "=r"(r[1]), "=r"(r[2]), "=r"(r[3]) : "r"(addr));
}
__device__ __forceinline__ void mma_bf16(float (&d)[4], const uint32_t (&a)[4],
                                         const uint32_t (&b)[2]) {
    asm volatile("mma.sync.aligned.m16n8k16.row.col.f32.bf16.bf16.f32 "
                 "{%0,%1,%2,%3}, {%4,%5,%6,%7}, {%8,%9}, {%0,%1,%2,%3};"
                 : "+f"(d[0]), "+f"(d[1]), "+f"(d[2]), "+f"(d[3])
                 : "r"(a[0]), "r"(a[1]), "r"(a[2]), "r"(a[3]),
                   "r"(b[0]), "r"(b[1]));
}
__device__ __forceinline__ void mma_fp16(float (&d)[4], const uint32_t (&a)[4],
                                         const uint32_t (&b)[2]) {
    asm volatile("mma.sync.aligned.m16n8k16.row.col.f32.f16.f16.f32 "
                 "{%0,%1,%2,%3}, {%4,%5,%6,%7}, {%8,%9}, {%0,%1,%2,%3};"
                 : "+f"(d[0]), "+f"(d[1]), "+f"(d[2]), "+f"(d[3])
                 : "r"(a[0]), "r"(a[1]), "r"(a[2]), "r"(a[3]),
                   "r"(b[0]), "r"(b[1]));
}

// ---------------- conversion kernels ----------------
__global__ __launch_bounds__(256)
void split_fp16_kernel(const float* __restrict__ in,
                       __half* __restrict__ hi,
                       __half* __restrict__ lo, int n4)
{
    int idx = blockIdx.x * blockDim.x + threadIdx.x;
    if (idx >= n4) return;
    float4 v = *(const float4*)&in[idx * 4];
    float vv[4] = { v.x, v.y, v.z, v.w };
#pragma unroll
    for (int i = 0; i < 4; i++) {
        __half h = __float2half(vv[i]);
        hi[idx * 4 + i] = h;
        lo[idx * 4 + i] = __float2half(vv[i] - __half2float(h));
    }
}

__global__ __launch_bounds__(256)
void conv_fp16_kernel(const float* __restrict__ in, __half* __restrict__ o, int n4)
{
    int idx = blockIdx.x * blockDim.x + threadIdx.x;
    if (idx >= n4) return;
    float4 v = *(const float4*)&in[idx * 4];
    __half2 a, b;
    a.x = __float2half(v.x); a.y = __float2half(v.y);
    b.x = __float2half(v.z); b.y = __float2half(v.w);
    *(__half2*)&o[idx * 4]     = a;
    *(__half2*)&o[idx * 4 + 2] = b;
}

__global__ __launch_bounds__(256)
void split_bf16_kernel(const float* __restrict__ in,
                       __nv_bfloat16* __restrict__ hi,
                       __nv_bfloat16* __restrict__ lo, int n4)
{
    int idx = blockIdx.x * blockDim.x + threadIdx.x;
    if (idx >= n4) return;
    float4 v = *(const float4*)&in[idx * 4];
    float vv[4] = { v.x, v.y, v.z, v.w };
#pragma unroll
    for (int i = 0; i < 4; i++) {
        __nv_bfloat16 h = __float2bfloat16(vv[i]);
        hi[idx * 4 + i] = h;
        lo[idx * 4 + i] = __float2bfloat16(vv[i] - __bfloat162float(h));
    }
}

// ---------------- common tile constants ----------------
#define AS_STRIDE 40
#define BS_STRIDE 136
#define GA_TILE (128*AS_STRIDE)   /* 5120 elems */
#define GB_TILE (32*BS_STRIDE)    /* 4352 elems */
#define NCHUNK (D_MODEL/32)

// ================= QKV GEMM: 2-term fp16 (A split, B single) =============
#define QSTAGE (2*GA_TILE + GB_TILE)            /* 14592 elems */
#define QKV_SMEM_BYTES (3*QSTAGE*2)             /* 87552 */

__device__ __forceinline__ void qkv_load_stage(char* dsm, int buf, int k0,
    const __half* Ah, const __half* Al, const __half* Bs,
    int row0, int col0, int tid)
{
    uint32_t base = smem_u32(dsm) + (uint32_t)buf * (QSTAGE*2);
#pragma unroll
    for (int s = 0; s < 2; s++) {
        int id = tid + s * 256;
        int ra = id >> 2, ca = id & 3;
        uint32_t da = base + ra * (AS_STRIDE*2) + ca * 16;
        const size_t aoff = (size_t)(row0 + ra) * D_MODEL + k0 + ca * 8;
        CP_ASYNC16(da, Ah + aoff);
        CP_ASYNC16(da + GA_TILE*2, Al + aoff);
        int rb = id >> 4, cb = id & 15;
        uint32_t db = base + 2*GA_TILE*2 + rb * (BS_STRIDE*2) + cb * 16;
        CP_ASYNC16(db, Bs + (size_t)(k0 + rb) * N_QKV + col0 + cb * 8);
    }
}

__device__ __forceinline__ void store_qkv_h(int grow, int gcol, float val)
{
    int b_ = grow >> 11;
    int t_ = grow & 2047;
    int which = gcol >> 11;     // 0=q 1=k 2=v
    int rem   = gcol & 2047;
    int h     = rem >> 7;
    int dd    = rem & 127;
    size_t idx = (((size_t)b_ * N_HEADS + h) * SEQ + t_) * D_HEAD + dd;
    __half hv = __float2half(val);
    if (which == 0)      g_Qh[idx] = hv;
    else if (which == 1) g_Kh[idx] = hv;
    else                 g_Vh[idx] = hv;
}

__global__ __launch_bounds__(256)
void gemm_qkv_kernel(const __half* __restrict__ Ah,
                     const __half* __restrict__ Al,
                     const __half* __restrict__ Bs,
                     const float* __restrict__ bias)
{
    extern __shared__ __align__(16) char dsm[];
    const int tid  = threadIdx.x;
    const int lane = tid & 31;
    const int warp = tid >> 5;
    const int wm = warp & 1;
    const int wn = warp >> 1;
    const int row0 = blockIdx.y * 128;
    const int col0 = blockIdx.x * 128;
    const int l16 = lane & 15;
    const int lhi = lane >> 4;

    float acc[4][4][4];
#pragma unroll
    for (int i = 0; i < 4; i++)
#pragma unroll
        for (int j = 0; j < 4; j++)
#pragma unroll
            for (int k = 0; k < 4; k++) acc[i][j][k] = 0.f;

    qkv_load_stage(dsm, 0, 0,  Ah, Al, Bs, row0, col0, tid);
    CP_COMMIT();
    qkv_load_stage(dsm, 1, 32, Ah, Al, Bs, row0, col0, tid);
    CP_COMMIT();

    int bufc = 0;
#pragma unroll 1
    for (int c = 0; c < NCHUNK; c++) {
        CP_WAITG(1);
        __syncthreads();

        int bufl = bufc + 2; if (bufl >= 3) bufl -= 3;
        if (c + 2 < NCHUNK)
            qkv_load_stage(dsm, bufl, (c + 2) * 32, Ah, Al, Bs, row0, col0, tid);
        CP_COMMIT();

        const __half* Ahs = (const __half*)(dsm + (size_t)bufc * QSTAGE * 2);
        const __half* Als = Ahs + GA_TILE;
        const __half* Bss = Als + GA_TILE;

#pragma unroll
        for (int ksub = 0; ksub < 2; ksub++) {
            uint32_t bf[4][2];
#pragma unroll
            for (int np = 0; np < 2; np++) {
                uint32_t bk[4];
                ldsm_x4t(bk, smem_u32(&Bss[(ksub*16 + l16) * BS_STRIDE +
                                           wn*32 + (np*2 + lhi)*8]));
                bf[np*2][0]   = bk[0]; bf[np*2][1]   = bk[1];
                bf[np*2+1][0] = bk[2]; bf[np*2+1][1] = bk[3];
            }
#pragma unroll
            for (int mt = 0; mt < 4; mt++) {
                uint32_t ah[4], al[4];
                ldsm_x4(ah, smem_u32(&Ahs[(wm*64 + mt*16 + l16) * AS_STRIDE + ksub*16 + lhi*8]));
                ldsm_x4(al, smem_u32(&Als[(wm*64 + mt*16 + l16) * AS_STRIDE + ksub*16 + lhi*8]));
#pragma unroll
                for (int nt = 0; nt < 4; nt++) {
                    mma_fp16(acc[mt][nt], ah, bf[nt]);
                    mma_fp16(acc[mt][nt], al, bf[nt]);
                }
            }
        }
        bufc++; if (bufc >= 3) bufc = 0;
    }

    const int g = lane >> 2, tq = lane & 3;
#pragma unroll
    for (int mt = 0; mt < 4; mt++) {
#pragma unroll
        for (int nt = 0; nt < 4; nt++) {
            int r = row0 + wm*64 + mt*16 + g;
            int cc = col0 + wn*32 + nt*8 + tq*2;
            float bias0 = __ldg(&bias[cc]);
            float bias1 = __ldg(&bias[cc + 1]);
            store_qkv_h(r,     cc,     acc[mt][nt][0] + bias0);
            store_qkv_h(r,     cc + 1, acc[mt][nt][1] + bias1);
            store_qkv_h(r + 8, cc,     acc[mt][nt][2] + bias0);
            store_qkv_h(r + 8, cc + 1, acc[mt][nt][3] + bias1);
        }
    }
}

// ================= out-proj GEMM: 3-term bf16 =============
#define GSTAGE (2*GA_TILE + 2*GB_TILE)
#define OUT_SMEM_BYTES (3*GSTAGE*2)             /* 113664 */

__device__ __forceinline__ void out_load_stage(char* dsm, int buf, int k0,
    const __nv_bfloat16* Ah, const __nv_bfloat16* Al,
    const __nv_bfloat16* Bh, const __nv_bfloat16* Bl,
    int row0, int col0, int tid)
{
    uint32_t base = smem_u32(dsm) + (uint32_t)buf * (GSTAGE*2);
#pragma unroll
    for (int s = 0; s < 2; s++) {
        int id = tid + s * 256;
        int ra = id >> 2, ca = id & 3;
        uint32_t da = base + ra * (AS_STRIDE*2) + ca * 16;
        const size_t aoff = (size_t)(row0 + ra) * D_MODEL + k0 + ca * 8;
        CP_ASYNC16(da, Ah + aoff);
        CP_ASYNC16(da + GA_TILE*2, Al + aoff);
        int rb = id >> 4, cb = id & 15;
        uint32_t db = base + 2*GA_TILE*2 + rb * (BS_STRIDE*2) + cb * 16;
        const size_t boff = (size_t)(k0 + rb) * D_MODEL + col0 + cb * 8;
        CP_ASYNC16(db, Bh + boff);
        CP_ASYNC16(db + GB_TILE*2, Bl + boff);
    }
}

__global__ __launch_bounds__(256)
void gemm_out_kernel(const __nv_bfloat16* __restrict__ Ah,
                     const __nv_bfloat16* __restrict__ Al,
                     const __nv_bfloat16* __restrict__ Bh,
                     const __nv_bfloat16* __restrict__ Bl,
                     const float* __restrict__ bias,
                     float* __restrict__ out)
{
    extern __shared__ __align__(16) char dsm[];
    const int tid  = threadIdx.x;
    const int lane = tid & 31;
    const int warp = tid >> 5;
    const int wm = warp & 1;
    const int wn = warp >> 1;
    const int row0 = blockIdx.y * 128;
    const int col0 = blockIdx.x * 128;
    const int l16 = lane & 15;
    const int lhi = lane >> 4;

    float acc[4][4][4];
#pragma unroll
    for (int i = 0; i < 4; i++)
#pragma unroll
        for (int j = 0; j < 4; j++)
#pragma unroll
            for (int k = 0; k < 4; k++) acc[i][j][k] = 0.f;

    out_load_stage(dsm, 0, 0,  Ah, Al, Bh, Bl, row0, col0, tid);
    CP_COMMIT();
    out_load_stage(dsm, 1, 32, Ah, Al, Bh, Bl, row0, col0, tid);
    CP_COMMIT();

    int bufc = 0;
#pragma unroll 1
    for (int c = 0; c < NCHUNK; c++) {
        CP_WAITG(1);
        __syncthreads();

        int bufl = bufc + 2; if (bufl >= 3) bufl -= 3;
        if (c + 2 < NCHUNK)
            out_load_stage(dsm, bufl, (c + 2) * 32, Ah, Al, Bh, Bl, row0, col0, tid);
        CP_COMMIT();

        const __nv_bfloat16* Ahs = (const __nv_bfloat16*)(dsm + (size_t)bufc * GSTAGE * 2);
        const __nv_bfloat16* Als = Ahs + GA_TILE;
        const __nv_bfloat16* Bhs = Als + GA_TILE;
        const __nv_bfloat16* Bls = Bhs + GB_TILE;

#pragma unroll
        for (int ksub = 0; ksub < 2; ksub++) {
            uint32_t bhf[4][2], blf[4][2];
#pragma unroll
            for (int np = 0; np < 2; np++) {
                uint32_t bk[4];
                ldsm_x4t(bk, smem_u32(&Bhs[(ksub*16 + l16) * BS_STRIDE +
                                           wn*32 + (np*2 + lhi)*8]));
                bhf[np*2][0]   = bk[0]; bhf[np*2][1]   = bk[1];
                bhf[np*2+1][0] = bk[2]; bhf[np*2+1][1] = bk[3];
                ldsm_x4t(bk, smem_u32(&Bls[(ksub*16 + l16) * BS_STRIDE +
                                           wn*32 + (np*2 + lhi)*8]));
                blf[np*2][0]   = bk[0]; blf[np*2][1]   = bk[1];
                blf[np*2+1][0] = bk[2]; blf[np*2+1][1] = bk[3];
            }
#pragma unroll
            for (int mt = 0; mt < 4; mt++) {
                uint32_t ah[4], al[4];
                ldsm_x4(ah, smem_u32(&Ahs[(wm*64 + mt*16 + l16) * AS_STRIDE + ksub*16 + lhi*8]));
                ldsm_x4(al, smem_u32(&Als[(wm*64 + mt*16 + l16) * AS_STRIDE + ksub*16 + lhi*8]));
#pragma unroll
                for (int nt = 0; nt < 4; nt++) {
                    mma_bf16(acc[mt][nt], ah, bhf[nt]);
                    mma_bf16(acc[mt][nt], ah, blf[nt]);
                    mma_bf16(acc[mt][nt], al, bhf[nt]);
                }
            }
        }
        bufc++; if (bufc >= 3) bufc = 0;
    }

    const int g = lane >> 2, tq = lane & 3;
#pragma unroll
    for (int mt = 0; mt < 4; mt++) {
#pragma unroll
        for (int nt = 0; nt < 4; nt++) {
            int r = row0 + wm*64 + mt*16 + g;
            int cc = col0 + wn*32 + nt*8 + tq*2;
            float bias0 = __ldg(&bias[cc]);
            float bias1 = __ldg(&bias[cc + 1]);
            out[(size_t)r * D_MODEL + cc]           = acc[mt][nt][0] + bias0;
            out[(size_t)r * D_MODEL + cc + 1]       = acc[mt][nt][1] + bias1;
            out[(size_t)(r + 8) * D_MODEL + cc]     = acc[mt][nt][2] + bias0;
            out[(size_t)(r + 8) * D_MODEL + cc + 1] = acc[mt][nt][3] + bias1;
        }
    }
}

// -------- RoPE: in-place on fp16 Q/K (fp32 internal math) --------
__global__ __launch_bounds__(256)
void rope_kernel()
{
    int idx = blockIdx.x * blockDim.x + threadIdx.x;
    if (idx >= BH * SEQ * 64) return;
    int i  = idx & 63;
    int t  = (idx >> 6) & (SEQ - 1);
    int bh = idx >> 17;

    float inv = __expf(-(float)i * (9.210340371976184f / 64.0f));
    float freq = (float)t * inv;
    float s, c;
    __sincosf(freq, &s, &c);

    size_t base = ((size_t)bh * SEQ + t) * D_HEAD;
    float q1 = __half2float(g_Qh[base + i]);
    float q2 = __half2float(g_Qh[base + i + 64]);
    g_Qh[base + i]      = __float2half(q1 * c - q2 * s);
    g_Qh[base + i + 64] = __float2half(q2 * c + q1 * s);
    float k1 = __half2float(g_Kh[base + i]);
    float k2 = __half2float(g_Kh[base + i + 64]);
    g_Kh[base + i]      = __float2half(k1 * c - k2 * s);
    g_Kh[base + i + 64] = __float2half(k2 * c + k1 * s);
}

// ---------------- Flash attention via mma.sync (fp16) ----------------
#define TS 136
#define PS 72
#define ATTN_Q_ELEMS (128*TS)
#define ATTN_K_ELEMS (64*TS)
#define ATTN_P_ELEMS (128*PS)
#define ATTN_SMEM_BYTES ((ATTN_Q_ELEMS + 2*ATTN_K_ELEMS + ATTN_P_ELEMS)*2)

__global__ __launch_bounds__(256)
void attn_mma_kernel()
{
    extern __shared__ __align__(16) char dsm[];
    __half* Qs = (__half*)dsm;
    __half* Ks = Qs + ATTN_Q_ELEMS;
    __half* Vs = Ks + ATTN_K_ELEMS;
    __half* Ps = Vs + ATTN_K_ELEMS;

    const int bh = blockIdx.y;
    const int qt = blockIdx.x;
    const int q0 = qt * 128;
    const float SC2 = 0.08838834764831845f * 1.4426950408889634f;

    const __half* Qg = g_Qh + (size_t)bh * SEQ * D_HEAD;
    const __half* Kg = g_Kh + (size_t)bh * SEQ * D_HEAD;
    const __half* Vg = g_Vh + (size_t)bh * SEQ * D_HEAD;

    const int tid = threadIdx.x;
    const int warp = tid >> 5, lane = tid & 31;
    const int m0 = warp * 16;
    const int l16 = lane & 15, lhi = lane >> 4;
    const int g = lane >> 2, tq = lane & 3;

    for (int i = tid; i < 128 * 16; i += 256) {
        int r = i >> 4, c16 = i & 15;
        CP_ASYNC16(smem_u32(&Qs[r * TS + c16 * 8]),
                   &Qg[(size_t)(q0 + r) * D_HEAD + c16 * 8]);
    }
    CP_COMMIT();

    float mI0 = -INFINITY, mI1 = -INFINITY, lI0 = 0.f, lI1 = 0.f;
    float ctx[16][4];
#pragma unroll
    for (int i = 0; i < 16; i++)
#pragma unroll
        for (int j = 0; j < 4; j++) ctx[i][j] = 0.f;

    const int ktiles = 2 * qt + 2;
#pragma unroll 1
    for (int kt = 0; kt < ktiles; kt++) {
        const int kb = kt * 64;
        __syncthreads();
        for (int i = tid; i < 64 * 16; i += 256) {
            int r = i >> 4, c16 = i & 15;
            size_t goff = (size_t)(kb + r) * D_HEAD + c16 * 8;
            CP_ASYNC16(smem_u32(&Ks[r * TS + c16 * 8]), &Kg[goff]);
            CP_ASYNC16(smem_u32(&Vs[r * TS + c16 * 8]), &Vg[goff]);
        }
        CP_COMMIT();
        CP_WAITG(0);
        __syncthreads();

        float sacc[8][4];
#pragma unroll
        for (int nt = 0; nt < 8; nt++)
#pragma unroll
            for (int e = 0; e < 4; e++) sacc[nt][e] = 0.f;

        const int krow = lane & 7;
        const int kpair = (lane >> 4) & 1;
        const int kcolsel = ((lane >> 3) & 1) * 8;
#pragma unroll
        for (int ks = 0; ks < 8; ks++) {
            uint32_t ah[4];
            ldsm_x4(ah, smem_u32(&Qs[(m0 + l16) * TS + ks * 16 + lhi * 8]));
#pragma unroll
            for (int np = 0; np < 4; np++) {
                uint32_t bk[4];
                ldsm_x4(bk, smem_u32(&Ks[((np * 2 + kpair) * 8 + krow) * TS +
                                         ks * 16 + kcolsel]));
                uint32_t b0[2] = { bk[0], bk[1] };
                uint32_t b1[2] = { bk[2], bk[3] };
                mma_fp16(sacc[np * 2],     ah, b0);
                mma_fp16(sacc[np * 2 + 1], ah, b1);
            }
        }

        const bool diag = (kt >= ktiles - 2);
        const int r0 = q0 + m0 + g, r1 = r0 + 8;
        float rm0 = -INFINITY, rm1 = -INFINITY;
#pragma unroll
        for (int nt = 0; nt < 8; nt++) {
            int cb0 = kb + nt * 8 + tq * 2;
            float s0 = sacc[nt][0] * SC2, s1 = sacc[nt][1] * SC2;
            float s2 = sacc[nt][2] * SC2, s3 = sacc[nt][3] * SC2;
            if (diag) {
                if (cb0     > r0) s0 = -INFINITY;
                if (cb0 + 1 > r0) s1 = -INFINITY;
                if (cb0     > r1) s2 = -INFINITY;
                if (cb0 + 1 > r1) s3 = -INFINITY;
            }
            sacc[nt][0] = s0; sacc[nt][1] = s1; sacc[nt][2] = s2; sacc[nt][3] = s3;
            rm0 = fmaxf(rm0, fmaxf(s0, s1));
            rm1 = fmaxf(rm1, fmaxf(s2, s3));
        }
        rm0 = fmaxf(rm0, __shfl_xor_sync(0xffffffffu, rm0, 1));
        rm0 = fmaxf(rm0, __shfl_xor_sync(0xffffffffu, rm0, 2));
        rm1 = fmaxf(rm1, __shfl_xor_sync(0xffffffffu, rm1, 1));
        rm1 = fmaxf(rm1, __shfl_xor_sync(0xffffffffu, rm1, 2));
        float mn0 = fmaxf(mI0, rm0), mn1 = fmaxf(mI1, rm1);
        float c0 = exp2f(mI0 - mn0), c1 = exp2f(mI1 - mn1);
        float ps0 = 0.f, ps1 = 0.f;
#pragma unroll
        for (int nt = 0; nt < 8; nt++) {
            float p0 = exp2f(sacc[nt][0] - mn0);
            float p1 = exp2f(sacc[nt][1] - mn0);
            float p2 = exp2f(sacc[nt][2] - mn1);
            float p3 = exp2f(sacc[nt][3] - mn1);
            ps0 += p0 + p1; ps1 += p2 + p3;
            __half2 ph;
            ph.x = __float2half(p0); ph.y = __float2half(p1);
            *(__half2*)&Ps[(m0 + g) * PS + nt * 8 + tq * 2] = ph;
            ph.x = __float2half(p2); ph.y = __float2half(p3);
            *(__half2*)&Ps[(m0 + g + 8) * PS + nt * 8 + tq * 2] = ph;
        }
        ps0 += __shfl_xor_sync(0xffffffffu, ps0, 1);
        ps0 += __shfl_xor_sync(0xffffffffu, ps0, 2);
        ps1 += __shfl_xor_sync(0xffffffffu, ps1, 1);
        ps1 += __shfl_xor_sync(0xffffffffu, ps1, 2);
        lI0 = lI0 * c0 + ps0; lI1 = lI1 * c1 + ps1;
        mI0 = mn0; mI1 = mn1;
#pragma unroll
        for (int n2 = 0; n2 < 16; n2++) {
            ctx[n2][0] *= c0; ctx[n2][1] *= c0;
            ctx[n2][2] *= c1; ctx[n2][3] *= c1;
        }
        __syncwarp();

        const int vpair = lane >> 4;
#pragma unroll
        for (int ks = 0; ks < 4; ks++) {
            uint32_t aph[4];
            ldsm_x4(aph, smem_u32(&Ps[(m0 + l16) * PS + ks * 16 + lhi * 8]));
#pragma unroll
            for (int np = 0; np < 8; np++) {
                uint32_t bv[4];
                ldsm_x4t(bv, smem_u32(&Vs[(ks * 16 + l16) * TS +
                                          (np * 2 + vpair) * 8]));
                uint32_t b0[2] = { bv[0], bv[1] };
                uint32_t b1[2] = { bv[2], bv[3] };
                mma_fp16(ctx[np * 2],     aph, b0);
                mma_fp16(ctx[np * 2 + 1], aph, b1);
            }
        }
    }

    float ri0 = 1.0f / lI0, ri1 = 1.0f / lI1;
    const int b_ = bh >> 4, h_ = bh & 15;
    const int t0 = q0 + m0 + g, t1 = t0 + 8;
#pragma unroll
    for (int nt = 0; nt < 16; nt++) {
        int col = h_ * D_HEAD + nt * 8 + tq * 2;
        {
            float o0 = ctx[nt][0] * ri0, o1 = ctx[nt][1] * ri0;
            __nv_bfloat162 hh, ll;
            hh.x = __float2bfloat16(o0); ll.x = __float2bfloat16(o0 - __bfloat162float(hh.x));
            hh.y = __float2bfloat16(o1); ll.y = __float2bfloat16(o1 - __bfloat162float(hh.y));
            size_t idx = (size_t)(b_ * SEQ + t0) * D_MODEL + col;
            *(__nv_bfloat162*)&g_ch[idx] = hh;
            *(__nv_bfloat162*)&g_cl[idx] = ll;
        }
        {
            float o0 = ctx[nt][2] * ri1, o1 = ctx[nt][3] * ri1;
            __nv_bfloat162 hh, ll;
            hh.x = __float2bfloat16(o0); ll.x = __float2bfloat16(o0 - __bfloat162float(hh.x));
            hh.y = __float2bfloat16(o1); ll.y = __float2bfloat16(o1 - __bfloat162float(hh.y));
            size_t idx = (size_t)(b_ * SEQ + t1) * D_MODEL + col;
            *(__nv_bfloat162*)&g_ch[idx] = hh;
            *(__nv_bfloat162*)&g_cl[idx] = ll;
        }
    }
}

// ---------------- launcher ----------------
extern "C" void kernel_launch(void* const* d_in, const int* in_sizes, int n_in,
                              void* d_out, int out_size)
{
    const float* x     = (const float*)d_in[0];
    const float* w_qkv = (const float*)d_in[1];
    const float* b_qkv = (const float*)d_in[2];
    const float* w_out = (const float*)d_in[3];
    const float* b_out = (const float*)d_in[4];
    float* out = (float*)d_out;

    (void)in_sizes; (void)n_in; (void)out_size;

    __half *xh, *xl, *wq;
    __nv_bfloat16 *woh, *wol, *ch, *cl;
    cudaGetSymbolAddress((void**)&xh,  g_xh16);
    cudaGetSymbolAddress((void**)&xl,  g_xl16);
    cudaGetSymbolAddress((void**)&wq,  g_wq16);
    cudaGetSymbolAddress((void**)&woh, g_woh);
    cudaGetSymbolAddress((void**)&wol, g_wol);
    cudaGetSymbolAddress((void**)&ch,  g_ch);
    cudaGetSymbolAddress((void**)&cl,  g_cl);

    // 0) conversions
    {
        int n4 = M_ROWS * D_MODEL / 4;
        split_fp16_kernel<<<(n4 + 255) / 256, 256>>>(x, xh, xl, n4);
        n4 = D_MODEL * N_QKV / 4;
        conv_fp16_kernel<<<(n4 + 255) / 256, 256>>>(w_qkv, wq, n4);
        n4 = D_MODEL * D_MODEL / 4;
        split_bf16_kernel<<<(n4 + 255) / 256, 256>>>(w_out, woh, wol, n4);
    }
    // 1) QKV projection (2-term fp16 mma; writes fp16 Q/K/V)
    {
        cudaFuncSetAttribute(gemm_qkv_kernel,
                             cudaFuncAttributeMaxDynamicSharedMemorySize, QKV_SMEM_BYTES);
        dim3 grid(N_QKV / 128, M_ROWS / 128);
        gemm_qkv_kernel<<<grid, 256, QKV_SMEM_BYTES>>>(xh, xl, wq, b_qkv);
    }
    // 2) RoPE (fp16 in-place)
    {
        int total = BH * SEQ * 64;
        rope_kernel<<<(total + 255) / 256, 256>>>();
    }
    // 3) Flash attention (fp16 mma)
    {
        cudaFuncSetAttribute(attn_mma_kernel,
                             cudaFuncAttributeMaxDynamicSharedMemorySize, ATTN_SMEM_BYTES);
        dim3 grid(SEQ / 128, BH);
        attn_mma_kernel<<<grid, 256, ATTN_SMEM_BYTES>>>();
    }
    // 4) Output projection (3-term bf16 mma)
    {
        cudaFuncSetAttribute(gemm_out_kernel,
                             cudaFuncAttributeMaxDynamicSharedMemorySize, OUT_SMEM_BYTES);
        dim3 grid(D_MODEL / 128, M_ROWS / 128);
        gemm_out_kernel<<<grid, 256, OUT_SMEM_BYTES>>>(ch, cl, woh, wol, b_out, out);
    }
}

// round 8
// speedup vs baseline: 7.2699x; 1.4276x over previous
#include <cuda_runtime.h>
#include <cuda_fp16.h>
#include <math.h>
#include <stdint.h>

#define D_MODEL 2048
#define N_HEADS 16
#define D_HEAD 128
#define BATCH 4
#define SEQ 2048
#define M_ROWS (BATCH*SEQ)      /* 8192 */
#define N_QKV (3*D_MODEL)       /* 6144 */
#define BH (BATCH*N_HEADS)      /* 64  */

// ---------------- scratch (no allocation allowed) ----------------
__device__ __half g_Qh[(size_t)BH*SEQ*D_HEAD];
__device__ __half g_Kh[(size_t)BH*SEQ*D_HEAD];
__device__ __half g_Vh[(size_t)BH*SEQ*D_HEAD];

__device__ __half g_x16[(size_t)M_ROWS*D_MODEL];
__device__ __half g_wq16[(size_t)D_MODEL*N_QKV];
__device__ __half g_wo16[(size_t)D_MODEL*D_MODEL];
__device__ __half g_ch16[(size_t)M_ROWS*D_MODEL];
__device__ __half g_cl16[(size_t)M_ROWS*D_MODEL];

// ---------------- helpers ----------------
__device__ __forceinline__ uint32_t smem_u32(const void* p) {
    return (uint32_t)__cvta_generic_to_shared(p);
}
#define CP_ASYNC16(dst, src) \
    asm volatile("cp.async.cg.shared.global [%0], [%1], 16;" :: "r"(dst), "l"(src))
#define CP_COMMIT()  asm volatile("cp.async.commit_group;" ::: "memory")
#define CP_WAITG(n)  asm volatile("cp.async.wait_group %0;" :: "n"(n) : "memory")

__device__ __forceinline__ void ldsm_x4(uint32_t (&r)[4], uint32_t addr) {
    asm volatile("ldmatrix.sync.aligned.m8n8.x4.shared.b16 {%0,%1,%2,%3}, [%4];"
                 : "=r"(r[0]), "=r"(r[1]), "=r"(r[2]), "=r"(r[3]) : "r"(addr));
}
__device__ __forceinline__ void ldsm_x4t(uint32_t (&r)[4], uint32_t addr) {
    asm volatile("ldmatrix.sync.aligned.m8n8.x4.trans.shared.b16 {%0,%1,%2,%3}, [%4];"
                 : "=r"(r[0]), "=r"(r[1]), "=r"(r[2]), "=r"(r[3]) : "r"(addr));
}
__device__ __forceinline__ void mma_fp16(float (&d)[4], const uint32_t (&a)[4],
                                         const uint32_t (&b)[2]) {
    asm volatile("mma.sync.aligned.m16n8k16.row.col.f32.f16.f16.f32 "
                 "{%0,%1,%2,%3}, {%4,%5,%6,%7}, {%8,%9}, {%0,%1,%2,%3};"
                 : "+f"(d[0]), "+f"(d[1]), "+f"(d[2]), "+f"(d[3])
                 : "r"(a[0]), "r"(a[1]), "r"(a[2]), "r"(a[3]),
                   "r"(b[0]), "r"(b[1]));
}

// ---------------- conversion kernel ----------------
__global__ __launch_bounds__(256)
void conv_fp16_kernel(const float* __restrict__ in, __half* __restrict__ o, int n4)
{
    int idx = blockIdx.x * blockDim.x + threadIdx.x;
    if (idx >= n4) return;
    float4 v = *(const float4*)&in[idx * 4];
    __half2 a, b;
    a.x = __float2half(v.x); a.y = __float2half(v.y);
    b.x = __float2half(v.z); b.y = __float2half(v.w);
    *(__half2*)&o[idx * 4]     = a;
    *(__half2*)&o[idx * 4 + 2] = b;
}

// ---------------- common tile constants ----------------
#define AS_STRIDE 40
#define BS_STRIDE 136
#define GA_TILE (128*AS_STRIDE)   /* 5120 elems */
#define GB_TILE (32*BS_STRIDE)    /* 4352 elems */
#define NCHUNK (D_MODEL/32)

// ================= QKV GEMM: 1-term fp16 =============
#define Q1STAGE (GA_TILE + GB_TILE)             /* 9472 elems */
#define QKV_SMEM_BYTES (3*Q1STAGE*2)            /* 56832 */

__device__ __forceinline__ void qkv_load_stage(char* dsm, int buf, int k0,
    const __half* A, const __half* Bs, int row0, int col0, int tid)
{
    uint32_t base = smem_u32(dsm) + (uint32_t)buf * (Q1STAGE*2);
#pragma unroll
    for (int s = 0; s < 2; s++) {
        int id = tid + s * 256;
        int ra = id >> 2, ca = id & 3;
        CP_ASYNC16(base + ra * (AS_STRIDE*2) + ca * 16,
                   A + (size_t)(row0 + ra) * D_MODEL + k0 + ca * 8);
        int rb = id >> 4, cb = id & 15;
        CP_ASYNC16(base + GA_TILE*2 + rb * (BS_STRIDE*2) + cb * 16,
                   Bs + (size_t)(k0 + rb) * N_QKV + col0 + cb * 8);
    }
}

__device__ __forceinline__ void store_qkv_h(int grow, int gcol, float val)
{
    int b_ = grow >> 11;
    int t_ = grow & 2047;
    int which = gcol >> 11;     // 0=q 1=k 2=v
    int rem   = gcol & 2047;
    int h     = rem >> 7;
    int dd    = rem & 127;
    size_t idx = (((size_t)b_ * N_HEADS + h) * SEQ + t_) * D_HEAD + dd;
    __half hv = __float2half(val);
    if (which == 0)      g_Qh[idx] = hv;
    else if (which == 1) g_Kh[idx] = hv;
    else                 g_Vh[idx] = hv;
}

__global__ __launch_bounds__(256)
void gemm_qkv_kernel(const __half* __restrict__ A,
                     const __half* __restrict__ Bs,
                     const float* __restrict__ bias)
{
    extern __shared__ __align__(16) char dsm[];
    const int tid  = threadIdx.x;
    const int lane = tid & 31;
    const int warp = tid >> 5;
    const int wm = warp & 1;
    const int wn = warp >> 1;
    const int row0 = blockIdx.y * 128;
    const int col0 = blockIdx.x * 128;
    const int l16 = lane & 15;
    const int lhi = lane >> 4;

    float acc[4][4][4];
#pragma unroll
    for (int i = 0; i < 4; i++)
#pragma unroll
        for (int j = 0; j < 4; j++)
#pragma unroll
            for (int k = 0; k < 4; k++) acc[i][j][k] = 0.f;

    qkv_load_stage(dsm, 0, 0,  A, Bs, row0, col0, tid);
    CP_COMMIT();
    qkv_load_stage(dsm, 1, 32, A, Bs, row0, col0, tid);
    CP_COMMIT();

    int bufc = 0;
#pragma unroll 1
    for (int c = 0; c < NCHUNK; c++) {
        CP_WAITG(1);
        __syncthreads();

        int bufl = bufc + 2; if (bufl >= 3) bufl -= 3;
        if (c + 2 < NCHUNK)
            qkv_load_stage(dsm, bufl, (c + 2) * 32, A, Bs, row0, col0, tid);
        CP_COMMIT();

        const __half* As  = (const __half*)(dsm + (size_t)bufc * Q1STAGE * 2);
        const __half* Bss = As + GA_TILE;

#pragma unroll
        for (int ksub = 0; ksub < 2; ksub++) {
            uint32_t bf[4][2];
#pragma unroll
            for (int np = 0; np < 2; np++) {
                uint32_t bk[4];
                ldsm_x4t(bk, smem_u32(&Bss[(ksub*16 + l16) * BS_STRIDE +
                                           wn*32 + (np*2 + lhi)*8]));
                bf[np*2][0]   = bk[0]; bf[np*2][1]   = bk[1];
                bf[np*2+1][0] = bk[2]; bf[np*2+1][1] = bk[3];
            }
#pragma unroll
            for (int mt = 0; mt < 4; mt++) {
                uint32_t ah[4];
                ldsm_x4(ah, smem_u32(&As[(wm*64 + mt*16 + l16) * AS_STRIDE + ksub*16 + lhi*8]));
#pragma unroll
                for (int nt = 0; nt < 4; nt++)
                    mma_fp16(acc[mt][nt], ah, bf[nt]);
            }
        }
        bufc++; if (bufc >= 3) bufc = 0;
    }

    const int g = lane >> 2, tq = lane & 3;
#pragma unroll
    for (int mt = 0; mt < 4; mt++) {
#pragma unroll
        for (int nt = 0; nt < 4; nt++) {
            int r = row0 + wm*64 + mt*16 + g;
            int cc = col0 + wn*32 + nt*8 + tq*2;
            float bias0 = __ldg(&bias[cc]);
            float bias1 = __ldg(&bias[cc + 1]);
            store_qkv_h(r,     cc,     acc[mt][nt][0] + bias0);
            store_qkv_h(r,     cc + 1, acc[mt][nt][1] + bias1);
            store_qkv_h(r + 8, cc,     acc[mt][nt][2] + bias0);
            store_qkv_h(r + 8, cc + 1, acc[mt][nt][3] + bias1);
        }
    }
}

// ================= out-proj GEMM: 2-term fp16 (A split, B single) =============
#define OSTAGE (2*GA_TILE + GB_TILE)            /* 14592 elems */
#define OUT_SMEM_BYTES (3*OSTAGE*2)             /* 87552 */

__device__ __forceinline__ void out_load_stage(char* dsm, int buf, int k0,
    const __half* Ah, const __half* Al, const __half* Bs,
    int row0, int col0, int tid)
{
    uint32_t base = smem_u32(dsm) + (uint32_t)buf * (OSTAGE*2);
#pragma unroll
    for (int s = 0; s < 2; s++) {
        int id = tid + s * 256;
        int ra = id >> 2, ca = id & 3;
        uint32_t da = base + ra * (AS_STRIDE*2) + ca * 16;
        const size_t aoff = (size_t)(row0 + ra) * D_MODEL + k0 + ca * 8;
        CP_ASYNC16(da, Ah + aoff);
        CP_ASYNC16(da + GA_TILE*2, Al + aoff);
        int rb = id >> 4, cb = id & 15;
        CP_ASYNC16(base + 2*GA_TILE*2 + rb * (BS_STRIDE*2) + cb * 16,
                   Bs + (size_t)(k0 + rb) * D_MODEL + col0 + cb * 8);
    }
}

__global__ __launch_bounds__(256)
void gemm_out_kernel(const __half* __restrict__ Ah,
                     const __half* __restrict__ Al,
                     const __half* __restrict__ Bs,
                     const float* __restrict__ bias,
                     float* __restrict__ out)
{
    extern __shared__ __align__(16) char dsm[];
    const int tid  = threadIdx.x;
    const int lane = tid & 31;
    const int warp = tid >> 5;
    const int wm = warp & 1;
    const int wn = warp >> 1;
    const int row0 = blockIdx.y * 128;
    const int col0 = blockIdx.x * 128;
    const int l16 = lane & 15;
    const int lhi = lane >> 4;

    float acc[4][4][4];
#pragma unroll
    for (int i = 0; i < 4; i++)
#pragma unroll
        for (int j = 0; j < 4; j++)
#pragma unroll
            for (int k = 0; k < 4; k++) acc[i][j][k] = 0.f;

    out_load_stage(dsm, 0, 0,  Ah, Al, Bs, row0, col0, tid);
    CP_COMMIT();
    out_load_stage(dsm, 1, 32, Ah, Al, Bs, row0, col0, tid);
    CP_COMMIT();

    int bufc = 0;
#pragma unroll 1
    for (int c = 0; c < NCHUNK; c++) {
        CP_WAITG(1);
        __syncthreads();

        int bufl = bufc + 2; if (bufl >= 3) bufl -= 3;
        if (c + 2 < NCHUNK)
            out_load_stage(dsm, bufl, (c + 2) * 32, Ah, Al, Bs, row0, col0, tid);
        CP_COMMIT();

        const __half* Ahs = (const __half*)(dsm + (size_t)bufc * OSTAGE * 2);
        const __half* Als = Ahs + GA_TILE;
        const __half* Bss = Als + GA_TILE;

#pragma unroll
        for (int ksub = 0; ksub < 2; ksub++) {
            uint32_t bf[4][2];
#pragma unroll
            for (int np = 0; np < 2; np++) {
                uint32_t bk[4];
                ldsm_x4t(bk, smem_u32(&Bss[(ksub*16 + l16) * BS_STRIDE +
                                           wn*32 + (np*2 + lhi)*8]));
                bf[np*2][0]   = bk[0]; bf[np*2][1]   = bk[1];
                bf[np*2+1][0] = bk[2]; bf[np*2+1][1] = bk[3];
            }
#pragma unroll
            for (int mt = 0; mt < 4; mt++) {
                uint32_t ah[4], al[4];
                ldsm_x4(ah, smem_u32(&Ahs[(wm*64 + mt*16 + l16) * AS_STRIDE + ksub*16 + lhi*8]));
                ldsm_x4(al, smem_u32(&Als[(wm*64 + mt*16 + l16) * AS_STRIDE + ksub*16 + lhi*8]));
#pragma unroll
                for (int nt = 0; nt < 4; nt++) {
                    mma_fp16(acc[mt][nt], ah, bf[nt]);
                    mma_fp16(acc[mt][nt], al, bf[nt]);
                }
            }
        }
        bufc++; if (bufc >= 3) bufc = 0;
    }

    const int g = lane >> 2, tq = lane & 3;
#pragma unroll
    for (int mt = 0; mt < 4; mt++) {
#pragma unroll
        for (int nt = 0; nt < 4; nt++) {
            int r = row0 + wm*64 + mt*16 + g;
            int cc = col0 + wn*32 + nt*8 + tq*2;
            float bias0 = __ldg(&bias[cc]);
            float bias1 = __ldg(&bias[cc + 1]);
            out[(size_t)r * D_MODEL + cc]           = acc[mt][nt][0] + bias0;
            out[(size_t)r * D_MODEL + cc + 1]       = acc[mt][nt][1] + bias1;
            out[(size_t)(r + 8) * D_MODEL + cc]     = acc[mt][nt][2] + bias0;
            out[(size_t)(r + 8) * D_MODEL + cc + 1] = acc[mt][nt][3] + bias1;
        }
    }
}

// -------- RoPE: in-place on fp16 Q/K (fp32 internal math) --------
__global__ __launch_bounds__(256)
void rope_kernel()
{
    int idx = blockIdx.x * blockDim.x + threadIdx.x;
    if (idx >= BH * SEQ * 64) return;
    int i  = idx & 63;
    int t  = (idx >> 6) & (SEQ - 1);
    int bh = idx >> 17;

    float inv = __expf(-(float)i * (9.210340371976184f / 64.0f));
    float freq = (float)t * inv;
    float s, c;
    __sincosf(freq, &s, &c);

    size_t base = ((size_t)bh * SEQ + t) * D_HEAD;
    float q1 = __half2float(g_Qh[base + i]);
    float q2 = __half2float(g_Qh[base + i + 64]);
    g_Qh[base + i]      = __float2half(q1 * c - q2 * s);
    g_Qh[base + i + 64] = __float2half(q2 * c + q1 * s);
    float k1 = __half2float(g_Kh[base + i]);
    float k2 = __half2float(g_Kh[base + i + 64]);
    g_Kh[base + i]      = __float2half(k1 * c - k2 * s);
    g_Kh[base + i + 64] = __float2half(k2 * c + k1 * s);
}

// ---------------- Flash attention via mma.sync (fp16) ----------------
#define TS 136
#define PS 72
#define ATTN_Q_ELEMS (128*TS)
#define ATTN_K_ELEMS (64*TS)
#define ATTN_P_ELEMS (128*PS)
#define ATTN_SMEM_BYTES ((ATTN_Q_ELEMS + 2*ATTN_K_ELEMS + ATTN_P_ELEMS)*2)

__global__ __launch_bounds__(256)
void attn_mma_kernel()
{
    extern __shared__ __align__(16) char dsm[];
    __half* Qs = (__half*)dsm;
    __half* Ks = Qs + ATTN_Q_ELEMS;
    __half* Vs = Ks + ATTN_K_ELEMS;
    __half* Ps = Vs + ATTN_K_ELEMS;

    const int bh = blockIdx.y;
    const int qt = blockIdx.x;
    const int q0 = qt * 128;
    const float SC2 = 0.08838834764831845f * 1.4426950408889634f;

    const __half* Qg = g_Qh + (size_t)bh * SEQ * D_HEAD;
    const __half* Kg = g_Kh + (size_t)bh * SEQ * D_HEAD;
    const __half* Vg = g_Vh + (size_t)bh * SEQ * D_HEAD;

    const int tid = threadIdx.x;
    const int warp = tid >> 5, lane = tid & 31;
    const int m0 = warp * 16;
    const int l16 = lane & 15, lhi = lane >> 4;
    const int g = lane >> 2, tq = lane & 3;

    for (int i = tid; i < 128 * 16; i += 256) {
        int r = i >> 4, c16 = i & 15;
        CP_ASYNC16(smem_u32(&Qs[r * TS + c16 * 8]),
                   &Qg[(size_t)(q0 + r) * D_HEAD + c16 * 8]);
    }
    CP_COMMIT();

    float mI0 = -INFINITY, mI1 = -INFINITY, lI0 = 0.f, lI1 = 0.f;
    float ctx[16][4];
#pragma unroll
    for (int i = 0; i < 16; i++)
#pragma unroll
        for (int j = 0; j < 4; j++) ctx[i][j] = 0.f;

    const int ktiles = 2 * qt + 2;
#pragma unroll 1
    for (int kt = 0; kt < ktiles; kt++) {
        const int kb = kt * 64;
        __syncthreads();
        for (int i = tid; i < 64 * 16; i += 256) {
            int r = i >> 4, c16 = i & 15;
            size_t goff = (size_t)(kb + r) * D_HEAD + c16 * 8;
            CP_ASYNC16(smem_u32(&Ks[r * TS + c16 * 8]), &Kg[goff]);
            CP_ASYNC16(smem_u32(&Vs[r * TS + c16 * 8]), &Vg[goff]);
        }
        CP_COMMIT();
        CP_WAITG(0);
        __syncthreads();

        float sacc[8][4];
#pragma unroll
        for (int nt = 0; nt < 8; nt++)
#pragma unroll
            for (int e = 0; e < 4; e++) sacc[nt][e] = 0.f;

        const int krow = lane & 7;
        const int kpair = (lane >> 4) & 1;
        const int kcolsel = ((lane >> 3) & 1) * 8;
#pragma unroll
        for (int ks = 0; ks < 8; ks++) {
            uint32_t ah[4];
            ldsm_x4(ah, smem_u32(&Qs[(m0 + l16) * TS + ks * 16 + lhi * 8]));
#pragma unroll
            for (int np = 0; np < 4; np++) {
                uint32_t bk[4];
                ldsm_x4(bk, smem_u32(&Ks[((np * 2 + kpair) * 8 + krow) * TS +
                                         ks * 16 + kcolsel]));
                uint32_t b0[2] = { bk[0], bk[1] };
                uint32_t b1[2] = { bk[2], bk[3] };
                mma_fp16(sacc[np * 2],     ah, b0);
                mma_fp16(sacc[np * 2 + 1], ah, b1);
            }
        }

        const bool diag = (kt >= ktiles - 2);
        const int r0 = q0 + m0 + g, r1 = r0 + 8;
        float rm0 = -INFINITY, rm1 = -INFINITY;
#pragma unroll
        for (int nt = 0; nt < 8; nt++) {
            int cb0 = kb + nt * 8 + tq * 2;
            float s0 = sacc[nt][0] * SC2, s1 = sacc[nt][1] * SC2;
            float s2 = sacc[nt][2] * SC2, s3 = sacc[nt][3] * SC2;
            if (diag) {
                if (cb0     > r0) s0 = -INFINITY;
                if (cb0 + 1 > r0) s1 = -INFINITY;
                if (cb0     > r1) s2 = -INFINITY;
                if (cb0 + 1 > r1) s3 = -INFINITY;
            }
            sacc[nt][0] = s0; sacc[nt][1] = s1; sacc[nt][2] = s2; sacc[nt][3] = s3;
            rm0 = fmaxf(rm0, fmaxf(s0, s1));
            rm1 = fmaxf(rm1, fmaxf(s2, s3));
        }
        rm0 = fmaxf(rm0, __shfl_xor_sync(0xffffffffu, rm0, 1));
        rm0 = fmaxf(rm0, __shfl_xor_sync(0xffffffffu, rm0, 2));
        rm1 = fmaxf(rm1, __shfl_xor_sync(0xffffffffu, rm1, 1));
        rm1 = fmaxf(rm1, __shfl_xor_sync(0xffffffffu, rm1, 2));
        float mn0 = fmaxf(mI0, rm0), mn1 = fmaxf(mI1, rm1);
        float c0 = exp2f(mI0 - mn0), c1 = exp2f(mI1 - mn1);
        float ps0 = 0.f, ps1 = 0.f;
#pragma unroll
        for (int nt = 0; nt < 8; nt++) {
            float p0 = exp2f(sacc[nt][0] - mn0);
            float p1 = exp2f(sacc[nt][1] - mn0);
            float p2 = exp2f(sacc[nt][2] - mn1);
            float p3 = exp2f(sacc[nt][3] - mn1);
            ps0 += p0 + p1; ps1 += p2 + p3;
            __half2 ph;
            ph.x = __float2half(p0); ph.y = __float2half(p1);
            *(__half2*)&Ps[(m0 + g) * PS + nt * 8 + tq * 2] = ph;
            ph.x = __float2half(p2); ph.y = __float2half(p3);
            *(__half2*)&Ps[(m0 + g + 8) * PS + nt * 8 + tq * 2] = ph;
        }
        ps0 += __shfl_xor_sync(0xffffffffu, ps0, 1);
        ps0 += __shfl_xor_sync(0xffffffffu, ps0, 2);
        ps1 += __shfl_xor_sync(0xffffffffu, ps1, 1);
        ps1 += __shfl_xor_sync(0xffffffffu, ps1, 2);
        lI0 = lI0 * c0 + ps0; lI1 = lI1 * c1 + ps1;
        mI0 = mn0; mI1 = mn1;
#pragma unroll
        for (int n2 = 0; n2 < 16; n2++) {
            ctx[n2][0] *= c0; ctx[n2][1] *= c0;
            ctx[n2][2] *= c1; ctx[n2][3] *= c1;
        }
        __syncwarp();

        const int vpair = lane >> 4;
#pragma unroll
        for (int ks = 0; ks < 4; ks++) {
            uint32_t aph[4];
            ldsm_x4(aph, smem_u32(&Ps[(m0 + l16) * PS + ks * 16 + lhi * 8]));
#pragma unroll
            for (int np = 0; np < 8; np++) {
                uint32_t bv[4];
                ldsm_x4t(bv, smem_u32(&Vs[(ks * 16 + l16) * TS +
                                          (np * 2 + vpair) * 8]));
                uint32_t b0[2] = { bv[0], bv[1] };
                uint32_t b1[2] = { bv[2], bv[3] };
                mma_fp16(ctx[np * 2],     aph, b0);
                mma_fp16(ctx[np * 2 + 1], aph, b1);
            }
        }
    }

    // ---- epilogue: normalize, split to fp16 hi/lo, write (b*t, d_model) ----
    float ri0 = 1.0f / lI0, ri1 = 1.0f / lI1;
    const int b_ = bh >> 4, h_ = bh & 15;
    const int t0 = q0 + m0 + g, t1 = t0 + 8;
#pragma unroll
    for (int nt = 0; nt < 16; nt++) {
        int col = h_ * D_HEAD + nt * 8 + tq * 2;
        {
            float o0 = ctx[nt][0] * ri0, o1 = ctx[nt][1] * ri0;
            __half2 hh, ll;
            hh.x = __float2half(o0); ll.x = __float2half(o0 - __half2float(hh.x));
            hh.y = __float2half(o1); ll.y = __float2half(o1 - __half2float(hh.y));
            size_t idx = (size_t)(b_ * SEQ + t0) * D_MODEL + col;
            *(__half2*)&g_ch16[idx] = hh;
            *(__half2*)&g_cl16[idx] = ll;
        }
        {
            float o0 = ctx[nt][2] * ri1, o1 = ctx[nt][3] * ri1;
            __half2 hh, ll;
            hh.x = __float2half(o0); ll.x = __float2half(o0 - __half2float(hh.x));
            hh.y = __float2half(o1); ll.y = __float2half(o1 - __half2float(hh.y));
            size_t idx = (size_t)(b_ * SEQ + t1) * D_MODEL + col;
            *(__half2*)&g_ch16[idx] = hh;
            *(__half2*)&g_cl16[idx] = ll;
        }
    }
}

// ---------------- launcher ----------------
extern "C" void kernel_launch(void* const* d_in, const int* in_sizes, int n_in,
                              void* d_out, int out_size)
{
    const float* x     = (const float*)d_in[0];
    const float* w_qkv = (const float*)d_in[1];
    const float* b_qkv = (const float*)d_in[2];
    const float* w_out = (const float*)d_in[3];
    const float* b_out = (const float*)d_in[4];
    float* out = (float*)d_out;

    (void)in_sizes; (void)n_in; (void)out_size;

    __half *x16, *wq, *wo, *ch, *cl;
    cudaGetSymbolAddress((void**)&x16, g_x16);
    cudaGetSymbolAddress((void**)&wq,  g_wq16);
    cudaGetSymbolAddress((void**)&wo,  g_wo16);
    cudaGetSymbolAddress((void**)&ch,  g_ch16);
    cudaGetSymbolAddress((void**)&cl,  g_cl16);

    // 0) conversions (single fp16)
    {
        int n4 = M_ROWS * D_MODEL / 4;
        conv_fp16_kernel<<<(n4 + 255) / 256, 256>>>(x, x16, n4);
        n4 = D_MODEL * N_QKV / 4;
        conv_fp16_kernel<<<(n4 + 255) / 256, 256>>>(w_qkv, wq, n4);
        n4 = D_MODEL * D_MODEL / 4;
        conv_fp16_kernel<<<(n4 + 255) / 256, 256>>>(w_out, wo, n4);
    }
    // 1) QKV projection (1-term fp16 mma)
    {
        cudaFuncSetAttribute(gemm_qkv_kernel,
                             cudaFuncAttributeMaxDynamicSharedMemorySize, QKV_SMEM_BYTES);
        dim3 grid(N_QKV / 128, M_ROWS / 128);
        gemm_qkv_kernel<<<grid, 256, QKV_SMEM_BYTES>>>(x16, wq, b_qkv);
    }
    // 2) RoPE (fp16 in-place)
    {
        int total = BH * SEQ * 64;
        rope_kernel<<<(total + 255) / 256, 256>>>();
    }
    // 3) Flash attention (fp16 mma; ctx written as fp16 hi/lo)
    {
        cudaFuncSetAttribute(attn_mma_kernel,
                             cudaFuncAttributeMaxDynamicSharedMemorySize, ATTN_SMEM_BYTES);
        dim3 grid(SEQ / 128, BH);
        attn_mma_kernel<<<grid, 256, ATTN_SMEM_BYTES>>>();
    }
    // 4) Output projection (2-term fp16 mma)
    {
        cudaFuncSetAttribute(gemm_out_kernel,
                             cudaFuncAttributeMaxDynamicSharedMemorySize, OUT_SMEM_BYTES);
        dim3 grid(D_MODEL / 128, M_ROWS / 128);
        gemm_out_kernel<<<grid, 256, OUT_SMEM_BYTES>>>(ch, cl, wo, b_out, out);
    }
}

// round 9
// speedup vs baseline: 7.7464x; 1.0655x over previous
#include <cuda_runtime.h>
#include <cuda_fp16.h>
#include <math.h>
#include <stdint.h>

#define D_MODEL 2048
#define N_HEADS 16
#define D_HEAD 128
#define BATCH 4
#define SEQ 2048
#define M_ROWS (BATCH*SEQ)      /* 8192 */
#define N_QKV (3*D_MODEL)       /* 6144 */
#define BH (BATCH*N_HEADS)      /* 64  */

// ---------------- scratch (no allocation allowed) ----------------
__device__ __half g_Qh[(size_t)BH*SEQ*D_HEAD];
__device__ __half g_Kh[(size_t)BH*SEQ*D_HEAD];
__device__ __half g_Vh[(size_t)BH*SEQ*D_HEAD];

__device__ __half g_x16[(size_t)M_ROWS*D_MODEL];
__device__ __half g_wq16[(size_t)D_MODEL*N_QKV];
__device__ __half g_wo16[(size_t)D_MODEL*D_MODEL];
__device__ __half g_ch16[(size_t)M_ROWS*D_MODEL];
__device__ __half g_cl16[(size_t)M_ROWS*D_MODEL];

// ---------------- helpers ----------------
__device__ __forceinline__ uint32_t smem_u32(const void* p) {
    return (uint32_t)__cvta_generic_to_shared(p);
}
#define CP_ASYNC16(dst, src) \
    asm volatile("cp.async.cg.shared.global [%0], [%1], 16;" :: "r"(dst), "l"(src))
#define CP_COMMIT()  asm volatile("cp.async.commit_group;" ::: "memory")
#define CP_WAITG(n)  asm volatile("cp.async.wait_group %0;" :: "n"(n) : "memory")

__device__ __forceinline__ void ldsm_x4(uint32_t (&r)[4], uint32_t addr) {
    asm volatile("ldmatrix.sync.aligned.m8n8.x4.shared.b16 {%0,%1,%2,%3}, [%4];"
                 : "=r"(r[0]), "=r"(r[1]), "=r"(r[2]), "=r"(r[3]) : "r"(addr));
}
__device__ __forceinline__ void ldsm_x4t(uint32_t (&r)[4], uint32_t addr) {
    asm volatile("ldmatrix.sync.aligned.m8n8.x4.trans.shared.b16 {%0,%1,%2,%3}, [%4];"
                 : "=r"(r[0]), "=r"(r[1]), "=r"(r[2]), "=r"(r[3]) : "r"(addr));
}
__device__ __forceinline__ void mma_fp16(float (&d)[4], const uint32_t (&a)[4],
                                         const uint32_t (&b)[2]) {
    asm volatile("mma.sync.aligned.m16n8k16.row.col.f32.f16.f16.f32 "
                 "{%0,%1,%2,%3}, {%4,%5,%6,%7}, {%8,%9}, {%0,%1,%2,%3};"
                 : "+f"(d[0]), "+f"(d[1]), "+f"(d[2]), "+f"(d[3])
                 : "r"(a[0]), "r"(a[1]), "r"(a[2]), "r"(a[3]),
                   "r"(b[0]), "r"(b[1]));
}

// ---------------- conversion kernel ----------------
__global__ __launch_bounds__(256)
void conv_fp16_kernel(const float* __restrict__ in, __half* __restrict__ o, int n4)
{
    int idx = blockIdx.x * blockDim.x + threadIdx.x;
    if (idx >= n4) return;
    float4 v = *(const float4*)&in[idx * 4];
    __half2 a, b;
    a.x = __float2half(v.x); a.y = __float2half(v.y);
    b.x = __float2half(v.z); b.y = __float2half(v.w);
    *(__half2*)&o[idx * 4]     = a;
    *(__half2*)&o[idx * 4 + 2] = b;
}

// ---------------- common tile constants (K-chunk = 64) ----------------
#define A64_STRIDE 72
#define B64_STRIDE 136
#define GA64 (128*A64_STRIDE)   /* 9216 elems: 128 rows x 64 cols (+pad) */
#define GB64 (64*B64_STRIDE)    /* 8704 elems: 64 rows x 128 cols (+pad) */
#define NCH64 (D_MODEL/64)      /* 32 chunks */

// ================= QKV GEMM: 1-term fp16, K64, 3-stage =============
#define Q64STAGE (GA64 + GB64)           /* 17920 elems */
#define QKV_SMEM_BYTES (3*Q64STAGE*2)    /* 107520 */

__device__ __forceinline__ void qkv_load_stage(char* dsm, int buf, int k0,
    const __half* A, const __half* Bs, int row0, int col0, int tid)
{
    uint32_t base = smem_u32(dsm) + (uint32_t)buf * (Q64STAGE*2);
#pragma unroll
    for (int s = 0; s < 4; s++) {
        int id = tid + s * 256;                 // 0..1023
        int ra = id >> 3, ca = id & 7;          // A: 128 rows x 8 chunks
        CP_ASYNC16(base + ra * (A64_STRIDE*2) + ca * 16,
                   A + (size_t)(row0 + ra) * D_MODEL + k0 + ca * 8);
        int rb = id >> 4, cb = id & 15;         // B: 64 rows x 16 chunks
        CP_ASYNC16(base + GA64*2 + rb * (B64_STRIDE*2) + cb * 16,
                   Bs + (size_t)(k0 + rb) * N_QKV + col0 + cb * 8);
    }
}

__device__ __forceinline__ void store_qkv_h(int grow, int gcol, float val)
{
    int b_ = grow >> 11;
    int t_ = grow & 2047;
    int which = gcol >> 11;     // 0=q 1=k 2=v
    int rem   = gcol & 2047;
    int h     = rem >> 7;
    int dd    = rem & 127;
    size_t idx = (((size_t)b_ * N_HEADS + h) * SEQ + t_) * D_HEAD + dd;
    __half hv = __float2half(val);
    if (which == 0)      g_Qh[idx] = hv;
    else if (which == 1) g_Kh[idx] = hv;
    else                 g_Vh[idx] = hv;
}

__global__ __launch_bounds__(256)
void gemm_qkv_kernel(const __half* __restrict__ A,
                     const __half* __restrict__ Bs,
                     const float* __restrict__ bias)
{
    extern __shared__ __align__(16) char dsm[];
    const int tid  = threadIdx.x;
    const int lane = tid & 31;
    const int warp = tid >> 5;
    const int wm = warp & 1;
    const int wn = warp >> 1;
    const int row0 = blockIdx.y * 128;
    const int col0 = blockIdx.x * 128;
    const int l16 = lane & 15;
    const int lhi = lane >> 4;

    float acc[4][4][4];
#pragma unroll
    for (int i = 0; i < 4; i++)
#pragma unroll
        for (int j = 0; j < 4; j++)
#pragma unroll
            for (int k = 0; k < 4; k++) acc[i][j][k] = 0.f;

    qkv_load_stage(dsm, 0, 0,  A, Bs, row0, col0, tid);
    CP_COMMIT();
    qkv_load_stage(dsm, 1, 64, A, Bs, row0, col0, tid);
    CP_COMMIT();

    int bufc = 0;
#pragma unroll 1
    for (int c = 0; c < NCH64; c++) {
        CP_WAITG(1);
        __syncthreads();

        int bufl = bufc + 2; if (bufl >= 3) bufl -= 3;
        if (c + 2 < NCH64)
            qkv_load_stage(dsm, bufl, (c + 2) * 64, A, Bs, row0, col0, tid);
        CP_COMMIT();

        const __half* As  = (const __half*)(dsm + (size_t)bufc * Q64STAGE * 2);
        const __half* Bss = As + GA64;

#pragma unroll
        for (int ksub = 0; ksub < 4; ksub++) {
            uint32_t bf[4][2];
#pragma unroll
            for (int np = 0; np < 2; np++) {
                uint32_t bk[4];
                ldsm_x4t(bk, smem_u32(&Bss[(ksub*16 + l16) * B64_STRIDE +
                                           wn*32 + (np*2 + lhi)*8]));
                bf[np*2][0]   = bk[0]; bf[np*2][1]   = bk[1];
                bf[np*2+1][0] = bk[2]; bf[np*2+1][1] = bk[3];
            }
#pragma unroll
            for (int mt = 0; mt < 4; mt++) {
                uint32_t ah[4];
                ldsm_x4(ah, smem_u32(&As[(wm*64 + mt*16 + l16) * A64_STRIDE + ksub*16 + lhi*8]));
#pragma unroll
                for (int nt = 0; nt < 4; nt++)
                    mma_fp16(acc[mt][nt], ah, bf[nt]);
            }
        }
        bufc++; if (bufc >= 3) bufc = 0;
    }

    const int g = lane >> 2, tq = lane & 3;
#pragma unroll
    for (int mt = 0; mt < 4; mt++) {
#pragma unroll
        for (int nt = 0; nt < 4; nt++) {
            int r = row0 + wm*64 + mt*16 + g;
            int cc = col0 + wn*32 + nt*8 + tq*2;
            float bias0 = __ldg(&bias[cc]);
            float bias1 = __ldg(&bias[cc + 1]);
            store_qkv_h(r,     cc,     acc[mt][nt][0] + bias0);
            store_qkv_h(r,     cc + 1, acc[mt][nt][1] + bias1);
            store_qkv_h(r + 8, cc,     acc[mt][nt][2] + bias0);
            store_qkv_h(r + 8, cc + 1, acc[mt][nt][3] + bias1);
        }
    }
}

// ================= out-proj GEMM: 2-term fp16, K64, 2-stage =============
#define O64STAGE (2*GA64 + GB64)         /* 27136 elems */
#define OUT_SMEM_BYTES (2*O64STAGE*2)    /* 108544 */

__device__ __forceinline__ void out_load_stage(char* dsm, int buf, int k0,
    const __half* Ah, const __half* Al, const __half* Bs,
    int row0, int col0, int tid)
{
    uint32_t base = smem_u32(dsm) + (uint32_t)buf * (O64STAGE*2);
#pragma unroll
    for (int s = 0; s < 4; s++) {
        int id = tid + s * 256;
        int ra = id >> 3, ca = id & 7;
        uint32_t da = base + ra * (A64_STRIDE*2) + ca * 16;
        const size_t aoff = (size_t)(row0 + ra) * D_MODEL + k0 + ca * 8;
        CP_ASYNC16(da, Ah + aoff);
        CP_ASYNC16(da + GA64*2, Al + aoff);
        int rb = id >> 4, cb = id & 15;
        CP_ASYNC16(base + 2*GA64*2 + rb * (B64_STRIDE*2) + cb * 16,
                   Bs + (size_t)(k0 + rb) * D_MODEL + col0 + cb * 8);
    }
}

__global__ __launch_bounds__(256)
void gemm_out_kernel(const __half* __restrict__ Ah,
                     const __half* __restrict__ Al,
                     const __half* __restrict__ Bs,
                     const float* __restrict__ bias,
                     float* __restrict__ out)
{
    extern __shared__ __align__(16) char dsm[];
    const int tid  = threadIdx.x;
    const int lane = tid & 31;
    const int warp = tid >> 5;
    const int wm = warp & 1;
    const int wn = warp >> 1;
    const int row0 = blockIdx.y * 128;
    const int col0 = blockIdx.x * 128;
    const int l16 = lane & 15;
    const int lhi = lane >> 4;

    float acc[4][4][4];
#pragma unroll
    for (int i = 0; i < 4; i++)
#pragma unroll
        for (int j = 0; j < 4; j++)
#pragma unroll
            for (int k = 0; k < 4; k++) acc[i][j][k] = 0.f;

    out_load_stage(dsm, 0, 0,  Ah, Al, Bs, row0, col0, tid);
    CP_COMMIT();
    out_load_stage(dsm, 1, 64, Ah, Al, Bs, row0, col0, tid);
    CP_COMMIT();

#pragma unroll 1
    for (int c = 0; c < NCH64; c++) {
        CP_WAITG(1);
        __syncthreads();

        const __half* Ahs = (const __half*)(dsm + (size_t)(c & 1) * O64STAGE * 2);
        const __half* Als = Ahs + GA64;
        const __half* Bss = Als + GA64;

#pragma unroll
        for (int ksub = 0; ksub < 4; ksub++) {
            uint32_t bf[4][2];
#pragma unroll
            for (int np = 0; np < 2; np++) {
                uint32_t bk[4];
                ldsm_x4t(bk, smem_u32(&Bss[(ksub*16 + l16) * B64_STRIDE +
                                           wn*32 + (np*2 + lhi)*8]));
                bf[np*2][0]   = bk[0]; bf[np*2][1]   = bk[1];
                bf[np*2+1][0] = bk[2]; bf[np*2+1][1] = bk[3];
            }
#pragma unroll
            for (int mt = 0; mt < 4; mt++) {
                uint32_t ah[4], al[4];
                ldsm_x4(ah, smem_u32(&Ahs[(wm*64 + mt*16 + l16) * A64_STRIDE + ksub*16 + lhi*8]));
                ldsm_x4(al, smem_u32(&Als[(wm*64 + mt*16 + l16) * A64_STRIDE + ksub*16 + lhi*8]));
#pragma unroll
                for (int nt = 0; nt < 4; nt++) {
                    mma_fp16(acc[mt][nt], ah, bf[nt]);
                    mma_fp16(acc[mt][nt], al, bf[nt]);
                }
            }
        }

        __syncthreads();      // all warps done reading buf (c&1)
        if (c + 2 < NCH64)
            out_load_stage(dsm, c & 1, (c + 2) * 64, Ah, Al, Bs, row0, col0, tid);
        CP_COMMIT();
    }

    const int g = lane >> 2, tq = lane & 3;
#pragma unroll
    for (int mt = 0; mt < 4; mt++) {
#pragma unroll
        for (int nt = 0; nt < 4; nt++) {
            int r = row0 + wm*64 + mt*16 + g;
            int cc = col0 + wn*32 + nt*8 + tq*2;
            float bias0 = __ldg(&bias[cc]);
            float bias1 = __ldg(&bias[cc + 1]);
            out[(size_t)r * D_MODEL + cc]           = acc[mt][nt][0] + bias0;
            out[(size_t)r * D_MODEL + cc + 1]       = acc[mt][nt][1] + bias1;
            out[(size_t)(r + 8) * D_MODEL + cc]     = acc[mt][nt][2] + bias0;
            out[(size_t)(r + 8) * D_MODEL + cc + 1] = acc[mt][nt][3] + bias1;
        }
    }
}

// -------- RoPE: in-place on fp16 Q/K (fp32 internal math) --------
__global__ __launch_bounds__(256)
void rope_kernel()
{
    int idx = blockIdx.x * blockDim.x + threadIdx.x;
    if (idx >= BH * SEQ * 64) return;
    int i  = idx & 63;
    int t  = (idx >> 6) & (SEQ - 1);
    int bh = idx >> 17;

    float inv = __expf(-(float)i * (9.210340371976184f / 64.0f));
    float freq = (float)t * inv;
    float s, c;
    __sincosf(freq, &s, &c);

    size_t base = ((size_t)bh * SEQ + t) * D_HEAD;
    float q1 = __half2float(g_Qh[base + i]);
    float q2 = __half2float(g_Qh[base + i + 64]);
    g_Qh[base + i]      = __float2half(q1 * c - q2 * s);
    g_Qh[base + i + 64] = __float2half(q2 * c + q1 * s);
    float k1 = __half2float(g_Kh[base + i]);
    float k2 = __half2float(g_Kh[base + i + 64]);
    g_Kh[base + i]      = __float2half(k1 * c - k2 * s);
    g_Kh[base + i + 64] = __float2half(k2 * c + k1 * s);
}

// ---------------- Flash attention via mma.sync (fp16) ----------------
#define TS 136
#define PS 72
#define ATTN_Q_ELEMS (128*TS)
#define ATTN_K_ELEMS (64*TS)
#define ATTN_P_ELEMS (128*PS)
#define ATTN_SMEM_BYTES ((ATTN_Q_ELEMS + 2*ATTN_K_ELEMS + ATTN_P_ELEMS)*2)

__global__ __launch_bounds__(256)
void attn_mma_kernel()
{
    extern __shared__ __align__(16) char dsm[];
    __half* Qs = (__half*)dsm;
    __half* Ks = Qs + ATTN_Q_ELEMS;
    __half* Vs = Ks + ATTN_K_ELEMS;
    __half* Ps = Vs + ATTN_K_ELEMS;

    const int bh = blockIdx.y;
    const int qt = (SEQ/128 - 1) - blockIdx.x;   // heavy tiles first
    const int q0 = qt * 128;
    const float SC2 = 0.08838834764831845f * 1.4426950408889634f;

    const __half* Qg = g_Qh + (size_t)bh * SEQ * D_HEAD;
    const __half* Kg = g_Kh + (size_t)bh * SEQ * D_HEAD;
    const __half* Vg = g_Vh + (size_t)bh * SEQ * D_HEAD;

    const int tid = threadIdx.x;
    const int warp = tid >> 5, lane = tid & 31;
    const int m0 = warp * 16;
    const int l16 = lane & 15, lhi = lane >> 4;
    const int g = lane >> 2, tq = lane & 3;

    for (int i = tid; i < 128 * 16; i += 256) {
        int r = i >> 4, c16 = i & 15;
        CP_ASYNC16(smem_u32(&Qs[r * TS + c16 * 8]),
                   &Qg[(size_t)(q0 + r) * D_HEAD + c16 * 8]);
    }
    CP_COMMIT();

    float mI0 = -INFINITY, mI1 = -INFINITY, lI0 = 0.f, lI1 = 0.f;
    float ctx[16][4];
#pragma unroll
    for (int i = 0; i < 16; i++)
#pragma unroll
        for (int j = 0; j < 4; j++) ctx[i][j] = 0.f;

    const int ktiles = 2 * qt + 2;
#pragma unroll 1
    for (int kt = 0; kt < ktiles; kt++) {
        const int kb = kt * 64;
        __syncthreads();
        for (int i = tid; i < 64 * 16; i += 256) {
            int r = i >> 4, c16 = i & 15;
            size_t goff = (size_t)(kb + r) * D_HEAD + c16 * 8;
            CP_ASYNC16(smem_u32(&Ks[r * TS + c16 * 8]), &Kg[goff]);
            CP_ASYNC16(smem_u32(&Vs[r * TS + c16 * 8]), &Vg[goff]);
        }
        CP_COMMIT();
        CP_WAITG(0);
        __syncthreads();

        float sacc[8][4];
#pragma unroll
        for (int nt = 0; nt < 8; nt++)
#pragma unroll
            for (int e = 0; e < 4; e++) sacc[nt][e] = 0.f;

        const int krow = lane & 7;
        const int kpair = (lane >> 4) & 1;
        const int kcolsel = ((lane >> 3) & 1) * 8;
#pragma unroll
        for (int ks = 0; ks < 8; ks++) {
            uint32_t ah[4];
            ldsm_x4(ah, smem_u32(&Qs[(m0 + l16) * TS + ks * 16 + lhi * 8]));
#pragma unroll
            for (int np = 0; np < 4; np++) {
                uint32_t bk[4];
                ldsm_x4(bk, smem_u32(&Ks[((np * 2 + kpair) * 8 + krow) * TS +
                                         ks * 16 + kcolsel]));
                uint32_t b0[2] = { bk[0], bk[1] };
                uint32_t b1[2] = { bk[2], bk[3] };
                mma_fp16(sacc[np * 2],     ah, b0);
                mma_fp16(sacc[np * 2 + 1], ah, b1);
            }
        }

        const bool diag = (kt >= ktiles - 2);
        const int r0 = q0 + m0 + g, r1 = r0 + 8;
        float rm0 = -INFINITY, rm1 = -INFINITY;
#pragma unroll
        for (int nt = 0; nt < 8; nt++) {
            int cb0 = kb + nt * 8 + tq * 2;
            float s0 = sacc[nt][0] * SC2, s1 = sacc[nt][1] * SC2;
            float s2 = sacc[nt][2] * SC2, s3 = sacc[nt][3] * SC2;
            if (diag) {
                if (cb0     > r0) s0 = -INFINITY;
                if (cb0 + 1 > r0) s1 = -INFINITY;
                if (cb0     > r1) s2 = -INFINITY;
                if (cb0 + 1 > r1) s3 = -INFINITY;
            }
            sacc[nt][0] = s0; sacc[nt][1] = s1; sacc[nt][2] = s2; sacc[nt][3] = s3;
            rm0 = fmaxf(rm0, fmaxf(s0, s1));
            rm1 = fmaxf(rm1, fmaxf(s2, s3));
        }
        rm0 = fmaxf(rm0, __shfl_xor_sync(0xffffffffu, rm0, 1));
        rm0 = fmaxf(rm0, __shfl_xor_sync(0xffffffffu, rm0, 2));
        rm1 = fmaxf(rm1, __shfl_xor_sync(0xffffffffu, rm1, 1));
        rm1 = fmaxf(rm1, __shfl_xor_sync(0xffffffffu, rm1, 2));
        float mn0 = fmaxf(mI0, rm0), mn1 = fmaxf(mI1, rm1);
        float c0 = exp2f(mI0 - mn0), c1 = exp2f(mI1 - mn1);
        float ps0 = 0.f, ps1 = 0.f;
#pragma unroll
        for (int nt = 0; nt < 8; nt++) {
            float p0 = exp2f(sacc[nt][0] - mn0);
            float p1 = exp2f(sacc[nt][1] - mn0);
            float p2 = exp2f(sacc[nt][2] - mn1);
            float p3 = exp2f(sacc[nt][3] - mn1);
            ps0 += p0 + p1; ps1 += p2 + p3;
            __half2 ph;
            ph.x = __float2half(p0); ph.y = __float2half(p1);
            *(__half2*)&Ps[(m0 + g) * PS + nt * 8 + tq * 2] = ph;
            ph.x = __float2half(p2); ph.y = __float2half(p3);
            *(__half2*)&Ps[(m0 + g + 8) * PS + nt * 8 + tq * 2] = ph;
        }
        ps0 += __shfl_xor_sync(0xffffffffu, ps0, 1);
        ps0 += __shfl_xor_sync(0xffffffffu, ps0, 2);
        ps1 += __shfl_xor_sync(0xffffffffu, ps1, 1);
        ps1 += __shfl_xor_sync(0xffffffffu, ps1, 2);
        lI0 = lI0 * c0 + ps0; lI1 = lI1 * c1 + ps1;
        mI0 = mn0; mI1 = mn1;
#pragma unroll
        for (int n2 = 0; n2 < 16; n2++) {
            ctx[n2][0] *= c0; ctx[n2][1] *= c0;
            ctx[n2][2] *= c1; ctx[n2][3] *= c1;
        }
        __syncwarp();

        const int vpair = lane >> 4;
#pragma unroll
        for (int ks = 0; ks < 4; ks++) {
            uint32_t aph[4];
            ldsm_x4(aph, smem_u32(&Ps[(m0 + l16) * PS + ks * 16 + lhi * 8]));
#pragma unroll
            for (int np = 0; np < 8; np++) {
                uint32_t bv[4];
                ldsm_x4t(bv, smem_u32(&Vs[(ks * 16 + l16) * TS +
                                          (np * 2 + vpair) * 8]));
                uint32_t b0[2] = { bv[0], bv[1] };
                uint32_t b1[2] = { bv[2], bv[3] };
                mma_fp16(ctx[np * 2],     aph, b0);
                mma_fp16(ctx[np * 2 + 1], aph, b1);
            }
        }
    }

    // ---- epilogue: normalize, split to fp16 hi/lo, write (b*t, d_model) ----
    float ri0 = 1.0f / lI0, ri1 = 1.0f / lI1;
    const int b_ = bh >> 4, h_ = bh & 15;
    const int t0 = q0 + m0 + g, t1 = t0 + 8;
#pragma unroll
    for (int nt = 0; nt < 16; nt++) {
        int col = h_ * D_HEAD + nt * 8 + tq * 2;
        {
            float o0 = ctx[nt][0] * ri0, o1 = ctx[nt][1] * ri0;
            __half2 hh, ll;
            hh.x = __float2half(o0); ll.x = __float2half(o0 - __half2float(hh.x));
            hh.y = __float2half(o1); ll.y = __float2half(o1 - __half2float(hh.y));
            size_t idx = (size_t)(b_ * SEQ + t0) * D_MODEL + col;
            *(__half2*)&g_ch16[idx] = hh;
            *(__half2*)&g_cl16[idx] = ll;
        }
        {
            float o0 = ctx[nt][2] * ri1, o1 = ctx[nt][3] * ri1;
            __half2 hh, ll;
            hh.x = __float2half(o0); ll.x = __float2half(o0 - __half2float(hh.x));
            hh.y = __float2half(o1); ll.y = __float2half(o1 - __half2float(hh.y));
            size_t idx = (size_t)(b_ * SEQ + t1) * D_MODEL + col;
            *(__half2*)&g_ch16[idx] = hh;
            *(__half2*)&g_cl16[idx] = ll;
        }
    }
}

// ---------------- launcher ----------------
extern "C" void kernel_launch(void* const* d_in, const int* in_sizes, int n_in,
                              void* d_out, int out_size)
{
    const float* x     = (const float*)d_in[0];
    const float* w_qkv = (const float*)d_in[1];
    const float* b_qkv = (const float*)d_in[2];
    const float* w_out = (const float*)d_in[3];
    const float* b_out = (const float*)d_in[4];
    float* out = (float*)d_out;

    (void)in_sizes; (void)n_in; (void)out_size;

    __half *x16, *wq, *wo, *ch, *cl;
    cudaGetSymbolAddress((void**)&x16, g_x16);
    cudaGetSymbolAddress((void**)&wq,  g_wq16);
    cudaGetSymbolAddress((void**)&wo,  g_wo16);
    cudaGetSymbolAddress((void**)&ch,  g_ch16);
    cudaGetSymbolAddress((void**)&cl,  g_cl16);

    // 0) conversions (single fp16)
    {
        int n4 = M_ROWS * D_MODEL / 4;
        conv_fp16_kernel<<<(n4 + 255) / 256, 256>>>(x, x16, n4);
        n4 = D_MODEL * N_QKV / 4;
        conv_fp16_kernel<<<(n4 + 255) / 256, 256>>>(w_qkv, wq, n4);
        n4 = D_MODEL * D_MODEL / 4;
        conv_fp16_kernel<<<(n4 + 255) / 256, 256>>>(w_out, wo, n4);
    }
    // 1) QKV projection (1-term fp16 mma, K64, 3-stage)
    {
        cudaFuncSetAttribute(gemm_qkv_kernel,
                             cudaFuncAttributeMaxDynamicSharedMemorySize, QKV_SMEM_BYTES);
        dim3 grid(N_QKV / 128, M_ROWS / 128);
        gemm_qkv_kernel<<<grid, 256, QKV_SMEM_BYTES>>>(x16, wq, b_qkv);
    }
    // 2) RoPE (fp16 in-place)
    {
        int total = BH * SEQ * 64;
        rope_kernel<<<(total + 255) / 256, 256>>>();
    }
    // 3) Flash attention (fp16 mma; ctx written as fp16 hi/lo)
    {
        cudaFuncSetAttribute(attn_mma_kernel,
                             cudaFuncAttributeMaxDynamicSharedMemorySize, ATTN_SMEM_BYTES);
        dim3 grid(SEQ / 128, BH);
        attn_mma_kernel<<<grid, 256, ATTN_SMEM_BYTES>>>();
    }
    // 4) Output projection (2-term fp16 mma, K64, 2-stage)
    {
        cudaFuncSetAttribute(gemm_out_kernel,
                             cudaFuncAttributeMaxDynamicSharedMemorySize, OUT_SMEM_BYTES);
        dim3 grid(D_MODEL / 128, M_ROWS / 128);
        gemm_out_kernel<<<grid, 256, OUT_SMEM_BYTES>>>(ch, cl, wo, b_out, out);
    }
}

// round 10
// speedup vs baseline: 8.9724x; 1.1583x over previous
#include <cuda_runtime.h>
#include <cuda_fp16.h>
#include <math.h>
#include <stdint.h>

#define D_MODEL 2048
#define N_HEADS 16
#define D_HEAD 128
#define BATCH 4
#define SEQ 2048
#define M_ROWS (BATCH*SEQ)      /* 8192 */
#define N_QKV (3*D_MODEL)       /* 6144 */
#define BH (BATCH*N_HEADS)      /* 64  */

// ---------------- scratch (no allocation allowed) ----------------
__device__ __half g_Qh[(size_t)BH*SEQ*D_HEAD];
__device__ __half g_Kh[(size_t)BH*SEQ*D_HEAD];
__device__ __half g_Vh[(size_t)BH*SEQ*D_HEAD];

__device__ __half g_x16[(size_t)M_ROWS*D_MODEL];
__device__ __half g_wq16[(size_t)D_MODEL*N_QKV];
__device__ __half g_wo16[(size_t)D_MODEL*D_MODEL];
__device__ __half g_c16[(size_t)M_ROWS*D_MODEL];

// ---------------- helpers ----------------
__device__ __forceinline__ uint32_t smem_u32(const void* p) {
    return (uint32_t)__cvta_generic_to_shared(p);
}
#define CP_ASYNC16(dst, src) \
    asm volatile("cp.async.cg.shared.global [%0], [%1], 16;" :: "r"(dst), "l"(src))
#define CP_COMMIT()  asm volatile("cp.async.commit_group;" ::: "memory")
#define CP_WAITG(n)  asm volatile("cp.async.wait_group %0;" :: "n"(n) : "memory")

__device__ __forceinline__ void ldsm_x4(uint32_t (&r)[4], uint32_t addr) {
    asm volatile("ldmatrix.sync.aligned.m8n8.x4.shared.b16 {%0,%1,%2,%3}, [%4];"
                 : "=r"(r[0]), "=r"(r[1]), "=r"(r[2]), "=r"(r[3]) : "r"(addr));
}
__device__ __forceinline__ void ldsm_x4t(uint32_t (&r)[4], uint32_t addr) {
    asm volatile("ldmatrix.sync.aligned.m8n8.x4.trans.shared.b16 {%0,%1,%2,%3}, [%4];"
                 : "=r"(r[0]), "=r"(r[1]), "=r"(r[2]), "=r"(r[3]) : "r"(addr));
}
__device__ __forceinline__ void mma_fp16(float (&d)[4], const uint32_t (&a)[4],
                                         const uint32_t (&b)[2]) {
    asm volatile("mma.sync.aligned.m16n8k16.row.col.f32.f16.f16.f32 "
                 "{%0,%1,%2,%3}, {%4,%5,%6,%7}, {%8,%9}, {%0,%1,%2,%3};"
                 : "+f"(d[0]), "+f"(d[1]), "+f"(d[2]), "+f"(d[3])
                 : "r"(a[0]), "r"(a[1]), "r"(a[2]), "r"(a[3]),
                   "r"(b[0]), "r"(b[1]));
}

// ---------------- conversion kernel ----------------
__global__ __launch_bounds__(256)
void conv_fp16_kernel(const float* __restrict__ in, __half* __restrict__ o, int n4)
{
    int idx = blockIdx.x * blockDim.x + threadIdx.x;
    if (idx >= n4) return;
    float4 v = *(const float4*)&in[idx * 4];
    __half2 a, b;
    a.x = __float2half(v.x); a.y = __float2half(v.y);
    b.x = __float2half(v.z); b.y = __float2half(v.w);
    *(__half2*)&o[idx * 4]     = a;
    *(__half2*)&o[idx * 4 + 2] = b;
}

// ---------------- tile constants (K-chunk = 64) ----------------
#define A64_STRIDE 72
#define B64_STRIDE 136
#define GA64 (128*A64_STRIDE)   /* 9216 elems */
#define GB64 (64*B64_STRIDE)    /* 8704 elems */
#define NCH64 (D_MODEL/64)      /* 32 chunks */
#define G64STAGE (GA64 + GB64)           /* 17920 elems */
#define GEMM_SMEM_BYTES (3*G64STAGE*2)   /* 107520 */
#define STG_STRIDE 136

// ================= 1-term fp16 GEMM (K64, 3-stage) =============
template<int N_DIM>
__device__ __forceinline__ void g_load_stage(char* dsm, int buf, int k0,
    const __half* A, const __half* Bs, int row0, int col0, int tid)
{
    uint32_t base = smem_u32(dsm) + (uint32_t)buf * (G64STAGE*2);
#pragma unroll
    for (int s = 0; s < 4; s++) {
        int id = tid + s * 256;                 // 0..1023
        int ra = id >> 3, ca = id & 7;          // A: 128 rows x 8 chunks
        CP_ASYNC16(base + ra * (A64_STRIDE*2) + ca * 16,
                   A + (size_t)(row0 + ra) * D_MODEL + k0 + ca * 8);
        int rb = id >> 4, cb = id & 15;         // B: 64 rows x 16 chunks
        CP_ASYNC16(base + GA64*2 + rb * (B64_STRIDE*2) + cb * 16,
                   Bs + (size_t)(k0 + rb) * N_DIM + col0 + cb * 8);
    }
}

template<int N_DIM, bool IS_QKV>
__global__ __launch_bounds__(256)
void gemm_kernel(const __half* __restrict__ A,
                 const __half* __restrict__ Bs,
                 const float* __restrict__ bias,
                 float* __restrict__ out)
{
    extern __shared__ __align__(16) char dsm[];
    const int tid  = threadIdx.x;
    const int lane = tid & 31;
    const int warp = tid >> 5;
    const int wm = warp & 1;
    const int wn = warp >> 1;
    const int row0 = blockIdx.y * 128;
    const int col0 = blockIdx.x * 128;
    const int l16 = lane & 15;
    const int lhi = lane >> 4;

    float acc[4][4][4];
#pragma unroll
    for (int i = 0; i < 4; i++)
#pragma unroll
        for (int j = 0; j < 4; j++)
#pragma unroll
            for (int k = 0; k < 4; k++) acc[i][j][k] = 0.f;

    g_load_stage<N_DIM>(dsm, 0, 0,  A, Bs, row0, col0, tid);
    CP_COMMIT();
    g_load_stage<N_DIM>(dsm, 1, 64, A, Bs, row0, col0, tid);
    CP_COMMIT();

    int bufc = 0;
#pragma unroll 1
    for (int c = 0; c < NCH64; c++) {
        CP_WAITG(1);
        __syncthreads();

        int bufl = bufc + 2; if (bufl >= 3) bufl -= 3;
        if (c + 2 < NCH64)
            g_load_stage<N_DIM>(dsm, bufl, (c + 2) * 64, A, Bs, row0, col0, tid);
        CP_COMMIT();

        const __half* As  = (const __half*)(dsm + (size_t)bufc * G64STAGE * 2);
        const __half* Bss = As + GA64;

#pragma unroll
        for (int ksub = 0; ksub < 4; ksub++) {
            uint32_t bf[4][2];
#pragma unroll
            for (int np = 0; np < 2; np++) {
                uint32_t bk[4];
                ldsm_x4t(bk, smem_u32(&Bss[(ksub*16 + l16) * B64_STRIDE +
                                           wn*32 + (np*2 + lhi)*8]));
                bf[np*2][0]   = bk[0]; bf[np*2][1]   = bk[1];
                bf[np*2+1][0] = bk[2]; bf[np*2+1][1] = bk[3];
            }
#pragma unroll
            for (int mt = 0; mt < 4; mt++) {
                uint32_t ah[4];
                ldsm_x4(ah, smem_u32(&As[(wm*64 + mt*16 + l16) * A64_STRIDE + ksub*16 + lhi*8]));
#pragma unroll
                for (int nt = 0; nt < 4; nt++)
                    mma_fp16(acc[mt][nt], ah, bf[nt]);
            }
        }
        bufc++; if (bufc >= 3) bufc = 0;
    }

    const int g = lane >> 2, tq = lane & 3;

    if (IS_QKV) {
        // stage bias-added fp16 tile in smem, then vectorized scatter
        __syncthreads();
        __half* stg = (__half*)dsm;   // 128 x STG_STRIDE
#pragma unroll
        for (int mt = 0; mt < 4; mt++) {
#pragma unroll
            for (int nt = 0; nt < 4; nt++) {
                int rr = wm*64 + mt*16 + g;
                int cc = wn*32 + nt*8 + tq*2;
                float bias0 = __ldg(&bias[col0 + cc]);
                float bias1 = __ldg(&bias[col0 + cc + 1]);
                __half2 v0, v1;
                v0.x = __float2half(acc[mt][nt][0] + bias0);
                v0.y = __float2half(acc[mt][nt][1] + bias1);
                v1.x = __float2half(acc[mt][nt][2] + bias0);
                v1.y = __float2half(acc[mt][nt][3] + bias1);
                *(__half2*)&stg[rr * STG_STRIDE + cc]       = v0;
                *(__half2*)&stg[(rr + 8) * STG_STRIDE + cc] = v1;
            }
        }
        __syncthreads();

        // col0 block covers exactly one head's d-range for one of q/k/v
        const int which = col0 >> 11;        // 0=q 1=k 2=v
        const int h_    = (col0 & 2047) >> 7;
        __half* buf = (which == 0) ? g_Qh : ((which == 1) ? g_Kh : g_Vh);

        const int r  = tid >> 1;             // 0..127
        const int hf = tid & 1;              // half-row: cols hf*64..+63
        const int grow = row0 + r;
        const int b_ = grow >> 11;
        const int t_ = grow & 2047;
        size_t gbase = (((size_t)b_ * N_HEADS + h_) * SEQ + t_) * D_HEAD + hf * 64;
        const __half* src = &stg[r * STG_STRIDE + hf * 64];
#pragma unroll
        for (int i = 0; i < 8; i++)
            *(uint4*)&buf[gbase + i * 8] = *(const uint4*)&src[i * 8];
    } else {
#pragma unroll
        for (int mt = 0; mt < 4; mt++) {
#pragma unroll
            for (int nt = 0; nt < 4; nt++) {
                int r = row0 + wm*64 + mt*16 + g;
                int cc = col0 + wn*32 + nt*8 + tq*2;
                float bias0 = __ldg(&bias[cc]);
                float bias1 = __ldg(&bias[cc + 1]);
                out[(size_t)r * D_MODEL + cc]           = acc[mt][nt][0] + bias0;
                out[(size_t)r * D_MODEL + cc + 1]       = acc[mt][nt][1] + bias1;
                out[(size_t)(r + 8) * D_MODEL + cc]     = acc[mt][nt][2] + bias0;
                out[(size_t)(r + 8) * D_MODEL + cc + 1] = acc[mt][nt][3] + bias1;
            }
        }
    }
}

// -------- RoPE: in-place on fp16 Q/K (fp32 internal math) --------
__global__ __launch_bounds__(256)
void rope_kernel()
{
    int idx = blockIdx.x * blockDim.x + threadIdx.x;
    if (idx >= BH * SEQ * 64) return;
    int i  = idx & 63;
    int t  = (idx >> 6) & (SEQ - 1);
    int bh = idx >> 17;

    float inv = __expf(-(float)i * (9.210340371976184f / 64.0f));
    float freq = (float)t * inv;
    float s, c;
    __sincosf(freq, &s, &c);

    size_t base = ((size_t)bh * SEQ + t) * D_HEAD;
    float q1 = __half2float(g_Qh[base + i]);
    float q2 = __half2float(g_Qh[base + i + 64]);
    g_Qh[base + i]      = __float2half(q1 * c - q2 * s);
    g_Qh[base + i + 64] = __float2half(q2 * c + q1 * s);
    float k1 = __half2float(g_Kh[base + i]);
    float k2 = __half2float(g_Kh[base + i + 64]);
    g_Kh[base + i]      = __float2half(k1 * c - k2 * s);
    g_Kh[base + i + 64] = __float2half(k2 * c + k1 * s);
}

// ---------------- Flash attention via mma.sync (fp16) ----------------
#define TS 136
#define PS 72
#define ATTN_Q_ELEMS (128*TS)
#define ATTN_K_ELEMS (64*TS)
#define ATTN_P_ELEMS (128*PS)
#define ATTN_SMEM_BYTES ((ATTN_Q_ELEMS + 2*ATTN_K_ELEMS + ATTN_P_ELEMS)*2)

__global__ __launch_bounds__(256)
void attn_mma_kernel()
{
    extern __shared__ __align__(16) char dsm[];
    __half* Qs = (__half*)dsm;
    __half* Ks = Qs + ATTN_Q_ELEMS;
    __half* Vs = Ks + ATTN_K_ELEMS;
    __half* Ps = Vs + ATTN_K_ELEMS;

    const int bh = blockIdx.y;
    const int qt = (SEQ/128 - 1) - blockIdx.x;   // heavy tiles first
    const int q0 = qt * 128;
    const float SC2 = 0.08838834764831845f * 1.4426950408889634f;

    const __half* Qg = g_Qh + (size_t)bh * SEQ * D_HEAD;
    const __half* Kg = g_Kh + (size_t)bh * SEQ * D_HEAD;
    const __half* Vg = g_Vh + (size_t)bh * SEQ * D_HEAD;

    const int tid = threadIdx.x;
    const int warp = tid >> 5, lane = tid & 31;
    const int m0 = warp * 16;
    const int l16 = lane & 15, lhi = lane >> 4;
    const int g = lane >> 2, tq = lane & 3;

    for (int i = tid; i < 128 * 16; i += 256) {
        int r = i >> 4, c16 = i & 15;
        CP_ASYNC16(smem_u32(&Qs[r * TS + c16 * 8]),
                   &Qg[(size_t)(q0 + r) * D_HEAD + c16 * 8]);
    }
    CP_COMMIT();

    float mI0 = -INFINITY, mI1 = -INFINITY, lI0 = 0.f, lI1 = 0.f;
    float ctx[16][4];
#pragma unroll
    for (int i = 0; i < 16; i++)
#pragma unroll
        for (int j = 0; j < 4; j++) ctx[i][j] = 0.f;

    const int ktiles = 2 * qt + 2;
#pragma unroll 1
    for (int kt = 0; kt < ktiles; kt++) {
        const int kb = kt * 64;
        __syncthreads();
        for (int i = tid; i < 64 * 16; i += 256) {
            int r = i >> 4, c16 = i & 15;
            size_t goff = (size_t)(kb + r) * D_HEAD + c16 * 8;
            CP_ASYNC16(smem_u32(&Ks[r * TS + c16 * 8]), &Kg[goff]);
            CP_ASYNC16(smem_u32(&Vs[r * TS + c16 * 8]), &Vg[goff]);
        }
        CP_COMMIT();
        CP_WAITG(0);
        __syncthreads();

        float sacc[8][4];
#pragma unroll
        for (int nt = 0; nt < 8; nt++)
#pragma unroll
            for (int e = 0; e < 4; e++) sacc[nt][e] = 0.f;

        const int krow = lane & 7;
        const int kpair = (lane >> 4) & 1;
        const int kcolsel = ((lane >> 3) & 1) * 8;
#pragma unroll
        for (int ks = 0; ks < 8; ks++) {
            uint32_t ah[4];
            ldsm_x4(ah, smem_u32(&Qs[(m0 + l16) * TS + ks * 16 + lhi * 8]));
#pragma unroll
            for (int np = 0; np < 4; np++) {
                uint32_t bk[4];
                ldsm_x4(bk, smem_u32(&Ks[((np * 2 + kpair) * 8 + krow) * TS +
                                         ks * 16 + kcolsel]));
                uint32_t b0[2] = { bk[0], bk[1] };
                uint32_t b1[2] = { bk[2], bk[3] };
                mma_fp16(sacc[np * 2],     ah, b0);
                mma_fp16(sacc[np * 2 + 1], ah, b1);
            }
        }

        const bool diag = (kt >= ktiles - 2);
        const int r0 = q0 + m0 + g, r1 = r0 + 8;
        float rm0 = -INFINITY, rm1 = -INFINITY;
#pragma unroll
        for (int nt = 0; nt < 8; nt++) {
            int cb0 = kb + nt * 8 + tq * 2;
            float s0 = sacc[nt][0] * SC2, s1 = sacc[nt][1] * SC2;
            float s2 = sacc[nt][2] * SC2, s3 = sacc[nt][3] * SC2;
            if (diag) {
                if (cb0     > r0) s0 = -INFINITY;
                if (cb0 + 1 > r0) s1 = -INFINITY;
                if (cb0     > r1) s2 = -INFINITY;
                if (cb0 + 1 > r1) s3 = -INFINITY;
            }
            sacc[nt][0] = s0; sacc[nt][1] = s1; sacc[nt][2] = s2; sacc[nt][3] = s3;
            rm0 = fmaxf(rm0, fmaxf(s0, s1));
            rm1 = fmaxf(rm1, fmaxf(s2, s3));
        }
        rm0 = fmaxf(rm0, __shfl_xor_sync(0xffffffffu, rm0, 1));
        rm0 = fmaxf(rm0, __shfl_xor_sync(0xffffffffu, rm0, 2));
        rm1 = fmaxf(rm1, __shfl_xor_sync(0xffffffffu, rm1, 1));
        rm1 = fmaxf(rm1, __shfl_xor_sync(0xffffffffu, rm1, 2));
        float mn0 = fmaxf(mI0, rm0), mn1 = fmaxf(mI1, rm1);
        float c0 = exp2f(mI0 - mn0), c1 = exp2f(mI1 - mn1);
        float ps0 = 0.f, ps1 = 0.f;
#pragma unroll
        for (int nt = 0; nt < 8; nt++) {
            float p0 = exp2f(sacc[nt][0] - mn0);
            float p1 = exp2f(sacc[nt][1] - mn0);
            float p2 = exp2f(sacc[nt][2] - mn1);
            float p3 = exp2f(sacc[nt][3] - mn1);
            ps0 += p0 + p1; ps1 += p2 + p3;
            __half2 ph;
            ph.x = __float2half(p0); ph.y = __float2half(p1);
            *(__half2*)&Ps[(m0 + g) * PS + nt * 8 + tq * 2] = ph;
            ph.x = __float2half(p2); ph.y = __float2half(p3);
            *(__half2*)&Ps[(m0 + g + 8) * PS + nt * 8 + tq * 2] = ph;
        }
        ps0 += __shfl_xor_sync(0xffffffffu, ps0, 1);
        ps0 += __shfl_xor_sync(0xffffffffu, ps0, 2);
        ps1 += __shfl_xor_sync(0xffffffffu, ps1, 1);
        ps1 += __shfl_xor_sync(0xffffffffu, ps1, 2);
        lI0 = lI0 * c0 + ps0; lI1 = lI1 * c1 + ps1;
        mI0 = mn0; mI1 = mn1;
#pragma unroll
        for (int n2 = 0; n2 < 16; n2++) {
            ctx[n2][0] *= c0; ctx[n2][1] *= c0;
            ctx[n2][2] *= c1; ctx[n2][3] *= c1;
        }
        __syncwarp();

        const int vpair = lane >> 4;
#pragma unroll
        for (int ks = 0; ks < 4; ks++) {
            uint32_t aph[4];
            ldsm_x4(aph, smem_u32(&Ps[(m0 + l16) * PS + ks * 16 + lhi * 8]));
#pragma unroll
            for (int np = 0; np < 8; np++) {
                uint32_t bv[4];
                ldsm_x4t(bv, smem_u32(&Vs[(ks * 16 + l16) * TS +
                                          (np * 2 + vpair) * 8]));
                uint32_t b0[2] = { bv[0], bv[1] };
                uint32_t b1[2] = { bv[2], bv[3] };
                mma_fp16(ctx[np * 2],     aph, b0);
                mma_fp16(ctx[np * 2 + 1], aph, b1);
            }
        }
    }

    // ---- epilogue: normalize, single fp16 ctx write (b*t, d_model) ----
    float ri0 = 1.0f / lI0, ri1 = 1.0f / lI1;
    const int b_ = bh >> 4, h_ = bh & 15;
    const int t0 = q0 + m0 + g, t1 = t0 + 8;
#pragma unroll
    for (int nt = 0; nt < 16; nt++) {
        int col = h_ * D_HEAD + nt * 8 + tq * 2;
        {
            __half2 hh;
            hh.x = __float2half(ctx[nt][0] * ri0);
            hh.y = __float2half(ctx[nt][1] * ri0);
            *(__half2*)&g_c16[(size_t)(b_ * SEQ + t0) * D_MODEL + col] = hh;
        }
        {
            __half2 hh;
            hh.x = __float2half(ctx[nt][2] * ri1);
            hh.y = __float2half(ctx[nt][3] * ri1);
            *(__half2*)&g_c16[(size_t)(b_ * SEQ + t1) * D_MODEL + col] = hh;
        }
    }
}

// ---------------- launcher ----------------
extern "C" void kernel_launch(void* const* d_in, const int* in_sizes, int n_in,
                              void* d_out, int out_size)
{
    const float* x     = (const float*)d_in[0];
    const float* w_qkv = (const float*)d_in[1];
    const float* b_qkv = (const float*)d_in[2];
    const float* w_out = (const float*)d_in[3];
    const float* b_out = (const float*)d_in[4];
    float* out = (float*)d_out;

    (void)in_sizes; (void)n_in; (void)out_size;

    __half *x16, *wq, *wo, *c16;
    cudaGetSymbolAddress((void**)&x16, g_x16);
    cudaGetSymbolAddress((void**)&wq,  g_wq16);
    cudaGetSymbolAddress((void**)&wo,  g_wo16);
    cudaGetSymbolAddress((void**)&c16, g_c16);

    // 0) conversions (single fp16)
    {
        int n4 = M_ROWS * D_MODEL / 4;
        conv_fp16_kernel<<<(n4 + 255) / 256, 256>>>(x, x16, n4);
        n4 = D_MODEL * N_QKV / 4;
        conv_fp16_kernel<<<(n4 + 255) / 256, 256>>>(w_qkv, wq, n4);
        n4 = D_MODEL * D_MODEL / 4;
        conv_fp16_kernel<<<(n4 + 255) / 256, 256>>>(w_out, wo, n4);
    }
    // 1) QKV projection (1-term fp16, K64, 3-stage, staged epilogue)
    {
        cudaFuncSetAttribute(gemm_kernel<N_QKV, true>,
                             cudaFuncAttributeMaxDynamicSharedMemorySize, GEMM_SMEM_BYTES);
        dim3 grid(N_QKV / 128, M_ROWS / 128);
        gemm_kernel<N_QKV, true><<<grid, 256, GEMM_SMEM_BYTES>>>(x16, wq, b_qkv, nullptr);
    }
    // 2) RoPE (fp16 in-place)
    {
        int total = BH * SEQ * 64;
        rope_kernel<<<(total + 255) / 256, 256>>>();
    }
    // 3) Flash attention (fp16 mma; single fp16 ctx)
    {
        cudaFuncSetAttribute(attn_mma_kernel,
                             cudaFuncAttributeMaxDynamicSharedMemorySize, ATTN_SMEM_BYTES);
        dim3 grid(SEQ / 128, BH);
        attn_mma_kernel<<<grid, 256, ATTN_SMEM_BYTES>>>();
    }
    // 4) Output projection (1-term fp16, K64, 3-stage)
    {
        cudaFuncSetAttribute(gemm_kernel<D_MODEL, false>,
                             cudaFuncAttributeMaxDynamicSharedMemorySize, GEMM_SMEM_BYTES);
        dim3 grid(D_MODEL / 128, M_ROWS / 128);
        gemm_kernel<D_MODEL, false><<<grid, 256, GEMM_SMEM_BYTES>>>(c16, wo, b_out, out);
    }
}

// round 11
// speedup vs baseline: 10.0581x; 1.1210x over previous
#include <cuda_runtime.h>
#include <cuda_fp16.h>
#include <math.h>
#include <stdint.h>

#define D_MODEL 2048
#define N_HEADS 16
#define D_HEAD 128
#define BATCH 4
#define SEQ 2048
#define M_ROWS (BATCH*SEQ)      /* 8192 */
#define N_QKV (3*D_MODEL)       /* 6144 */
#define BH (BATCH*N_HEADS)      /* 64  */

// ---------------- scratch (no allocation allowed) ----------------
__device__ __half g_Qh[(size_t)BH*SEQ*D_HEAD];
__device__ __half g_Kh[(size_t)BH*SEQ*D_HEAD];
__device__ __half g_Vh[(size_t)BH*SEQ*D_HEAD];

__device__ __half g_x16[(size_t)M_ROWS*D_MODEL];
__device__ __half g_wq16[(size_t)D_MODEL*N_QKV];
__device__ __half g_wo16[(size_t)D_MODEL*D_MODEL];
__device__ __half g_c16[(size_t)M_ROWS*D_MODEL];

// ---------------- helpers ----------------
__device__ __forceinline__ uint32_t smem_u32(const void* p) {
    return (uint32_t)__cvta_generic_to_shared(p);
}
#define CP_ASYNC16(dst, src) \
    asm volatile("cp.async.cg.shared.global [%0], [%1], 16;" :: "r"(dst), "l"(src))
#define CP_COMMIT()  asm volatile("cp.async.commit_group;" ::: "memory")
#define CP_WAITG(n)  asm volatile("cp.async.wait_group %0;" :: "n"(n) : "memory")

__device__ __forceinline__ void ldsm_x4(uint32_t (&r)[4], uint32_t addr) {
    asm volatile("ldmatrix.sync.aligned.m8n8.x4.shared.b16 {%0,%1,%2,%3}, [%4];"
                 : "=r"(r[0]), "=r"(r[1]), "=r"(r[2]), "=r"(r[3]) : "r"(addr));
}
__device__ __forceinline__ void ldsm_x4t(uint32_t (&r)[4], uint32_t addr) {
    asm volatile("ldmatrix.sync.aligned.m8n8.x4.trans.shared.b16 {%0,%1,%2,%3}, [%4];"
                 : "=r"(r[0]), "=r"(r[1]), "=r"(r[2]), "=r"(r[3]) : "r"(addr));
}
__device__ __forceinline__ void mma_fp16(float (&d)[4], const uint32_t (&a)[4],
                                         const uint32_t (&b)[2]) {
    asm volatile("mma.sync.aligned.m16n8k16.row.col.f32.f16.f16.f32 "
                 "{%0,%1,%2,%3}, {%4,%5,%6,%7}, {%8,%9}, {%0,%1,%2,%3};"
                 : "+f"(d[0]), "+f"(d[1]), "+f"(d[2]), "+f"(d[3])
                 : "r"(a[0]), "r"(a[1]), "r"(a[2]), "r"(a[3]),
                   "r"(b[0]), "r"(b[1]));
}
__device__ __forceinline__ uint32_t pack_h2(float lo, float hi) {
    __half2 h = __floats2half2_rn(lo, hi);
    return *(uint32_t*)&h;
}

// ---------------- conversion kernel ----------------
__global__ __launch_bounds__(256)
void conv_fp16_kernel(const float* __restrict__ in, __half* __restrict__ o, int n4)
{
    int idx = blockIdx.x * blockDim.x + threadIdx.x;
    if (idx >= n4) return;
    float4 v = *(const float4*)&in[idx * 4];
    __half2 a, b;
    a.x = __float2half(v.x); a.y = __float2half(v.y);
    b.x = __float2half(v.z); b.y = __float2half(v.w);
    *(__half2*)&o[idx * 4]     = a;
    *(__half2*)&o[idx * 4 + 2] = b;
}

// ---------------- tile constants (K-chunk = 64) ----------------
#define A64_STRIDE 72
#define B64_STRIDE 136
#define GA64 (128*A64_STRIDE)   /* 9216 elems */
#define GB64 (64*B64_STRIDE)    /* 8704 elems */
#define NCH64 (D_MODEL/64)      /* 32 chunks */
#define G64STAGE (GA64 + GB64)           /* 17920 elems */
#define GEMM_SMEM_BYTES (3*G64STAGE*2)   /* 107520 */
#define STG_STRIDE 136

// ================= 1-term fp16 GEMM (K64, 3-stage) =============
template<int N_DIM>
__device__ __forceinline__ void g_load_stage(char* dsm, int buf, int k0,
    const __half* A, const __half* Bs, int row0, int col0, int tid)
{
    uint32_t base = smem_u32(dsm) + (uint32_t)buf * (G64STAGE*2);
#pragma unroll
    for (int s = 0; s < 4; s++) {
        int id = tid + s * 256;                 // 0..1023
        int ra = id >> 3, ca = id & 7;          // A: 128 rows x 8 chunks
        CP_ASYNC16(base + ra * (A64_STRIDE*2) + ca * 16,
                   A + (size_t)(row0 + ra) * D_MODEL + k0 + ca * 8);
        int rb = id >> 4, cb = id & 15;         // B: 64 rows x 16 chunks
        CP_ASYNC16(base + GA64*2 + rb * (B64_STRIDE*2) + cb * 16,
                   Bs + (size_t)(k0 + rb) * N_DIM + col0 + cb * 8);
    }
}

template<int N_DIM, bool IS_QKV>
__global__ __launch_bounds__(256)
void gemm_kernel(const __half* __restrict__ A,
                 const __half* __restrict__ Bs,
                 const float* __restrict__ bias,
                 float* __restrict__ out)
{
    extern __shared__ __align__(16) char dsm[];
    const int tid  = threadIdx.x;
    const int lane = tid & 31;
    const int warp = tid >> 5;
    const int wm = warp & 1;
    const int wn = warp >> 1;
    const int row0 = blockIdx.y * 128;
    const int col0 = blockIdx.x * 128;
    const int l16 = lane & 15;
    const int lhi = lane >> 4;

    float acc[4][4][4];
#pragma unroll
    for (int i = 0; i < 4; i++)
#pragma unroll
        for (int j = 0; j < 4; j++)
#pragma unroll
            for (int k = 0; k < 4; k++) acc[i][j][k] = 0.f;

    g_load_stage<N_DIM>(dsm, 0, 0,  A, Bs, row0, col0, tid);
    CP_COMMIT();
    g_load_stage<N_DIM>(dsm, 1, 64, A, Bs, row0, col0, tid);
    CP_COMMIT();

    int bufc = 0;
#pragma unroll 1
    for (int c = 0; c < NCH64; c++) {
        CP_WAITG(1);
        __syncthreads();

        int bufl = bufc + 2; if (bufl >= 3) bufl -= 3;
        if (c + 2 < NCH64)
            g_load_stage<N_DIM>(dsm, bufl, (c + 2) * 64, A, Bs, row0, col0, tid);
        CP_COMMIT();

        const __half* As  = (const __half*)(dsm + (size_t)bufc * G64STAGE * 2);
        const __half* Bss = As + GA64;

#pragma unroll
        for (int ksub = 0; ksub < 4; ksub++) {
            uint32_t bf[4][2];
#pragma unroll
            for (int np = 0; np < 2; np++) {
                uint32_t bk[4];
                ldsm_x4t(bk, smem_u32(&Bss[(ksub*16 + l16) * B64_STRIDE +
                                           wn*32 + (np*2 + lhi)*8]));
                bf[np*2][0]   = bk[0]; bf[np*2][1]   = bk[1];
                bf[np*2+1][0] = bk[2]; bf[np*2+1][1] = bk[3];
            }
#pragma unroll
            for (int mt = 0; mt < 4; mt++) {
                uint32_t ah[4];
                ldsm_x4(ah, smem_u32(&As[(wm*64 + mt*16 + l16) * A64_STRIDE + ksub*16 + lhi*8]));
#pragma unroll
                for (int nt = 0; nt < 4; nt++)
                    mma_fp16(acc[mt][nt], ah, bf[nt]);
            }
        }
        bufc++; if (bufc >= 3) bufc = 0;
    }

    const int g = lane >> 2, tq = lane & 3;

    if (IS_QKV) {
        // stage bias-added fp16 tile in smem, then vectorized scatter
        __syncthreads();
        __half* stg = (__half*)dsm;   // 128 x STG_STRIDE
#pragma unroll
        for (int mt = 0; mt < 4; mt++) {
#pragma unroll
            for (int nt = 0; nt < 4; nt++) {
                int rr = wm*64 + mt*16 + g;
                int cc = wn*32 + nt*8 + tq*2;
                float bias0 = __ldg(&bias[col0 + cc]);
                float bias1 = __ldg(&bias[col0 + cc + 1]);
                __half2 v0, v1;
                v0.x = __float2half(acc[mt][nt][0] + bias0);
                v0.y = __float2half(acc[mt][nt][1] + bias1);
                v1.x = __float2half(acc[mt][nt][2] + bias0);
                v1.y = __float2half(acc[mt][nt][3] + bias1);
                *(__half2*)&stg[rr * STG_STRIDE + cc]       = v0;
                *(__half2*)&stg[(rr + 8) * STG_STRIDE + cc] = v1;
            }
        }
        __syncthreads();

        const int which = col0 >> 11;        // 0=q 1=k 2=v
        const int h_    = (col0 & 2047) >> 7;
        __half* buf = (which == 0) ? g_Qh : ((which == 1) ? g_Kh : g_Vh);

        const int r  = tid >> 1;             // 0..127
        const int hf = tid & 1;              // half-row: cols hf*64..+63
        const int grow = row0 + r;
        const int b_ = grow >> 11;
        const int t_ = grow & 2047;
        size_t gbase = (((size_t)b_ * N_HEADS + h_) * SEQ + t_) * D_HEAD + hf * 64;
        const __half* src = &stg[r * STG_STRIDE + hf * 64];
#pragma unroll
        for (int i = 0; i < 8; i++)
            *(uint4*)&buf[gbase + i * 8] = *(const uint4*)&src[i * 8];
    } else {
#pragma unroll
        for (int mt = 0; mt < 4; mt++) {
#pragma unroll
            for (int nt = 0; nt < 4; nt++) {
                int r = row0 + wm*64 + mt*16 + g;
                int cc = col0 + wn*32 + nt*8 + tq*2;
                float bias0 = __ldg(&bias[cc]);
                float bias1 = __ldg(&bias[cc + 1]);
                out[(size_t)r * D_MODEL + cc]           = acc[mt][nt][0] + bias0;
                out[(size_t)r * D_MODEL + cc + 1]       = acc[mt][nt][1] + bias1;
                out[(size_t)(r + 8) * D_MODEL + cc]     = acc[mt][nt][2] + bias0;
                out[(size_t)(r + 8) * D_MODEL + cc + 1] = acc[mt][nt][3] + bias1;
            }
        }
    }
}

// -------- RoPE: in-place on fp16 Q/K (fp32 internal math) --------
__global__ __launch_bounds__(256)
void rope_kernel()
{
    int idx = blockIdx.x * blockDim.x + threadIdx.x;
    if (idx >= BH * SEQ * 64) return;
    int i  = idx & 63;
    int t  = (idx >> 6) & (SEQ - 1);
    int bh = idx >> 17;

    float inv = __expf(-(float)i * (9.210340371976184f / 64.0f));
    float freq = (float)t * inv;
    float s, c;
    __sincosf(freq, &s, &c);

    size_t base = ((size_t)bh * SEQ + t) * D_HEAD;
    float q1 = __half2float(g_Qh[base + i]);
    float q2 = __half2float(g_Qh[base + i + 64]);
    g_Qh[base + i]      = __float2half(q1 * c - q2 * s);
    g_Qh[base + i + 64] = __float2half(q2 * c + q1 * s);
    float k1 = __half2float(g_Kh[base + i]);
    float k2 = __half2float(g_Kh[base + i + 64]);
    g_Kh[base + i]      = __float2half(k1 * c - k2 * s);
    g_Kh[base + i + 64] = __float2half(k2 * c + k1 * s);
}

// ---------------- Flash attention: register-P + double-buffered K/V --------
#define TS 136
#define ATTN_Q_ELEMS (128*TS)
#define KV_ELEMS (64*TS)
#define ATTN_SMEM_BYTES ((ATTN_Q_ELEMS + 4*KV_ELEMS)*2)   /* 104448 */

__global__ __launch_bounds__(256)
void attn_mma_kernel()
{
    extern __shared__ __align__(16) char dsm[];
    __half* Qs  = (__half*)dsm;
    __half* Kb0 = Qs + ATTN_Q_ELEMS;       // K stages 0,1
    __half* Vb0 = Kb0 + 2*KV_ELEMS;        // V stages 0,1

    const int bh = blockIdx.y;
    const int qt = (SEQ/128 - 1) - blockIdx.x;   // heavy tiles first
    const int q0 = qt * 128;
    const float SC2 = 0.08838834764831845f * 1.4426950408889634f;

    const __half* Qg = g_Qh + (size_t)bh * SEQ * D_HEAD;
    const __half* Kg = g_Kh + (size_t)bh * SEQ * D_HEAD;
    const __half* Vg = g_Vh + (size_t)bh * SEQ * D_HEAD;

    const int tid = threadIdx.x;
    const int warp = tid >> 5, lane = tid & 31;
    const int m0 = warp * 16;
    const int l16 = lane & 15, lhi = lane >> 4;
    const int g = lane >> 2, tq = lane & 3;

    // Q tile load
    for (int i = tid; i < 128 * 16; i += 256) {
        int r = i >> 4, c16 = i & 15;
        CP_ASYNC16(smem_u32(&Qs[r * TS + c16 * 8]),
                   &Qg[(size_t)(q0 + r) * D_HEAD + c16 * 8]);
    }
    CP_COMMIT();

    const int ktiles = 2 * qt + 2;

    // KV stage 0
    for (int i = tid; i < 64 * 16; i += 256) {
        int r = i >> 4, c16 = i & 15;
        size_t goff = (size_t)r * D_HEAD + c16 * 8;
        CP_ASYNC16(smem_u32(&Kb0[r * TS + c16 * 8]), &Kg[goff]);
        CP_ASYNC16(smem_u32(&Vb0[r * TS + c16 * 8]), &Vg[goff]);
    }
    CP_COMMIT();

    float mI0 = -INFINITY, mI1 = -INFINITY, lI0 = 0.f, lI1 = 0.f;
    float ctx[16][4];
#pragma unroll
    for (int i = 0; i < 16; i++)
#pragma unroll
        for (int j = 0; j < 4; j++) ctx[i][j] = 0.f;

#pragma unroll 1
    for (int kt = 0; kt < ktiles; kt++) {
        const int buf = kt & 1;
        __syncthreads();   // all warps done reading buf^1 (iteration kt-1)

        if (kt + 1 < ktiles) {
            const int kb1 = (kt + 1) * 64;
            __half* Kd = Kb0 + (buf ^ 1) * KV_ELEMS;
            __half* Vd = Vb0 + (buf ^ 1) * KV_ELEMS;
            for (int i = tid; i < 64 * 16; i += 256) {
                int r = i >> 4, c16 = i & 15;
                size_t goff = (size_t)(kb1 + r) * D_HEAD + c16 * 8;
                CP_ASYNC16(smem_u32(&Kd[r * TS + c16 * 8]), &Kg[goff]);
                CP_ASYNC16(smem_u32(&Vd[r * TS + c16 * 8]), &Vg[goff]);
            }
        }
        CP_COMMIT();
        CP_WAITG(1);       // groups FIFO: stage kt retired, kt+1 may stay in flight
        __syncthreads();   // publish stage kt to all warps

        const __half* Ks = Kb0 + buf * KV_ELEMS;
        const __half* Vs = Vb0 + buf * KV_ELEMS;
        const int kb = kt * 64;

        // ---- scores S = Q @ K^T ----
        float sacc[8][4];
#pragma unroll
        for (int nt = 0; nt < 8; nt++)
#pragma unroll
            for (int e = 0; e < 4; e++) sacc[nt][e] = 0.f;

        const int krow = lane & 7;
        const int kpair = (lane >> 4) & 1;
        const int kcolsel = ((lane >> 3) & 1) * 8;
#pragma unroll
        for (int ks = 0; ks < 8; ks++) {
            uint32_t ah[4];
            ldsm_x4(ah, smem_u32(&Qs[(m0 + l16) * TS + ks * 16 + lhi * 8]));
#pragma unroll
            for (int np = 0; np < 4; np++) {
                uint32_t bk[4];
                ldsm_x4(bk, smem_u32(&Ks[((np * 2 + kpair) * 8 + krow) * TS +
                                         ks * 16 + kcolsel]));
                uint32_t b0[2] = { bk[0], bk[1] };
                uint32_t b1[2] = { bk[2], bk[3] };
                mma_fp16(sacc[np * 2],     ah, b0);
                mma_fp16(sacc[np * 2 + 1], ah, b1);
            }
        }

        // ---- online softmax (base-2); p stays in sacc ----
        const bool diag = (kt >= ktiles - 2);
        const int r0 = q0 + m0 + g, r1 = r0 + 8;
        float rm0 = -INFINITY, rm1 = -INFINITY;
#pragma unroll
        for (int nt = 0; nt < 8; nt++) {
            int cb0 = kb + nt * 8 + tq * 2;
            float s0 = sacc[nt][0] * SC2, s1 = sacc[nt][1] * SC2;
            float s2 = sacc[nt][2] * SC2, s3 = sacc[nt][3] * SC2;
            if (diag) {
                if (cb0     > r0) s0 = -INFINITY;
                if (cb0 + 1 > r0) s1 = -INFINITY;
                if (cb0     > r1) s2 = -INFINITY;
                if (cb0 + 1 > r1) s3 = -INFINITY;
            }
            sacc[nt][0] = s0; sacc[nt][1] = s1; sacc[nt][2] = s2; sacc[nt][3] = s3;
            rm0 = fmaxf(rm0, fmaxf(s0, s1));
            rm1 = fmaxf(rm1, fmaxf(s2, s3));
        }
        rm0 = fmaxf(rm0, __shfl_xor_sync(0xffffffffu, rm0, 1));
        rm0 = fmaxf(rm0, __shfl_xor_sync(0xffffffffu, rm0, 2));
        rm1 = fmaxf(rm1, __shfl_xor_sync(0xffffffffu, rm1, 1));
        rm1 = fmaxf(rm1, __shfl_xor_sync(0xffffffffu, rm1, 2));
        float mn0 = fmaxf(mI0, rm0), mn1 = fmaxf(mI1, rm1);
        float c0 = exp2f(mI0 - mn0), c1 = exp2f(mI1 - mn1);
        float ps0 = 0.f, ps1 = 0.f;
#pragma unroll
        for (int nt = 0; nt < 8; nt++) {
            float p0 = exp2f(sacc[nt][0] - mn0);
            float p1 = exp2f(sacc[nt][1] - mn0);
            float p2 = exp2f(sacc[nt][2] - mn1);
            float p3 = exp2f(sacc[nt][3] - mn1);
            sacc[nt][0] = p0; sacc[nt][1] = p1;
            sacc[nt][2] = p2; sacc[nt][3] = p3;
            ps0 += p0 + p1; ps1 += p2 + p3;
        }
        ps0 += __shfl_xor_sync(0xffffffffu, ps0, 1);
        ps0 += __shfl_xor_sync(0xffffffffu, ps0, 2);
        ps1 += __shfl_xor_sync(0xffffffffu, ps1, 1);
        ps1 += __shfl_xor_sync(0xffffffffu, ps1, 2);
        lI0 = lI0 * c0 + ps0; lI1 = lI1 * c1 + ps1;
        mI0 = mn0; mI1 = mn1;
#pragma unroll
        for (int n2 = 0; n2 < 16; n2++) {
            ctx[n2][0] *= c0; ctx[n2][1] *= c0;
            ctx[n2][2] *= c1; ctx[n2][3] *= c1;
        }

        // ---- ctx += P @ V; P packed from registers (d-layout == A-layout) ----
        const int vpair = lane >> 4;
#pragma unroll
        for (int ks = 0; ks < 4; ks++) {
            uint32_t aph[4];
            aph[0] = pack_h2(sacc[2*ks][0],     sacc[2*ks][1]);
            aph[1] = pack_h2(sacc[2*ks][2],     sacc[2*ks][3]);
            aph[2] = pack_h2(sacc[2*ks + 1][0], sacc[2*ks + 1][1]);
            aph[3] = pack_h2(sacc[2*ks + 1][2], sacc[2*ks + 1][3]);
#pragma unroll
            for (int np = 0; np < 8; np++) {
                uint32_t bv[4];
                ldsm_x4t(bv, smem_u32(&Vs[(ks * 16 + l16) * TS +
                                          (np * 2 + vpair) * 8]));
                uint32_t b0[2] = { bv[0], bv[1] };
                uint32_t b1[2] = { bv[2], bv[3] };
                mma_fp16(ctx[np * 2],     aph, b0);
                mma_fp16(ctx[np * 2 + 1], aph, b1);
            }
        }
    }

    // ---- epilogue: normalize, single fp16 ctx write (b*t, d_model) ----
    float ri0 = 1.0f / lI0, ri1 = 1.0f / lI1;
    const int b_ = bh >> 4, h_ = bh & 15;
    const int t0 = q0 + m0 + g, t1 = t0 + 8;
#pragma unroll
    for (int nt = 0; nt < 16; nt++) {
        int col = h_ * D_HEAD + nt * 8 + tq * 2;
        {
            __half2 hh;
            hh.x = __float2half(ctx[nt][0] * ri0);
            hh.y = __float2half(ctx[nt][1] * ri0);
            *(__half2*)&g_c16[(size_t)(b_ * SEQ + t0) * D_MODEL + col] = hh;
        }
        {
            __half2 hh;
            hh.x = __float2half(ctx[nt][2] * ri1);
            hh.y = __float2half(ctx[nt][3] * ri1);
            *(__half2*)&g_c16[(size_t)(b_ * SEQ + t1) * D_MODEL + col] = hh;
        }
    }
}

// ---------------- launcher ----------------
extern "C" void kernel_launch(void* const* d_in, const int* in_sizes, int n_in,
                              void* d_out, int out_size)
{
    const float* x     = (const float*)d_in[0];
    const float* w_qkv = (const float*)d_in[1];
    const float* b_qkv = (const float*)d_in[2];
    const float* w_out = (const float*)d_in[3];
    const float* b_out = (const float*)d_in[4];
    float* out = (float*)d_out;

    (void)in_sizes; (void)n_in; (void)out_size;

    __half *x16, *wq, *wo, *c16;
    cudaGetSymbolAddress((void**)&x16, g_x16);
    cudaGetSymbolAddress((void**)&wq,  g_wq16);
    cudaGetSymbolAddress((void**)&wo,  g_wo16);
    cudaGetSymbolAddress((void**)&c16, g_c16);

    // 0) conversions (single fp16)
    {
        int n4 = M_ROWS * D_MODEL / 4;
        conv_fp16_kernel<<<(n4 + 255) / 256, 256>>>(x, x16, n4);
        n4 = D_MODEL * N_QKV / 4;
        conv_fp16_kernel<<<(n4 + 255) / 256, 256>>>(w_qkv, wq, n4);
        n4 = D_MODEL * D_MODEL / 4;
        conv_fp16_kernel<<<(n4 + 255) / 256, 256>>>(w_out, wo, n4);
    }
    // 1) QKV projection (1-term fp16, K64, 3-stage, staged epilogue)
    {
        cudaFuncSetAttribute(gemm_kernel<N_QKV, true>,
                             cudaFuncAttributeMaxDynamicSharedMemorySize, GEMM_SMEM_BYTES);
        dim3 grid(N_QKV / 128, M_ROWS / 128);
        gemm_kernel<N_QKV, true><<<grid, 256, GEMM_SMEM_BYTES>>>(x16, wq, b_qkv, nullptr);
    }
    // 2) RoPE (fp16 in-place)
    {
        int total = BH * SEQ * 64;
        rope_kernel<<<(total + 255) / 256, 256>>>();
    }
    // 3) Flash attention (register-P, double-buffered K/V)
    {
        cudaFuncSetAttribute(attn_mma_kernel,
                             cudaFuncAttributeMaxDynamicSharedMemorySize, ATTN_SMEM_BYTES);
        dim3 grid(SEQ / 128, BH);
        attn_mma_kernel<<<grid, 256, ATTN_SMEM_BYTES>>>();
    }
    // 4) Output projection (1-term fp16, K64, 3-stage)
    {
        cudaFuncSetAttribute(gemm_kernel<D_MODEL, false>,
                             cudaFuncAttributeMaxDynamicSharedMemorySize, GEMM_SMEM_BYTES);
        dim3 grid(D_MODEL / 128, M_ROWS / 128);
        gemm_kernel<D_MODEL, false><<<grid, 256, GEMM_SMEM_BYTES>>>(c16, wo, b_out, out);
    }
}